// round 1
// baseline (speedup 1.0000x reference)
#include <cuda_runtime.h>
#include <cuda_bf16.h>
#include <cmath>

// ---------------------------------------------------------------------------
// Problem constants
// ---------------------------------------------------------------------------
#define BATCH 4
#define DIM   96
#define HEADS 6
#define HDIM  16           // channels per head
#define C3    288          // 3*DIM
#define HID   192
#define HID2  384          // 2*HID
#define HW    65536        // 256*256
#define IMG   256

// ---------------------------------------------------------------------------
// Scratch (device globals; no allocation allowed)
// ---------------------------------------------------------------------------
__device__ float g_qkv  [(size_t)BATCH * C3  * HW];   // after qkv1 (1x1)
__device__ float g_qkv2 [(size_t)BATCH * C3  * HW];   // after qkv2 (3x3)
__device__ float g_t    [(size_t)BATCH * HID2 * HW];  // after pin (1x1)
__device__ float g_g    [(size_t)BATCH * HID * HW];   // after dwconv+gate
__device__ float g_x2   [(size_t)BATCH * DIM * HW];   // residual after attention
__device__ float g_mu   [BATCH * HW];
__device__ float g_rstd [BATCH * HW];
__device__ float g_Wg1  [C3 * DIM];
__device__ float g_wgs1 [C3];
__device__ float g_wb1  [C3];
__device__ float g_Wg2  [HID2 * DIM];
__device__ float g_wgs2 [HID2];
__device__ float g_wb2  [HID2];
__device__ float g_sqk  [BATCH * 2 * DIM];            // sum of squares for q rows then k rows
__device__ float g_attn [BATCH * HEADS * HDIM * HDIM];
__device__ float g_M    [BATCH * DIM * DIM];          // fused proj @ blockdiag(attn)

// ---------------------------------------------------------------------------
// prep: fold LN gamma/beta into the following 1x1 conv weights
//   out[oc] = rstd*(dot(W*g, x) - mu*sum(W*g)) + dot(W, beta)
// ---------------------------------------------------------------------------
__global__ void prep_kernel(const float* __restrict__ qkv1_w,
                            const float* __restrict__ ln1_w,
                            const float* __restrict__ ln1_b,
                            const float* __restrict__ pin_w,
                            const float* __restrict__ ln2_w,
                            const float* __restrict__ ln2_b) {
    int t = blockIdx.x * 256 + threadIdx.x;
    if (t < C3) {
        float s = 0.f, sb = 0.f;
        for (int c = 0; c < DIM; c++) {
            float w = qkv1_w[t * DIM + c];
            float wg = w * ln1_w[c];
            g_Wg1[t * DIM + c] = wg;
            s += wg; sb += w * ln1_b[c];
        }
        g_wgs1[t] = s; g_wb1[t] = sb;
    } else if (t < C3 + HID2) {
        int r = t - C3;
        float s = 0.f, sb = 0.f;
        for (int c = 0; c < DIM; c++) {
            float w = pin_w[r * DIM + c];
            float wg = w * ln2_w[c];
            g_Wg2[r * DIM + c] = wg;
            s += wg; sb += w * ln2_b[c];
        }
        g_wgs2[r] = s; g_wb2[r] = sb;
    }
}

__global__ void zero_kernel(float* __restrict__ p, int n) {
    int i = blockIdx.x * 256 + threadIdx.x;
    if (i < n) p[i] = 0.f;
}

// ---------------------------------------------------------------------------
// Per-pixel LayerNorm stats over 96 channels (NCHW, channel stride HW)
// ---------------------------------------------------------------------------
__global__ __launch_bounds__(256) void ln_stats_kernel(const float* __restrict__ x,
                                                       float* __restrict__ mu,
                                                       float* __restrict__ rstd) {
    int idx = blockIdx.x * 256 + threadIdx.x;     // 0 .. BATCH*HW-1
    int b = idx >> 16;
    int p = idx & (HW - 1);
    const float* xp = x + (size_t)b * DIM * HW + p;
    float s = 0.f, s2 = 0.f;
#pragma unroll 8
    for (int c = 0; c < DIM; c++) {
        float v = xp[(size_t)c * HW];
        s += v; s2 += v * v;
    }
    float m = s * (1.f / DIM);
    float var = s2 * (1.f / DIM) - m * m;
    mu[idx] = m;
    rstd[idx] = rsqrtf(var + 1e-5f);
}

// ---------------------------------------------------------------------------
// Generic 1x1 conv (GEMM over pixels). Block: 32 oc x 128 px, 256 threads,
// thread tile 4 oc x 4 px. Optional fused-LN input, optional residual add.
// W indexed [b*w_bstride + oc*IC + c].
// ---------------------------------------------------------------------------
template <int IC, bool LN, bool RES>
__global__ __launch_bounds__(256) void conv1x1_kernel(
    const float* __restrict__ in, int in_bstride, int in_choff,
    const float* __restrict__ W, int w_bstride,
    const float* __restrict__ wgs, const float* __restrict__ wb,
    const float* __restrict__ mu, const float* __restrict__ rstd,
    const float* __restrict__ res,
    float* __restrict__ out) {
    const int N = HW;
    int b   = blockIdx.z;
    int oc0 = blockIdx.y * 32;
    int px0 = blockIdx.x * 128;
    int OCtot = gridDim.y * 32;
    int tid = threadIdx.x;
    int tx = tid & 31;       // pixel group
    int ty = tid >> 5;       // oc group (0..7)

    __shared__ float sx[16][128];
    __shared__ float sw[32][16];

    float4 acc[4];
#pragma unroll
    for (int i = 0; i < 4; i++) acc[i] = make_float4(0.f, 0.f, 0.f, 0.f);

    const float* inb = in + (size_t)b * in_bstride + (size_t)in_choff * N + px0;
    const float* Wb  = W + (size_t)b * w_bstride + (size_t)oc0 * IC;

    for (int c0 = 0; c0 < IC; c0 += 16) {
#pragma unroll
        for (int k = 0; k < 8; k++) {
            int idx = tid + k * 256;
            int cc = idx >> 7, col = idx & 127;
            sx[cc][col] = inb[(size_t)(c0 + cc) * N + col];
        }
        {
            int idx = tid; int ocl = idx >> 4, cc = idx & 15;
            sw[ocl][cc] = Wb[ocl * IC + c0 + cc];
            idx = tid + 256; ocl = idx >> 4; cc = idx & 15;
            sw[ocl][cc] = Wb[ocl * IC + c0 + cc];
        }
        __syncthreads();
#pragma unroll
        for (int cc = 0; cc < 16; cc++) {
            float4 xv = *(const float4*)&sx[cc][tx * 4];
#pragma unroll
            for (int i = 0; i < 4; i++) {
                float w = sw[ty * 4 + i][cc];
                acc[i].x += w * xv.x; acc[i].y += w * xv.y;
                acc[i].z += w * xv.z; acc[i].w += w * xv.w;
            }
        }
        __syncthreads();
    }

    int p = px0 + tx * 4;
    float4 m4, r4;
    if (LN) {
        m4 = *(const float4*)&mu[(size_t)b * N + p];
        r4 = *(const float4*)&rstd[(size_t)b * N + p];
    }
#pragma unroll
    for (int i = 0; i < 4; i++) {
        int oc = oc0 + ty * 4 + i;
        float4 r = acc[i];
        if (LN) {
            float gsum = wgs[oc], bb = wb[oc];
            r.x = r4.x * (r.x - m4.x * gsum) + bb;
            r.y = r4.y * (r.y - m4.y * gsum) + bb;
            r.z = r4.z * (r.z - m4.z * gsum) + bb;
            r.w = r4.w * (r.w - m4.w * gsum) + bb;
        }
        if (RES) {
            float4 rr = *(const float4*)&res[((size_t)b * OCtot + oc) * N + p];
            r.x += rr.x; r.y += rr.y; r.z += rr.z; r.w += rr.w;
        }
        *(float4*)&out[((size_t)b * OCtot + oc) * N + p] = r;
    }
}

// ---------------------------------------------------------------------------
// 3x3 conv 288 -> 288, padding 1. Block: 32 oc x 128 px (one row segment),
// 256 threads, thread tile 4 oc x 4 px, input chunked 8 ic at a time in smem.
// ---------------------------------------------------------------------------
__global__ __launch_bounds__(256) void conv3x3_kernel(const float* __restrict__ in,
                                                      const float* __restrict__ W,
                                                      float* __restrict__ out) {
    int b   = blockIdx.z;
    int oc0 = blockIdx.y * 32;
    int y   = blockIdx.x >> 1;
    int px0 = (blockIdx.x & 1) * 128;
    int tid = threadIdx.x;
    int tx = tid & 31;
    int ty = tid >> 5;

    __shared__ float sin_s[8][3][132];     // 8 ic x 3 rows x (128 + 2 halo)
    __shared__ float sw_s[32][8][12];      // 32 oc x 8 ic x 9 taps (padded to 12)

    float acc[4][4];
#pragma unroll
    for (int i = 0; i < 4; i++)
#pragma unroll
        for (int j = 0; j < 4; j++) acc[i][j] = 0.f;

    for (int c0 = 0; c0 < C3; c0 += 8) {
        for (int idx = tid; idx < 8 * 3 * 130; idx += 256) {
            int ic = idx / 390;
            int rem = idx - ic * 390;
            int r = rem / 130;
            int l = rem - r * 130;
            int gy = y + r - 1;
            int gx = px0 - 1 + l;
            float v = 0.f;
            if ((unsigned)gy < 256u && (unsigned)gx < 256u)
                v = in[(((size_t)b * C3 + c0 + ic) * IMG + gy) * IMG + gx];
            sin_s[ic][r][l] = v;
        }
        for (int idx = tid; idx < 32 * 8 * 9; idx += 256) {
            int ocl = idx / 72;
            int rem = idx - ocl * 72;
            int ic = rem / 9;
            int tap = rem - ic * 9;
            sw_s[ocl][ic][tap] = W[(((size_t)(oc0 + ocl)) * C3 + c0 + ic) * 9 + tap];
        }
        __syncthreads();

#pragma unroll
        for (int ic = 0; ic < 8; ic++) {
            float s[3][6];
#pragma unroll
            for (int ky = 0; ky < 3; ky++) {
                const float* rp = &sin_s[ic][ky][tx * 4];
                float4 a = *(const float4*)rp;
                float2 bb = *(const float2*)(rp + 4);
                s[ky][0] = a.x; s[ky][1] = a.y; s[ky][2] = a.z;
                s[ky][3] = a.w; s[ky][4] = bb.x; s[ky][5] = bb.y;
            }
#pragma unroll
            for (int i = 0; i < 4; i++) {
                const float* wp = &sw_s[ty * 4 + i][ic][0];
                float4 w0 = *(const float4*)wp;
                float4 w1 = *(const float4*)(wp + 4);
                float w8 = wp[8];
                float wv[9] = {w0.x, w0.y, w0.z, w0.w, w1.x, w1.y, w1.z, w1.w, w8};
#pragma unroll
                for (int ky = 0; ky < 3; ky++)
#pragma unroll
                    for (int kx = 0; kx < 3; kx++) {
                        float w = wv[ky * 3 + kx];
#pragma unroll
                        for (int j = 0; j < 4; j++)
                            acc[i][j] += w * s[ky][j + kx];
                    }
            }
        }
        __syncthreads();
    }

#pragma unroll
    for (int i = 0; i < 4; i++) {
        float4 r = make_float4(acc[i][0], acc[i][1], acc[i][2], acc[i][3]);
        *(float4*)&out[(((size_t)b * C3 + oc0 + ty * 4 + i) * IMG + y) * IMG + px0 + tx * 4] = r;
    }
}

// ---------------------------------------------------------------------------
// Sum of squares per (b, channel) over HW for q (ch 0..95) and k (ch 96..191)
// ---------------------------------------------------------------------------
__global__ __launch_bounds__(256) void sumsq_kernel(const float* __restrict__ qkv2,
                                                    float* __restrict__ sqk) {
    int c = blockIdx.x;   // 0..191
    int b = blockIdx.y;
    int tid = threadIdx.x;
    const float* p = qkv2 + ((size_t)b * C3 + c) * HW;
    float s = 0.f;
    for (int i = tid; i < HW; i += 256) {
        float v = p[i];
        s += v * v;
    }
#pragma unroll
    for (int o = 16; o > 0; o >>= 1) s += __shfl_down_sync(0xffffffffu, s, o);
    __shared__ float red[8];
    if ((tid & 31) == 0) red[tid >> 5] = s;
    __syncthreads();
    if (tid == 0) {
        float tot = 0.f;
#pragma unroll
        for (int i = 0; i < 8; i++) tot += red[i];
        sqk[b * 2 * DIM + c] = tot;
    }
}

// ---------------------------------------------------------------------------
// Raw channel-gram: attn_raw[b,h,c,d] += sum_n q[c,n]*k[d,n] over an n-segment.
// Thread (c,d) pair; blocks cover 32 segments of 2048 pixels.
// ---------------------------------------------------------------------------
__global__ __launch_bounds__(256) void attn_dot_kernel(const float* __restrict__ qkv2,
                                                       float* __restrict__ attn_raw) {
    int seg = blockIdx.x;       // 0..31
    int bh = blockIdx.y;        // 0..23
    int b = bh / HEADS, h = bh % HEADS;
    int t = threadIdx.x;
    int c = t & 15, d = t >> 4;
    const float* qp = qkv2 + ((size_t)b * C3 + h * HDIM + c) * HW + seg * 2048;
    const float* kp = qkv2 + ((size_t)b * C3 + DIM + h * HDIM + d) * HW + seg * 2048;
    float a0 = 0.f, a1 = 0.f, a2 = 0.f, a3 = 0.f;
    for (int n = 0; n < 2048; n += 4) {
        a0 += qp[n] * kp[n];
        a1 += qp[n + 1] * kp[n + 1];
        a2 += qp[n + 2] * kp[n + 2];
        a3 += qp[n + 3] * kp[n + 3];
    }
    atomicAdd(&attn_raw[bh * 256 + t], (a0 + a1) + (a2 + a3));
}

// ---------------------------------------------------------------------------
// Normalize by q/k norms, scale, softmax over d, then build the fused matrix
//   M[b][o][j] = sum_{cg} proj_w[o][h*16+cg] * softattn[b][h][cg][j%16],  h=j/16
// so that attention-out + proj is a single per-batch 96x96 1x1 conv over v.
// ---------------------------------------------------------------------------
__global__ __launch_bounds__(256) void softmax_build_M(const float* __restrict__ attn_raw,
                                                       const float* __restrict__ sqk,
                                                       const float* __restrict__ scale,
                                                       const float* __restrict__ proj_w,
                                                       float* __restrict__ M) {
    int b = blockIdx.x;
    int t = threadIdx.x;
    __shared__ float A[HEADS * 256];
    __shared__ float nq[DIM], nk[DIM];
    if (t < DIM) {
        nq[t] = fmaxf(sqrtf(sqk[b * 2 * DIM + t]), 1e-12f);
        nk[t] = fmaxf(sqrtf(sqk[b * 2 * DIM + DIM + t]), 1e-12f);
    }
    __syncthreads();
    for (int idx = t; idx < HEADS * 256; idx += 256) {
        int h = idx >> 8;
        int cd = idx & 255;
        int c = cd >> 4, d = cd & 15;
        A[idx] = attn_raw[b * HEADS * 256 + idx] /
                 (nq[h * HDIM + c] * nk[h * HDIM + d]) * scale[h];
    }
    __syncthreads();
    if (t < DIM) {       // one softmax row per thread: row (h, c) of 16
        int h = t >> 4, c = t & 15;
        float* row = &A[h * 256 + c * 16];
        float mx = row[0];
#pragma unroll
        for (int d = 1; d < 16; d++) mx = fmaxf(mx, row[d]);
        float sum = 0.f;
#pragma unroll
        for (int d = 0; d < 16; d++) { float e = expf(row[d] - mx); row[d] = e; sum += e; }
        float inv = 1.f / sum;
#pragma unroll
        for (int d = 0; d < 16; d++) row[d] *= inv;
    }
    __syncthreads();
    for (int idx = t; idx < DIM * DIM; idx += 256) {
        int o = idx / DIM, j = idx % DIM;
        int h = j >> 4, d = j & 15;
        float s = 0.f;
#pragma unroll
        for (int cg = 0; cg < 16; cg++)
            s += proj_w[o * DIM + h * HDIM + cg] * A[h * 256 + cg * 16 + d];
        M[b * DIM * DIM + idx] = s;
    }
}

// ---------------------------------------------------------------------------
// Grouped 3x3 conv (groups=192, 2 ch/group) fused with GELU gate.
// Block: one pair-group m, 128-pixel row segment. Out chans {2m,2m+1} of g.
// ---------------------------------------------------------------------------
__device__ __forceinline__ float gelu_tanh(float x) {
    float x3 = x * x * x;
    return 0.5f * x * (1.f + tanhf(0.7978845608028654f * (x + 0.044715f * x3)));
}

__global__ __launch_bounds__(128) void dwgate_kernel(const float* __restrict__ tin,
                                                     const float* __restrict__ dw,
                                                     float* __restrict__ g) {
    int b = blockIdx.z;
    int m = blockIdx.y;              // 0..95 pair group
    int y = blockIdx.x >> 1;
    int px0 = (blockIdx.x & 1) * 128;
    int tid = threadIdx.x;

    __shared__ float sin_s[4][3][132];
    __shared__ float swt[72];

    int chans[4] = {2 * m, 2 * m + 1, HID + 2 * m, HID + 2 * m + 1};

    for (int idx = tid; idx < 4 * 3 * 130; idx += 128) {
        int ch = idx / 390;
        int rem = idx - ch * 390;
        int r = rem / 130;
        int l = rem - r * 130;
        int gy = y + r - 1, gx = px0 - 1 + l;
        float v = 0.f;
        if ((unsigned)gy < 256u && (unsigned)gx < 256u)
            v = tin[(((size_t)b * HID2 + chans[ch]) * IMG + gy) * IMG + gx];
        sin_s[ch][r][l] = v;
    }
    if (tid < 72) {
        int oci = tid / 18;
        int rem = tid - oci * 18;
        swt[tid] = dw[(size_t)chans[oci] * 18 + rem];
    }
    __syncthreads();

    float u[4] = {0.f, 0.f, 0.f, 0.f};
#pragma unroll
    for (int ol = 0; ol < 4; ol++) {
        int i0 = (ol < 2) ? 0 : 2;
#pragma unroll
        for (int i = 0; i < 2; i++)
#pragma unroll
            for (int ky = 0; ky < 3; ky++)
#pragma unroll
                for (int kx = 0; kx < 3; kx++)
                    u[ol] += swt[ol * 18 + i * 9 + ky * 3 + kx] * sin_s[i0 + i][ky][tid + kx];
    }
    float r0 = gelu_tanh(u[0]) * u[2];
    float r1 = gelu_tanh(u[1]) * u[3];
    size_t o0 = (((size_t)b * HID + 2 * m) * IMG + y) * IMG + px0 + tid;
    g[o0] = r0;
    g[o0 + HW] = r1;
}

// ---------------------------------------------------------------------------
// Launch
// ---------------------------------------------------------------------------
static float* sym_addr(const void* sym) {
    void* p = nullptr;
    cudaGetSymbolAddress(&p, sym);
    return (float*)p;
}

extern "C" void kernel_launch(void* const* d_in, const int* in_sizes, int n_in,
                              void* d_out, int out_size) {
    const float* x      = (const float*)d_in[0];
    const float* ln1_w  = (const float*)d_in[1];
    const float* ln1_b  = (const float*)d_in[2];
    const float* qkv1_w = (const float*)d_in[3];
    const float* qkv2_w = (const float*)d_in[4];
    const float* proj_w = (const float*)d_in[5];
    const float* scale  = (const float*)d_in[6];
    const float* ln2_w  = (const float*)d_in[7];
    const float* ln2_b  = (const float*)d_in[8];
    const float* pin_w  = (const float*)d_in[9];
    const float* dw_w   = (const float*)d_in[10];
    const float* pout_w = (const float*)d_in[11];

    float* qkv   = sym_addr(g_qkv);
    float* qkv2  = sym_addr(g_qkv2);
    float* tbuf  = sym_addr(g_t);
    float* gbuf  = sym_addr(g_g);
    float* x2    = sym_addr(g_x2);
    float* mu    = sym_addr(g_mu);
    float* rstd  = sym_addr(g_rstd);
    float* Wg1   = sym_addr(g_Wg1);
    float* wgs1  = sym_addr(g_wgs1);
    float* wb1   = sym_addr(g_wb1);
    float* Wg2   = sym_addr(g_Wg2);
    float* wgs2  = sym_addr(g_wgs2);
    float* wb2   = sym_addr(g_wb2);
    float* sqk   = sym_addr(g_sqk);
    float* attn  = sym_addr(g_attn);
    float* M     = sym_addr(g_M);
    float* out   = (float*)d_out;

    // weight prep + zero attn accumulator
    prep_kernel<<<3, 256>>>(qkv1_w, ln1_w, ln1_b, pin_w, ln2_w, ln2_b);
    zero_kernel<<<24, 256>>>(attn, BATCH * HEADS * 256);

    // LN1 stats, then LN-fused qkv1 (96 -> 288)
    ln_stats_kernel<<<(BATCH * HW) / 256, 256>>>(x, mu, rstd);
    conv1x1_kernel<DIM, true, false><<<dim3(512, 9, BATCH), 256>>>(
        x, DIM * HW, 0, Wg1, 0, wgs1, wb1, mu, rstd, nullptr, qkv);

    // qkv2: 3x3 conv 288 -> 288
    conv3x3_kernel<<<dim3(512, 9, BATCH), 256>>>(qkv, qkv2_w, qkv2);

    // attention statistics
    sumsq_kernel<<<dim3(2 * DIM, BATCH), 256>>>(qkv2, sqk);
    attn_dot_kernel<<<dim3(32, BATCH * HEADS), 256>>>(qkv2, attn);
    softmax_build_M<<<BATCH, 256>>>(attn, sqk, scale, proj_w, M);

    // fused (attn@v -> proj -> +x): per-batch 96x96 matrix over v channels
    conv1x1_kernel<DIM, false, true><<<dim3(512, 3, BATCH), 256>>>(
        qkv2, C3 * HW, 2 * DIM, M, DIM * DIM, nullptr, nullptr, nullptr, nullptr, x, x2);

    // LN2 stats, LN-fused pin (96 -> 384)
    ln_stats_kernel<<<(BATCH * HW) / 256, 256>>>(x2, mu, rstd);
    conv1x1_kernel<DIM, true, false><<<dim3(512, 12, BATCH), 256>>>(
        x2, DIM * HW, 0, Wg2, 0, wgs2, wb2, mu, rstd, nullptr, tbuf);

    // grouped 3x3 conv + GELU gate (384 -> 192)
    dwgate_kernel<<<dim3(512, DIM, BATCH), 128>>>(tbuf, dw_w, gbuf);

    // pout (192 -> 96) + residual -> output
    conv1x1_kernel<HID, false, true><<<dim3(512, 3, BATCH), 256>>>(
        gbuf, HID * HW, 0, pout_w, 0, nullptr, nullptr, nullptr, nullptr, x2, out);
}

// round 2
// speedup vs baseline: 1.8074x; 1.8074x over previous
#include <cuda_runtime.h>
#include <cuda_bf16.h>
#include <cmath>
#include <cstdint>

// ---------------------------------------------------------------------------
// Problem constants
// ---------------------------------------------------------------------------
#define BATCH 4
#define DIM   96
#define HEADS 6
#define HDIM  16           // channels per head
#define C3    288          // 3*DIM
#define HID   192
#define HID2  384          // 2*HID
#define HW    65536        // 256*256
#define IMG   256

// conv3x3 mma tiling
#define NCHUNK 36              // 288 / 8 ic per chunk
#define NSTAGE (NCHUNK * 3)    // (chunk, ky) stages
#define WSLICE 2304            // weights floats per stage slice: 2*3*3*32*4
#define WPSIZE (3 * NCHUNK * 3 * WSLICE)   // 746496

// ---------------------------------------------------------------------------
// Scratch (device globals; no allocation allowed)
// ---------------------------------------------------------------------------
__device__ float g_qkv  [(size_t)BATCH * C3  * HW];   // after qkv1 (1x1), tf32-rounded
__device__ float g_qkv2 [(size_t)BATCH * C3  * HW];   // after qkv2 (3x3)
__device__ float g_t    [(size_t)BATCH * HID2 * HW];  // after pin (1x1)
__device__ float g_g    [(size_t)BATCH * HID * HW];   // after dwconv+gate
__device__ float g_x2   [(size_t)BATCH * DIM * HW];   // residual after attention
__device__ float g_mu   [BATCH * HW];
__device__ float g_rstd [BATCH * HW];
__device__ float g_Wg1  [C3 * DIM];
__device__ float g_wgs1 [C3];
__device__ float g_wb1  [C3];
__device__ float g_Wg2  [HID2 * DIM];
__device__ float g_wgs2 [HID2];
__device__ float g_wb2  [HID2];
__device__ float g_sqk  [BATCH * 2 * DIM];
__device__ float g_attn [BATCH * HEADS * HDIM * HDIM];
__device__ float g_M    [BATCH * DIM * DIM];
__device__ float g_Wp   [WPSIZE];                      // permuted tf32 conv3x3 weights

// ---------------------------------------------------------------------------
// helpers
// ---------------------------------------------------------------------------
__device__ __forceinline__ float tf32_rna(float x) {
    uint32_t u;
    asm("cvt.rna.tf32.f32 %0, %1;" : "=r"(u) : "f"(x));
    return __uint_as_float(u);
}

__device__ __forceinline__ void cpa4(uint32_t dst, const void* src, bool v) {
    asm volatile("cp.async.ca.shared.global [%0], [%1], 4, %2;"
                 :: "r"(dst), "l"(src), "r"(v ? 4u : 0u));
}
__device__ __forceinline__ void cpa16(uint32_t dst, const void* src) {
    asm volatile("cp.async.cg.shared.global [%0], [%1], 16;"
                 :: "r"(dst), "l"(src));
}

__device__ __forceinline__ void mma_tf32(float* c, const uint32_t* a, const uint32_t* b) {
    asm volatile("mma.sync.aligned.m16n8k8.row.col.f32.tf32.tf32.f32 "
                 "{%0,%1,%2,%3}, {%4,%5,%6,%7}, {%8,%9}, {%0,%1,%2,%3};"
                 : "+f"(c[0]), "+f"(c[1]), "+f"(c[2]), "+f"(c[3])
                 : "r"(a[0]), "r"(a[1]), "r"(a[2]), "r"(a[3]),
                   "r"(b[0]), "r"(b[1]));
}

// ---------------------------------------------------------------------------
// prep: fold LN gamma/beta into following 1x1 conv weights
// ---------------------------------------------------------------------------
__global__ void prep_kernel(const float* __restrict__ qkv1_w,
                            const float* __restrict__ ln1_w,
                            const float* __restrict__ ln1_b,
                            const float* __restrict__ pin_w,
                            const float* __restrict__ ln2_w,
                            const float* __restrict__ ln2_b) {
    int t = blockIdx.x * 256 + threadIdx.x;
    if (t < C3) {
        float s = 0.f, sb = 0.f;
        for (int c = 0; c < DIM; c++) {
            float w = qkv1_w[t * DIM + c];
            float wg = w * ln1_w[c];
            g_Wg1[t * DIM + c] = wg;
            s += wg; sb += w * ln1_b[c];
        }
        g_wgs1[t] = s; g_wb1[t] = sb;
    } else if (t < C3 + HID2) {
        int r = t - C3;
        float s = 0.f, sb = 0.f;
        for (int c = 0; c < DIM; c++) {
            float w = pin_w[r * DIM + c];
            float wg = w * ln2_w[c];
            g_Wg2[r * DIM + c] = wg;
            s += wg; sb += w * ln2_b[c];
        }
        g_wgs2[r] = s; g_wb2[r] = sb;
    }
}

// permute conv3x3 weights into fragment-native, tf32-rounded layout
// g_Wp[ocT][chunk][ky][og][kx][mb][lane][v]
__global__ void prep_wp_kernel(const float* __restrict__ qkv2_w) {
    int idx = blockIdx.x * 256 + threadIdx.x;
    if (idx >= WPSIZE) return;
    int v = idx & 3;
    int t = (idx >> 2) & 31;
    int r = idx >> 7;
    int mb = r % 3; r /= 3;
    int kx = r % 3; r /= 3;
    int og = r % 2; r /= 2;
    int ky = r % 3; r /= 3;
    int ch = r % NCHUNK; r /= NCHUNK;
    int ocT = r;
    int oc = ocT * 96 + og * 48 + mb * 16 + (t >> 2) + ((v & 1) ? 8 : 0);
    int ic = ch * 8 + (t & 3) + ((v >> 1) ? 4 : 0);
    g_Wp[idx] = tf32_rna(qkv2_w[(oc * C3 + ic) * 9 + ky * 3 + kx]);
}

__global__ void zero_kernel(float* __restrict__ p, int n) {
    int i = blockIdx.x * 256 + threadIdx.x;
    if (i < n) p[i] = 0.f;
}

// ---------------------------------------------------------------------------
// Per-pixel LayerNorm stats over 96 channels
// ---------------------------------------------------------------------------
__global__ __launch_bounds__(256) void ln_stats_kernel(const float* __restrict__ x,
                                                       float* __restrict__ mu,
                                                       float* __restrict__ rstd) {
    int idx = blockIdx.x * 256 + threadIdx.x;
    int b = idx >> 16;
    int p = idx & (HW - 1);
    const float* xp = x + (size_t)b * DIM * HW + p;
    float s = 0.f, s2 = 0.f;
#pragma unroll 8
    for (int c = 0; c < DIM; c++) {
        float v = xp[(size_t)c * HW];
        s += v; s2 += v * v;
    }
    float m = s * (1.f / DIM);
    float var = s2 * (1.f / DIM) - m * m;
    mu[idx] = m;
    rstd[idx] = rsqrtf(var + 1e-5f);
}

// ---------------------------------------------------------------------------
// Generic 1x1 conv (GEMM over pixels). 32 oc x 128 px per block.
// ---------------------------------------------------------------------------
template <int IC, bool LN, bool RES, bool TF32O>
__global__ __launch_bounds__(256) void conv1x1_kernel(
    const float* __restrict__ in, int in_bstride, int in_choff,
    const float* __restrict__ W, int w_bstride,
    const float* __restrict__ wgs, const float* __restrict__ wb,
    const float* __restrict__ mu, const float* __restrict__ rstd,
    const float* __restrict__ res,
    float* __restrict__ out) {
    const int N = HW;
    int b   = blockIdx.z;
    int oc0 = blockIdx.y * 32;
    int px0 = blockIdx.x * 128;
    int OCtot = gridDim.y * 32;
    int tid = threadIdx.x;
    int tx = tid & 31;
    int ty = tid >> 5;

    __shared__ float sx[16][128];
    __shared__ float sw[32][16];

    float4 acc[4];
#pragma unroll
    for (int i = 0; i < 4; i++) acc[i] = make_float4(0.f, 0.f, 0.f, 0.f);

    const float* inb = in + (size_t)b * in_bstride + (size_t)in_choff * N + px0;
    const float* Wb  = W + (size_t)b * w_bstride + (size_t)oc0 * IC;

    for (int c0 = 0; c0 < IC; c0 += 16) {
#pragma unroll
        for (int k = 0; k < 8; k++) {
            int idx = tid + k * 256;
            int cc = idx >> 7, col = idx & 127;
            sx[cc][col] = inb[(size_t)(c0 + cc) * N + col];
        }
        {
            int idx = tid; int ocl = idx >> 4, cc = idx & 15;
            sw[ocl][cc] = Wb[ocl * IC + c0 + cc];
            idx = tid + 256; ocl = idx >> 4; cc = idx & 15;
            sw[ocl][cc] = Wb[ocl * IC + c0 + cc];
        }
        __syncthreads();
#pragma unroll
        for (int cc = 0; cc < 16; cc++) {
            float4 xv = *(const float4*)&sx[cc][tx * 4];
#pragma unroll
            for (int i = 0; i < 4; i++) {
                float w = sw[ty * 4 + i][cc];
                acc[i].x += w * xv.x; acc[i].y += w * xv.y;
                acc[i].z += w * xv.z; acc[i].w += w * xv.w;
            }
        }
        __syncthreads();
    }

    int p = px0 + tx * 4;
    float4 m4, r4;
    if (LN) {
        m4 = *(const float4*)&mu[(size_t)b * N + p];
        r4 = *(const float4*)&rstd[(size_t)b * N + p];
    }
#pragma unroll
    for (int i = 0; i < 4; i++) {
        int oc = oc0 + ty * 4 + i;
        float4 r = acc[i];
        if (LN) {
            float gsum = wgs[oc], bb = wb[oc];
            r.x = r4.x * (r.x - m4.x * gsum) + bb;
            r.y = r4.y * (r.y - m4.y * gsum) + bb;
            r.z = r4.z * (r.z - m4.z * gsum) + bb;
            r.w = r4.w * (r.w - m4.w * gsum) + bb;
        }
        if (RES) {
            float4 rr = *(const float4*)&res[((size_t)b * OCtot + oc) * N + p];
            r.x += rr.x; r.y += rr.y; r.z += rr.z; r.w += rr.w;
        }
        if (TF32O) {
            r.x = tf32_rna(r.x); r.y = tf32_rna(r.y);
            r.z = tf32_rna(r.z); r.w = tf32_rna(r.w);
        }
        *(float4*)&out[((size_t)b * OCtot + oc) * N + p] = r;
    }
}

// ---------------------------------------------------------------------------
// 3x3 conv 288 -> 288 via TF32 mma.sync implicit GEMM.
// Block: 96 oc x 256 px (one image row). 8 warps = 2(oc) x 4(px).
// Warp tile: 48 oc x 64 px = 3 m16 x 8 n8, k8 = ic chunk per (ky,kx) tap.
// Double-buffered cp.async staging of (input row strip, weight slice).
// ---------------------------------------------------------------------------
__global__ __launch_bounds__(256) void conv3x3_mma_kernel(const float* __restrict__ in,
                                                          float* __restrict__ out) {
    int b   = blockIdx.z;
    int ocT = blockIdx.y;
    int y   = blockIdx.x;
    int tid = threadIdx.x;
    int warp = tid >> 5, lane = tid & 31;
    int og = warp >> 2;          // 0..1 oc group
    int pg = warp & 3;           // 0..3 pixel group
    int tg = lane >> 2;          // groupID 0..7
    int tig = lane & 3;          // thread-in-group 0..3

    __shared__ __align__(16) float bsm[2][8][264];
    __shared__ __align__(16) float wsm[2][WSLICE];

    float acc[3][8][4];
#pragma unroll
    for (int mb = 0; mb < 3; mb++)
#pragma unroll
        for (int j = 0; j < 8; j++)
#pragma unroll
            for (int v = 0; v < 4; v++) acc[mb][j][v] = 0.f;

    const float* wp_base = g_Wp + (size_t)ocT * NCHUNK * 3 * WSLICE;

    // ---- stage issue: stage s = (chunk, ky) ----
    auto issue = [&](int s, int buf) {
        int ch = s / 3, ky = s - ch * 3;
        int gy = y + ky - 1;
        bool rowok = (unsigned)gy < 256u;
        const float* base = in + (((size_t)b * C3 + ch * 8) * IMG + gy) * IMG;
#pragma unroll
        for (int k = 0; k < 9; k++) {
            int i = tid + k * 256;
            if (i < 8 * 264) {
                int ic = i / 264, col = i - ic * 264;
                int gx = col - 1;
                bool v = rowok && (unsigned)gx < 256u;
                const float* src = v ? (base + (size_t)ic * HW + gx) : in;
                cpa4((uint32_t)__cvta_generic_to_shared(&bsm[buf][ic][col]), src, v);
            }
        }
        const float* wsrc = wp_base + (size_t)s * WSLICE;
#pragma unroll
        for (int k = 0; k < 3; k++) {
            int i = tid + k * 256;
            if (i < WSLICE / 4)
                cpa16((uint32_t)__cvta_generic_to_shared(&wsm[buf][i * 4]), wsrc + i * 4);
        }
        asm volatile("cp.async.commit_group;");
    };

    issue(0, 0);

    for (int s = 0; s < NSTAGE; s++) {
        if (s + 1 < NSTAGE) {
            issue(s + 1, (s + 1) & 1);
            asm volatile("cp.async.wait_group 1;");
        } else {
            asm volatile("cp.async.wait_group 0;");
        }
        __syncthreads();

        int buf = s & 1;
        const float* wb = &wsm[buf][og * (3 * 3 * 128)];
        int pxb = pg * 64 + tg;
#pragma unroll
        for (int kx = 0; kx < 3; kx++) {
            uint32_t a[3][4];
#pragma unroll
            for (int mb = 0; mb < 3; mb++) {
                float4 av = *(const float4*)&wb[(kx * 3 + mb) * 128 + lane * 4];
                a[mb][0] = __float_as_uint(av.x);
                a[mb][1] = __float_as_uint(av.y);
                a[mb][2] = __float_as_uint(av.z);
                a[mb][3] = __float_as_uint(av.w);
            }
            uint32_t bf[8][2];
#pragma unroll
            for (int j = 0; j < 8; j++) {
                int col = pxb + 8 * j + kx;
                bf[j][0] = __float_as_uint(bsm[buf][tig][col]);
                bf[j][1] = __float_as_uint(bsm[buf][tig + 4][col]);
            }
#pragma unroll
            for (int mb = 0; mb < 3; mb++)
#pragma unroll
                for (int j = 0; j < 8; j++)
                    mma_tf32(acc[mb][j], a[mb], bf[j]);
        }
        __syncthreads();
    }

    // epilogue: C frag c0,c1 -> (row tg, cols 2*tig, 2*tig+1); c2,c3 -> row tg+8
#pragma unroll
    for (int mb = 0; mb < 3; mb++) {
        int oc = ocT * 96 + og * 48 + mb * 16 + tg;
#pragma unroll
        for (int j = 0; j < 8; j++) {
            int px = pg * 64 + 8 * j + 2 * tig;
            float2 v01 = make_float2(acc[mb][j][0], acc[mb][j][1]);
            float2 v23 = make_float2(acc[mb][j][2], acc[mb][j][3]);
            *(float2*)&out[(((size_t)b * C3 + oc) * IMG + y) * IMG + px] = v01;
            *(float2*)&out[(((size_t)b * C3 + oc + 8) * IMG + y) * IMG + px] = v23;
        }
    }
}

// ---------------------------------------------------------------------------
// Sum of squares per (b, channel) over HW for q and k
// ---------------------------------------------------------------------------
__global__ __launch_bounds__(256) void sumsq_kernel(const float* __restrict__ qkv2,
                                                    float* __restrict__ sqk) {
    int c = blockIdx.x;
    int b = blockIdx.y;
    int tid = threadIdx.x;
    const float* p = qkv2 + ((size_t)b * C3 + c) * HW;
    float s = 0.f;
    for (int i = tid; i < HW; i += 256) {
        float v = p[i];
        s += v * v;
    }
#pragma unroll
    for (int o = 16; o > 0; o >>= 1) s += __shfl_down_sync(0xffffffffu, s, o);
    __shared__ float red[8];
    if ((tid & 31) == 0) red[tid >> 5] = s;
    __syncthreads();
    if (tid == 0) {
        float tot = 0.f;
#pragma unroll
        for (int i = 0; i < 8; i++) tot += red[i];
        sqk[b * 2 * DIM + c] = tot;
    }
}

// ---------------------------------------------------------------------------
// Raw channel-gram via segmented dot products + atomics
// ---------------------------------------------------------------------------
__global__ __launch_bounds__(256) void attn_dot_kernel(const float* __restrict__ qkv2,
                                                       float* __restrict__ attn_raw) {
    int seg = blockIdx.x;
    int bh = blockIdx.y;
    int b = bh / HEADS, h = bh % HEADS;
    int t = threadIdx.x;
    int c = t & 15, d = t >> 4;
    const float* qp = qkv2 + ((size_t)b * C3 + h * HDIM + c) * HW + seg * 2048;
    const float* kp = qkv2 + ((size_t)b * C3 + DIM + h * HDIM + d) * HW + seg * 2048;
    float a0 = 0.f, a1 = 0.f, a2 = 0.f, a3 = 0.f;
    for (int n = 0; n < 2048; n += 4) {
        a0 += qp[n] * kp[n];
        a1 += qp[n + 1] * kp[n + 1];
        a2 += qp[n + 2] * kp[n + 2];
        a3 += qp[n + 3] * kp[n + 3];
    }
    atomicAdd(&attn_raw[bh * 256 + t], (a0 + a1) + (a2 + a3));
}

// ---------------------------------------------------------------------------
// softmax + build fused per-batch 96x96 matrix M = proj @ blockdiag(attn)
// ---------------------------------------------------------------------------
__global__ __launch_bounds__(256) void softmax_build_M(const float* __restrict__ attn_raw,
                                                       const float* __restrict__ sqk,
                                                       const float* __restrict__ scale,
                                                       const float* __restrict__ proj_w,
                                                       float* __restrict__ M) {
    int b = blockIdx.x;
    int t = threadIdx.x;
    __shared__ float A[HEADS * 256];
    __shared__ float nq[DIM], nk[DIM];
    if (t < DIM) {
        nq[t] = fmaxf(sqrtf(sqk[b * 2 * DIM + t]), 1e-12f);
        nk[t] = fmaxf(sqrtf(sqk[b * 2 * DIM + DIM + t]), 1e-12f);
    }
    __syncthreads();
    for (int idx = t; idx < HEADS * 256; idx += 256) {
        int h = idx >> 8;
        int cd = idx & 255;
        int c = cd >> 4, d = cd & 15;
        A[idx] = attn_raw[b * HEADS * 256 + idx] /
                 (nq[h * HDIM + c] * nk[h * HDIM + d]) * scale[h];
    }
    __syncthreads();
    if (t < DIM) {
        int h = t >> 4, c = t & 15;
        float* row = &A[h * 256 + c * 16];
        float mx = row[0];
#pragma unroll
        for (int d = 1; d < 16; d++) mx = fmaxf(mx, row[d]);
        float sum = 0.f;
#pragma unroll
        for (int d = 0; d < 16; d++) { float e = expf(row[d] - mx); row[d] = e; sum += e; }
        float inv = 1.f / sum;
#pragma unroll
        for (int d = 0; d < 16; d++) row[d] *= inv;
    }
    __syncthreads();
    for (int idx = t; idx < DIM * DIM; idx += 256) {
        int o = idx / DIM, j = idx % DIM;
        int h = j >> 4, d = j & 15;
        float s = 0.f;
#pragma unroll
        for (int cg = 0; cg < 16; cg++)
            s += proj_w[o * DIM + h * HDIM + cg] * A[h * 256 + cg * 16 + d];
        M[b * DIM * DIM + idx] = s;
    }
}

// ---------------------------------------------------------------------------
// Grouped 3x3 conv (192 groups, 2 ch/group) fused with GELU gate.
// ---------------------------------------------------------------------------
__device__ __forceinline__ float gelu_tanh(float x) {
    float x3 = x * x * x;
    return 0.5f * x * (1.f + tanhf(0.7978845608028654f * (x + 0.044715f * x3)));
}

__global__ __launch_bounds__(128) void dwgate_kernel(const float* __restrict__ tin,
                                                     const float* __restrict__ dw,
                                                     float* __restrict__ g) {
    int b = blockIdx.z;
    int m = blockIdx.y;
    int y = blockIdx.x >> 1;
    int px0 = (blockIdx.x & 1) * 128;
    int tid = threadIdx.x;

    __shared__ float sin_s[4][3][132];
    __shared__ float swt[72];

    int chans[4] = {2 * m, 2 * m + 1, HID + 2 * m, HID + 2 * m + 1};

    for (int idx = tid; idx < 4 * 3 * 130; idx += 128) {
        int ch = idx / 390;
        int rem = idx - ch * 390;
        int r = rem / 130;
        int l = rem - r * 130;
        int gy = y + r - 1, gx = px0 - 1 + l;
        float v = 0.f;
        if ((unsigned)gy < 256u && (unsigned)gx < 256u)
            v = tin[(((size_t)b * HID2 + chans[ch]) * IMG + gy) * IMG + gx];
        sin_s[ch][r][l] = v;
    }
    if (tid < 72) {
        int oci = tid / 18;
        int rem = tid - oci * 18;
        swt[tid] = dw[(size_t)chans[oci] * 18 + rem];
    }
    __syncthreads();

    float u[4] = {0.f, 0.f, 0.f, 0.f};
#pragma unroll
    for (int ol = 0; ol < 4; ol++) {
        int i0 = (ol < 2) ? 0 : 2;
#pragma unroll
        for (int i = 0; i < 2; i++)
#pragma unroll
            for (int ky = 0; ky < 3; ky++)
#pragma unroll
                for (int kx = 0; kx < 3; kx++)
                    u[ol] += swt[ol * 18 + i * 9 + ky * 3 + kx] * sin_s[i0 + i][ky][tid + kx];
    }
    float r0 = gelu_tanh(u[0]) * u[2];
    float r1 = gelu_tanh(u[1]) * u[3];
    size_t o0 = (((size_t)b * HID + 2 * m) * IMG + y) * IMG + px0 + tid;
    g[o0] = r0;
    g[o0 + HW] = r1;
}

// ---------------------------------------------------------------------------
// Launch
// ---------------------------------------------------------------------------
static float* sym_addr(const void* sym) {
    void* p = nullptr;
    cudaGetSymbolAddress(&p, sym);
    return (float*)p;
}

extern "C" void kernel_launch(void* const* d_in, const int* in_sizes, int n_in,
                              void* d_out, int out_size) {
    const float* x      = (const float*)d_in[0];
    const float* ln1_w  = (const float*)d_in[1];
    const float* ln1_b  = (const float*)d_in[2];
    const float* qkv1_w = (const float*)d_in[3];
    const float* qkv2_w = (const float*)d_in[4];
    const float* proj_w = (const float*)d_in[5];
    const float* scale  = (const float*)d_in[6];
    const float* ln2_w  = (const float*)d_in[7];
    const float* ln2_b  = (const float*)d_in[8];
    const float* pin_w  = (const float*)d_in[9];
    const float* dw_w   = (const float*)d_in[10];
    const float* pout_w = (const float*)d_in[11];

    float* qkv   = sym_addr(g_qkv);
    float* qkv2  = sym_addr(g_qkv2);
    float* tbuf  = sym_addr(g_t);
    float* gbuf  = sym_addr(g_g);
    float* x2    = sym_addr(g_x2);
    float* mu    = sym_addr(g_mu);
    float* rstd  = sym_addr(g_rstd);
    float* Wg1   = sym_addr(g_Wg1);
    float* wgs1  = sym_addr(g_wgs1);
    float* wb1   = sym_addr(g_wb1);
    float* Wg2   = sym_addr(g_Wg2);
    float* wgs2  = sym_addr(g_wgs2);
    float* wb2   = sym_addr(g_wb2);
    float* sqk   = sym_addr(g_sqk);
    float* attn  = sym_addr(g_attn);
    float* M     = sym_addr(g_M);
    float* out   = (float*)d_out;

    // weight prep + zero attn accumulator
    prep_kernel<<<3, 256>>>(qkv1_w, ln1_w, ln1_b, pin_w, ln2_w, ln2_b);
    prep_wp_kernel<<<(WPSIZE + 255) / 256, 256>>>(qkv2_w);
    zero_kernel<<<24, 256>>>(attn, BATCH * HEADS * 256);

    // LN1 stats, then LN-fused qkv1 (96 -> 288), tf32-rounded output
    ln_stats_kernel<<<(BATCH * HW) / 256, 256>>>(x, mu, rstd);
    conv1x1_kernel<DIM, true, false, true><<<dim3(512, 9, BATCH), 256>>>(
        x, DIM * HW, 0, Wg1, 0, wgs1, wb1, mu, rstd, nullptr, qkv);

    // qkv2: 3x3 conv 288 -> 288 via TF32 tensor cores
    conv3x3_mma_kernel<<<dim3(256, 3, BATCH), 256>>>(qkv, qkv2);

    // attention statistics
    sumsq_kernel<<<dim3(2 * DIM, BATCH), 256>>>(qkv2, sqk);
    attn_dot_kernel<<<dim3(32, BATCH * HEADS), 256>>>(qkv2, attn);
    softmax_build_M<<<BATCH, 256>>>(attn, sqk, scale, proj_w, M);

    // fused (attn@v -> proj -> +x): per-batch 96x96 matrix over v channels
    conv1x1_kernel<DIM, false, true, false><<<dim3(512, 3, BATCH), 256>>>(
        qkv2, C3 * HW, 2 * DIM, M, DIM * DIM, nullptr, nullptr, nullptr, nullptr, x, x2);

    // LN2 stats, LN-fused pin (96 -> 384)
    ln_stats_kernel<<<(BATCH * HW) / 256, 256>>>(x2, mu, rstd);
    conv1x1_kernel<DIM, true, false, false><<<dim3(512, 12, BATCH), 256>>>(
        x2, DIM * HW, 0, Wg2, 0, wgs2, wb2, mu, rstd, nullptr, tbuf);

    // grouped 3x3 conv + GELU gate (384 -> 192)
    dwgate_kernel<<<dim3(512, DIM, BATCH), 128>>>(tbuf, dw_w, gbuf);

    // pout (192 -> 96) + residual -> output
    conv1x1_kernel<HID, false, true, false><<<dim3(512, 3, BATCH), 256>>>(
        gbuf, HID * HW, 0, pout_w, 0, nullptr, nullptr, nullptr, nullptr, x2, out);
}

// round 5
// speedup vs baseline: 3.4400x; 1.9033x over previous
#include <cuda_runtime.h>
#include <cuda_bf16.h>
#include <cmath>
#include <cstdint>

// ---------------------------------------------------------------------------
// Problem constants
// ---------------------------------------------------------------------------
#define BATCH 4
#define DIM   96
#define HEADS 6
#define HDIM  16           // channels per head
#define C3    288          // 3*DIM
#define HID   192
#define HID2  384          // 2*HID
#define HW    65536        // 256*256
#define IMG   256

// conv3x3 mma tiling
#define NCHUNK 36                    // 288 / 8 ic per chunk
#define WCHUNK 6912                  // weight floats per chunk: 3ky*2og*3kx*3mb*32*4
#define WPSIZE (3 * NCHUNK * WCHUNK) // 746496
#define BROW   280                   // smem row stride (floats), interior at +8
#define BSMSZ  (8 * 3 * BROW)        // floats per input buffer
#define SMEM3  ((2 * BSMSZ + 2 * WCHUNK) * 4)  // 109056 bytes

// ---------------------------------------------------------------------------
// Scratch (device globals; no allocation allowed)
// ---------------------------------------------------------------------------
__device__ float g_qkv  [(size_t)BATCH * C3  * HW];   // after qkv1 (1x1), tf32-rounded
__device__ float g_qkv2 [(size_t)BATCH * C3  * HW];   // after qkv2 (3x3)
__device__ float g_t    [(size_t)BATCH * HID2 * HW];  // after pin (1x1)
__device__ float g_g    [(size_t)BATCH * HID * HW];   // after dwconv+gate
__device__ float g_x2   [(size_t)BATCH * DIM * HW];   // residual after attention
__device__ float g_mu   [BATCH * HW];
__device__ float g_rstd [BATCH * HW];
__device__ float g_Wg1  [C3 * DIM];
__device__ float g_wgs1 [C3];
__device__ float g_wb1  [C3];
__device__ float g_Wg2  [HID2 * DIM];
__device__ float g_wgs2 [HID2];
__device__ float g_wb2  [HID2];
__device__ float g_sqk  [BATCH * 2 * DIM];
__device__ float g_attn [BATCH * HEADS * HDIM * HDIM];
__device__ float g_M    [BATCH * DIM * DIM];
__device__ float g_Wp   [WPSIZE];                      // permuted tf32 conv3x3 weights

// ---------------------------------------------------------------------------
// helpers
// ---------------------------------------------------------------------------
__device__ __forceinline__ float tf32_rna(float x) {
    uint32_t u;
    asm("cvt.rna.tf32.f32 %0, %1;" : "=r"(u) : "f"(x));
    return __uint_as_float(u);
}

__device__ __forceinline__ void cpa16(uint32_t dst, const void* src) {
    asm volatile("cp.async.cg.shared.global [%0], [%1], 16;"
                 :: "r"(dst), "l"(src));
}
__device__ __forceinline__ void cpa16z(uint32_t dst, const void* src, bool v) {
    asm volatile("cp.async.cg.shared.global [%0], [%1], 16, %2;"
                 :: "r"(dst), "l"(src), "r"(v ? 16u : 0u));
}

__device__ __forceinline__ void mma_tf32(float* c, const uint32_t* a, const uint32_t* b) {
    asm volatile("mma.sync.aligned.m16n8k8.row.col.f32.tf32.tf32.f32 "
                 "{%0,%1,%2,%3}, {%4,%5,%6,%7}, {%8,%9}, {%0,%1,%2,%3};"
                 : "+f"(c[0]), "+f"(c[1]), "+f"(c[2]), "+f"(c[3])
                 : "r"(a[0]), "r"(a[1]), "r"(a[2]), "r"(a[3]),
                   "r"(b[0]), "r"(b[1]));
}

// ---------------------------------------------------------------------------
// prep: fold LN gamma/beta into following 1x1 conv weights
// ---------------------------------------------------------------------------
__global__ void prep_kernel(const float* __restrict__ qkv1_w,
                            const float* __restrict__ ln1_w,
                            const float* __restrict__ ln1_b,
                            const float* __restrict__ pin_w,
                            const float* __restrict__ ln2_w,
                            const float* __restrict__ ln2_b) {
    int t = blockIdx.x * 256 + threadIdx.x;
    if (t < C3) {
        float s = 0.f, sb = 0.f;
        for (int c = 0; c < DIM; c++) {
            float w = qkv1_w[t * DIM + c];
            float wg = w * ln1_w[c];
            g_Wg1[t * DIM + c] = wg;
            s += wg; sb += w * ln1_b[c];
        }
        g_wgs1[t] = s; g_wb1[t] = sb;
    } else if (t < C3 + HID2) {
        int r = t - C3;
        float s = 0.f, sb = 0.f;
        for (int c = 0; c < DIM; c++) {
            float w = pin_w[r * DIM + c];
            float wg = w * ln2_w[c];
            g_Wg2[r * DIM + c] = wg;
            s += wg; sb += w * ln2_b[c];
        }
        g_wgs2[r] = s; g_wb2[r] = sb;
    }
}

// permute conv3x3 weights into fragment-native, tf32-rounded layout
// g_Wp[ocT][chunk][ky][og][kx][mb][lane][v]
__global__ void prep_wp_kernel(const float* __restrict__ qkv2_w) {
    int idx = blockIdx.x * 256 + threadIdx.x;
    if (idx >= WPSIZE) return;
    int v = idx & 3;
    int t = (idx >> 2) & 31;
    int r = idx >> 7;
    int mb = r % 3; r /= 3;
    int kx = r % 3; r /= 3;
    int og = r % 2; r /= 2;
    int ky = r % 3; r /= 3;
    int ch = r % NCHUNK; r /= NCHUNK;
    int ocT = r;
    int oc = ocT * 96 + og * 48 + mb * 16 + (t >> 2) + ((v & 1) ? 8 : 0);
    int ic = ch * 8 + (t & 3) + ((v >> 1) ? 4 : 0);
    g_Wp[idx] = tf32_rna(qkv2_w[(oc * C3 + ic) * 9 + ky * 3 + kx]);
}

__global__ void zero_kernel(float* __restrict__ p, int n) {
    int i = blockIdx.x * 256 + threadIdx.x;
    if (i < n) p[i] = 0.f;
}

// ---------------------------------------------------------------------------
// Per-pixel LayerNorm stats over 96 channels
// ---------------------------------------------------------------------------
__global__ __launch_bounds__(256) void ln_stats_kernel(const float* __restrict__ x,
                                                       float* __restrict__ mu,
                                                       float* __restrict__ rstd) {
    int idx = blockIdx.x * 256 + threadIdx.x;
    int b = idx >> 16;
    int p = idx & (HW - 1);
    const float* xp = x + (size_t)b * DIM * HW + p;
    float s = 0.f, s2 = 0.f;
#pragma unroll 8
    for (int c = 0; c < DIM; c++) {
        float v = xp[(size_t)c * HW];
        s += v; s2 += v * v;
    }
    float m = s * (1.f / DIM);
    float var = s2 * (1.f / DIM) - m * m;
    mu[idx] = m;
    rstd[idx] = rsqrtf(var + 1e-5f);
}

// ---------------------------------------------------------------------------
// Generic 1x1 conv (GEMM over pixels). Block: 32 oc x 256 px, 256 threads,
// thread tile 4 oc x 8 px.
// ---------------------------------------------------------------------------
template <int IC, bool LN, bool RES, bool TF32O>
__global__ __launch_bounds__(256) void conv1x1_kernel(
    const float* __restrict__ in, int in_bstride, int in_choff,
    const float* __restrict__ W, int w_bstride,
    const float* __restrict__ wgs, const float* __restrict__ wb,
    const float* __restrict__ mu, const float* __restrict__ rstd,
    const float* __restrict__ res,
    float* __restrict__ out) {
    const int N = HW;
    int b   = blockIdx.z;
    int oc0 = blockIdx.y * 32;
    int px0 = blockIdx.x * 256;
    int OCtot = gridDim.y * 32;
    int tid = threadIdx.x;
    int tx = tid & 31;       // pixel group (8 px each)
    int ty = tid >> 5;       // oc group (0..7, 4 oc each)

    __shared__ float sx[16][256];
    __shared__ float sw[32][16];

    float4 acc[4][2];
#pragma unroll
    for (int i = 0; i < 4; i++) {
        acc[i][0] = make_float4(0.f, 0.f, 0.f, 0.f);
        acc[i][1] = make_float4(0.f, 0.f, 0.f, 0.f);
    }

    const float* inb = in + (size_t)b * in_bstride + (size_t)in_choff * N + px0;
    const float* Wb  = W + (size_t)b * w_bstride + (size_t)oc0 * IC;

    for (int c0 = 0; c0 < IC; c0 += 16) {
#pragma unroll
        for (int k = 0; k < 4; k++) {
            int idx = tid + k * 256;      // 0..1023 float4 slots
            int cc = idx >> 6, col4 = idx & 63;
            *(float4*)&sx[cc][col4 * 4] =
                *(const float4*)&inb[(size_t)(c0 + cc) * N + col4 * 4];
        }
        {
            int idx = tid; int ocl = idx >> 4, cc = idx & 15;
            sw[ocl][cc] = Wb[ocl * IC + c0 + cc];
            idx = tid + 256; ocl = idx >> 4; cc = idx & 15;
            sw[ocl][cc] = Wb[ocl * IC + c0 + cc];
        }
        __syncthreads();
#pragma unroll
        for (int cc = 0; cc < 16; cc++) {
            float4 xv0 = *(const float4*)&sx[cc][tx * 8];
            float4 xv1 = *(const float4*)&sx[cc][tx * 8 + 4];
#pragma unroll
            for (int i = 0; i < 4; i++) {
                float w = sw[ty * 4 + i][cc];
                acc[i][0].x += w * xv0.x; acc[i][0].y += w * xv0.y;
                acc[i][0].z += w * xv0.z; acc[i][0].w += w * xv0.w;
                acc[i][1].x += w * xv1.x; acc[i][1].y += w * xv1.y;
                acc[i][1].z += w * xv1.z; acc[i][1].w += w * xv1.w;
            }
        }
        __syncthreads();
    }

    int p = px0 + tx * 8;
    float4 m4[2], r4[2];
    if (LN) {
        m4[0] = *(const float4*)&mu[(size_t)b * N + p];
        m4[1] = *(const float4*)&mu[(size_t)b * N + p + 4];
        r4[0] = *(const float4*)&rstd[(size_t)b * N + p];
        r4[1] = *(const float4*)&rstd[(size_t)b * N + p + 4];
    }
#pragma unroll
    for (int i = 0; i < 4; i++) {
        int oc = oc0 + ty * 4 + i;
        float gsum = 0.f, bbv = 0.f;
        if (LN) { gsum = wgs[oc]; bbv = wb[oc]; }
#pragma unroll
        for (int hh = 0; hh < 2; hh++) {
            float4 r = acc[i][hh];
            if (LN) {
                r.x = r4[hh].x * (r.x - m4[hh].x * gsum) + bbv;
                r.y = r4[hh].y * (r.y - m4[hh].y * gsum) + bbv;
                r.z = r4[hh].z * (r.z - m4[hh].z * gsum) + bbv;
                r.w = r4[hh].w * (r.w - m4[hh].w * gsum) + bbv;
            }
            if (RES) {
                float4 rr = *(const float4*)&res[((size_t)b * OCtot + oc) * N + p + hh * 4];
                r.x += rr.x; r.y += rr.y; r.z += rr.z; r.w += rr.w;
            }
            if (TF32O) {
                r.x = tf32_rna(r.x); r.y = tf32_rna(r.y);
                r.z = tf32_rna(r.z); r.w = tf32_rna(r.w);
            }
            *(float4*)&out[((size_t)b * OCtot + oc) * N + p + hh * 4] = r;
        }
    }
}

// ---------------------------------------------------------------------------
// 3x3 conv 288 -> 288 via TF32 mma.sync implicit GEMM.
// Block: 96 oc x 256 px (one image row). 8 warps = 2(oc) x 4(px).
// Stage = 8-ic chunk: 3 input rows + full chunk weights, double-buffered
// cp.async (16B only). 36 stages, 216 MMA per warp per stage.
// ---------------------------------------------------------------------------
__global__ __launch_bounds__(256) void conv3x3_mma_kernel(const float* __restrict__ in,
                                                          float* __restrict__ out) {
    extern __shared__ float dynsmem[];
    float* bsm = dynsmem;                      // [2][8][3][BROW], interior at +8
    float* wsm = dynsmem + 2 * BSMSZ;          // [2][WCHUNK]

    int b   = blockIdx.z;
    int ocT = blockIdx.y;
    int y   = blockIdx.x;
    int tid = threadIdx.x;
    int warp = tid >> 5, lane = tid & 31;
    int og = warp >> 2;          // 0..1 oc group
    int pg = warp & 3;           // 0..3 pixel group
    int tg = lane >> 2;          // 0..7
    int tig = lane & 3;          // 0..3

    // zero halo columns (idx 7 and 264) once, both buffers
    if (tid < 96) {
        int bufi = tid & 1;
        int t2 = tid >> 1;                   // 0..47
        int colh = (t2 & 1) ? 264 : 7;
        int t3 = t2 >> 1;                    // 0..23
        int r = t3 % 3, ic = t3 / 3;
        bsm[bufi * BSMSZ + (ic * 3 + r) * BROW + colh] = 0.f;
    }

    float acc[3][8][4];
#pragma unroll
    for (int mb = 0; mb < 3; mb++)
#pragma unroll
        for (int j = 0; j < 8; j++)
#pragma unroll
            for (int v = 0; v < 4; v++) acc[mb][j][v] = 0.f;

    const float* wp_base = g_Wp + (size_t)ocT * NCHUNK * WCHUNK;

    auto issue = [&](int ch, int buf) {
        int q = tid & 63, rr = tid >> 6;     // q = float4 col, rr = 0..3
        const float* ibase = in + ((size_t)b * C3 + ch * 8) * HW;
        float* bdst = bsm + buf * BSMSZ;
#pragma unroll
        for (int p = 0; p < 6; p++) {
            int pair = p * 4 + rr;           // 0..23 = (ic, r)
            int ic = pair / 3;
            int r = pair - 3 * ic;
            int gy = y + r - 1;
            bool v = (unsigned)gy < 256u;
            int gyc = v ? gy : 0;
            const float* src = ibase + ((size_t)ic * IMG + gyc) * IMG + q * 4;
            uint32_t dst = (uint32_t)__cvta_generic_to_shared(
                bdst + (ic * 3 + r) * BROW + 8 + q * 4);
            cpa16z(dst, src, v);
        }
        const float* wsrc = wp_base + (size_t)ch * WCHUNK;
        float* wdst = wsm + buf * WCHUNK;
#pragma unroll
        for (int k = 0; k < 7; k++) {
            int i = tid + k * 256;
            if (i < WCHUNK / 4)
                cpa16((uint32_t)__cvta_generic_to_shared(wdst + i * 4), wsrc + i * 4);
        }
        asm volatile("cp.async.commit_group;");
    };

    issue(0, 0);

    for (int s = 0; s < NCHUNK; s++) {
        if (s + 1 < NCHUNK) {
            issue(s + 1, (s + 1) & 1);
            asm volatile("cp.async.wait_group 1;");
        } else {
            asm volatile("cp.async.wait_group 0;");
        }
        __syncthreads();

        int buf = s & 1;
        const float* bb = bsm + buf * BSMSZ;
        const float* wc = wsm + buf * WCHUNK;
        int colbase = 7 + pg * 64 + tg;
#pragma unroll
        for (int ky = 0; ky < 3; ky++) {
            const float* wbp = wc + (ky * 2 + og) * 1152;
#pragma unroll
            for (int kx = 0; kx < 3; kx++) {
                uint32_t a[3][4];
#pragma unroll
                for (int mb = 0; mb < 3; mb++) {
                    float4 av = *(const float4*)&wbp[(kx * 3 + mb) * 128 + lane * 4];
                    a[mb][0] = __float_as_uint(av.x);
                    a[mb][1] = __float_as_uint(av.y);
                    a[mb][2] = __float_as_uint(av.z);
                    a[mb][3] = __float_as_uint(av.w);
                }
                uint32_t bf[8][2];
#pragma unroll
                for (int j = 0; j < 8; j++) {
                    int col = colbase + 8 * j + kx;
                    bf[j][0] = __float_as_uint(bb[(tig * 3 + ky) * BROW + col]);
                    bf[j][1] = __float_as_uint(bb[((tig + 4) * 3 + ky) * BROW + col]);
                }
#pragma unroll
                for (int mb = 0; mb < 3; mb++)
#pragma unroll
                    for (int j = 0; j < 8; j++)
                        mma_tf32(acc[mb][j], a[mb], bf[j]);
            }
        }
        __syncthreads();
    }

    // epilogue: c0,c1 -> (row tg, cols 2*tig, 2*tig+1); c2,c3 -> row tg+8
#pragma unroll
    for (int mb = 0; mb < 3; mb++) {
        int oc = ocT * 96 + og * 48 + mb * 16 + tg;
#pragma unroll
        for (int j = 0; j < 8; j++) {
            int px = pg * 64 + 8 * j + 2 * tig;
            float2 v01 = make_float2(acc[mb][j][0], acc[mb][j][1]);
            float2 v23 = make_float2(acc[mb][j][2], acc[mb][j][3]);
            *(float2*)&out[(((size_t)b * C3 + oc) * IMG + y) * IMG + px] = v01;
            *(float2*)&out[(((size_t)b * C3 + oc + 8) * IMG + y) * IMG + px] = v23;
        }
    }
}

// ---------------------------------------------------------------------------
// Sum of squares per (b, channel) over HW for q and k (float4)
// ---------------------------------------------------------------------------
__global__ __launch_bounds__(256) void sumsq_kernel(const float* __restrict__ qkv2,
                                                    float* __restrict__ sqk) {
    int c = blockIdx.x;
    int b = blockIdx.y;
    int tid = threadIdx.x;
    const float4* p = (const float4*)(qkv2 + ((size_t)b * C3 + c) * HW);
    float s = 0.f;
    for (int i = tid; i < HW / 4; i += 256) {
        float4 v = p[i];
        s += v.x * v.x + v.y * v.y + v.z * v.z + v.w * v.w;
    }
#pragma unroll
    for (int o = 16; o > 0; o >>= 1) s += __shfl_down_sync(0xffffffffu, s, o);
    __shared__ float red[8];
    if ((tid & 31) == 0) red[tid >> 5] = s;
    __syncthreads();
    if (tid == 0) {
        float tot = 0.f;
#pragma unroll
        for (int i = 0; i < 8; i++) tot += red[i];
        sqk[b * 2 * DIM + c] = tot;
    }
}

// ---------------------------------------------------------------------------
// Channel-gram via TF32 warp MMA over K = pixels.
// Warp computes a 16x16 partial gram for one (b,h) over 64 k32-slabs.
// K-permutation chosen so all operand loads are float4.
// Stores CORRECT orientation: attn_raw[bh*256 + c*16 + d] += q_c . k_d
// ---------------------------------------------------------------------------
__global__ __launch_bounds__(256) void attn_mma_kernel(const float* __restrict__ qkv2,
                                                       float* __restrict__ attn_raw) {
    int bh = blockIdx.y;
    int b = bh / HEADS, h = bh - b * HEADS;
    int warp = threadIdx.x >> 5, lane = threadIdx.x & 31;
    int tg = lane >> 2, tig = lane & 3;

    const float* qb = qkv2 + ((size_t)b * C3 + h * HDIM) * HW;
    const float* kb = qkv2 + ((size_t)b * C3 + DIM + h * HDIM) * HW;
    const float* qr0 = qb + (size_t)tg * HW;
    const float* qr1 = qb + (size_t)(tg + 8) * HW;
    const float* kr0 = kb + (size_t)tg * HW;
    const float* kr1 = kb + (size_t)(tg + 8) * HW;

    float c0[4] = {0.f, 0.f, 0.f, 0.f};
    float c1[4] = {0.f, 0.f, 0.f, 0.f};

    int slab0 = (blockIdx.x * 8 + warp) * 64;
    for (int s = 0; s < 64; s++) {
        int n0 = (slab0 + s) * 32 + tig * 8;
        float qv[4][4], kv[4][4];
        *(float4*)qv[0] = *(const float4*)(qr0 + n0);       // A row tg,   k lo
        *(float4*)qv[1] = *(const float4*)(qr1 + n0);       // A row tg+8, k lo
        *(float4*)qv[2] = *(const float4*)(qr0 + n0 + 4);   // A row tg,   k hi
        *(float4*)qv[3] = *(const float4*)(qr1 + n0 + 4);   // A row tg+8, k hi
        *(float4*)kv[0] = *(const float4*)(kr0 + n0);       // B col tg,   k lo
        *(float4*)kv[1] = *(const float4*)(kr0 + n0 + 4);   // B col tg,   k hi
        *(float4*)kv[2] = *(const float4*)(kr1 + n0);       // B col tg+8, k lo
        *(float4*)kv[3] = *(const float4*)(kr1 + n0 + 4);   // B col tg+8, k hi
#pragma unroll
        for (int m = 0; m < 4; m++) {
            uint32_t a[4] = { __float_as_uint(qv[0][m]), __float_as_uint(qv[1][m]),
                              __float_as_uint(qv[2][m]), __float_as_uint(qv[3][m]) };
            uint32_t b0[2] = { __float_as_uint(kv[0][m]), __float_as_uint(kv[1][m]) };
            uint32_t b1[2] = { __float_as_uint(kv[2][m]), __float_as_uint(kv[3][m]) };
            mma_tf32(c0, a, b0);
            mma_tf32(c1, a, b1);
        }
    }

    float* dst = attn_raw + bh * 256;
    atomicAdd(dst + tg * 16 + 2 * tig,           c0[0]);
    atomicAdd(dst + tg * 16 + 2 * tig + 1,       c0[1]);
    atomicAdd(dst + (tg + 8) * 16 + 2 * tig,     c0[2]);
    atomicAdd(dst + (tg + 8) * 16 + 2 * tig + 1, c0[3]);
    atomicAdd(dst + tg * 16 + 8 + 2 * tig,           c1[0]);
    atomicAdd(dst + tg * 16 + 8 + 2 * tig + 1,       c1[1]);
    atomicAdd(dst + (tg + 8) * 16 + 8 + 2 * tig,     c1[2]);
    atomicAdd(dst + (tg + 8) * 16 + 8 + 2 * tig + 1, c1[3]);
}

// ---------------------------------------------------------------------------
// softmax + build fused per-batch 96x96 matrix M = proj @ blockdiag(attn)
// ---------------------------------------------------------------------------
__global__ __launch_bounds__(256) void softmax_build_M(const float* __restrict__ attn_raw,
                                                       const float* __restrict__ sqk,
                                                       const float* __restrict__ scale,
                                                       const float* __restrict__ proj_w,
                                                       float* __restrict__ M) {
    int b = blockIdx.x;
    int t = threadIdx.x;
    __shared__ float A[HEADS * 256];
    __shared__ float nq[DIM], nk[DIM];
    if (t < DIM) {
        nq[t] = fmaxf(sqrtf(sqk[b * 2 * DIM + t]), 1e-12f);
        nk[t] = fmaxf(sqrtf(sqk[b * 2 * DIM + DIM + t]), 1e-12f);
    }
    __syncthreads();
    for (int idx = t; idx < HEADS * 256; idx += 256) {
        int h = idx >> 8;
        int cd = idx & 255;
        int c = cd >> 4, d = cd & 15;
        A[idx] = attn_raw[b * HEADS * 256 + idx] /
                 (nq[h * HDIM + c] * nk[h * HDIM + d]) * scale[h];
    }
    __syncthreads();
    if (t < DIM) {
        int h = t >> 4, c = t & 15;
        float* row = &A[h * 256 + c * 16];
        float mx = row[0];
#pragma unroll
        for (int d = 1; d < 16; d++) mx = fmaxf(mx, row[d]);
        float sum = 0.f;
#pragma unroll
        for (int d = 0; d < 16; d++) { float e = expf(row[d] - mx); row[d] = e; sum += e; }
        float inv = 1.f / sum;
#pragma unroll
        for (int d = 0; d < 16; d++) row[d] *= inv;
    }
    __syncthreads();
    for (int idx = t; idx < DIM * DIM; idx += 256) {
        int o = idx / DIM, j = idx % DIM;
        int h = j >> 4, d = j & 15;
        float s = 0.f;
#pragma unroll
        for (int cg = 0; cg < 16; cg++)
            s += proj_w[o * DIM + h * HDIM + cg] * A[h * 256 + cg * 16 + d];
        M[b * DIM * DIM + idx] = s;
    }
}

// ---------------------------------------------------------------------------
// Grouped 3x3 conv (192 groups, 2 ch/group) fused with GELU gate.
// ---------------------------------------------------------------------------
__device__ __forceinline__ float gelu_tanh(float x) {
    float x3 = x * x * x;
    return 0.5f * x * (1.f + tanhf(0.7978845608028654f * (x + 0.044715f * x3)));
}

__global__ __launch_bounds__(128) void dwgate_kernel(const float* __restrict__ tin,
                                                     const float* __restrict__ dw,
                                                     float* __restrict__ g) {
    int b = blockIdx.z;
    int m = blockIdx.y;
    int y = blockIdx.x >> 1;
    int px0 = (blockIdx.x & 1) * 128;
    int tid = threadIdx.x;

    __shared__ float sin_s[4][3][132];
    __shared__ float swt[72];

    int chans[4] = {2 * m, 2 * m + 1, HID + 2 * m, HID + 2 * m + 1};

    for (int idx = tid; idx < 4 * 3 * 130; idx += 128) {
        int ch = idx / 390;
        int rem = idx - ch * 390;
        int r = rem / 130;
        int l = rem - r * 130;
        int gy = y + r - 1, gx = px0 - 1 + l;
        float v = 0.f;
        if ((unsigned)gy < 256u && (unsigned)gx < 256u)
            v = tin[(((size_t)b * HID2 + chans[ch]) * IMG + gy) * IMG + gx];
        sin_s[ch][r][l] = v;
    }
    if (tid < 72) {
        int oci = tid / 18;
        int rem = tid - oci * 18;
        swt[tid] = dw[(size_t)chans[oci] * 18 + rem];
    }
    __syncthreads();

    float u[4] = {0.f, 0.f, 0.f, 0.f};
#pragma unroll
    for (int ol = 0; ol < 4; ol++) {
        int i0 = (ol < 2) ? 0 : 2;
#pragma unroll
        for (int i = 0; i < 2; i++)
#pragma unroll
            for (int ky = 0; ky < 3; ky++)
#pragma unroll
                for (int kx = 0; kx < 3; kx++)
                    u[ol] += swt[ol * 18 + i * 9 + ky * 3 + kx] * sin_s[i0 + i][ky][tid + kx];
    }
    float r0 = gelu_tanh(u[0]) * u[2];
    float r1 = gelu_tanh(u[1]) * u[3];
    size_t o0 = (((size_t)b * HID + 2 * m) * IMG + y) * IMG + px0 + tid;
    g[o0] = r0;
    g[o0 + HW] = r1;
}

// ---------------------------------------------------------------------------
// Launch
// ---------------------------------------------------------------------------
static float* sym_addr(const void* sym) {
    void* p = nullptr;
    cudaGetSymbolAddress(&p, sym);
    return (float*)p;
}

extern "C" void kernel_launch(void* const* d_in, const int* in_sizes, int n_in,
                              void* d_out, int out_size) {
    const float* x      = (const float*)d_in[0];
    const float* ln1_w  = (const float*)d_in[1];
    const float* ln1_b  = (const float*)d_in[2];
    const float* qkv1_w = (const float*)d_in[3];
    const float* qkv2_w = (const float*)d_in[4];
    const float* proj_w = (const float*)d_in[5];
    const float* scale  = (const float*)d_in[6];
    const float* ln2_w  = (const float*)d_in[7];
    const float* ln2_b  = (const float*)d_in[8];
    const float* pin_w  = (const float*)d_in[9];
    const float* dw_w   = (const float*)d_in[10];
    const float* pout_w = (const float*)d_in[11];

    float* qkv   = sym_addr(g_qkv);
    float* qkv2  = sym_addr(g_qkv2);
    float* tbuf  = sym_addr(g_t);
    float* gbuf  = sym_addr(g_g);
    float* x2    = sym_addr(g_x2);
    float* mu    = sym_addr(g_mu);
    float* rstd  = sym_addr(g_rstd);
    float* Wg1   = sym_addr(g_Wg1);
    float* wgs1  = sym_addr(g_wgs1);
    float* wb1   = sym_addr(g_wb1);
    float* Wg2   = sym_addr(g_Wg2);
    float* wgs2  = sym_addr(g_wgs2);
    float* wb2   = sym_addr(g_wb2);
    float* sqk   = sym_addr(g_sqk);
    float* attn  = sym_addr(g_attn);
    float* M     = sym_addr(g_M);
    float* out   = (float*)d_out;

    static bool attr_done = false;
    if (!attr_done) {
        cudaFuncSetAttribute(conv3x3_mma_kernel,
                             cudaFuncAttributeMaxDynamicSharedMemorySize, SMEM3);
        attr_done = true;
    }

    // weight prep + zero attn accumulator
    prep_kernel<<<3, 256>>>(qkv1_w, ln1_w, ln1_b, pin_w, ln2_w, ln2_b);
    prep_wp_kernel<<<(WPSIZE + 255) / 256, 256>>>(qkv2_w);
    zero_kernel<<<24, 256>>>(attn, BATCH * HEADS * 256);

    // LN1 stats, then LN-fused qkv1 (96 -> 288), tf32-rounded output
    ln_stats_kernel<<<(BATCH * HW) / 256, 256>>>(x, mu, rstd);
    conv1x1_kernel<DIM, true, false, true><<<dim3(256, 9, BATCH), 256>>>(
        x, DIM * HW, 0, Wg1, 0, wgs1, wb1, mu, rstd, nullptr, qkv);

    // qkv2: 3x3 conv 288 -> 288 via TF32 tensor cores
    conv3x3_mma_kernel<<<dim3(256, 3, BATCH), 256, SMEM3>>>(qkv, qkv2);

    // attention statistics
    sumsq_kernel<<<dim3(2 * DIM, BATCH), 256>>>(qkv2, sqk);
    attn_mma_kernel<<<dim3(4, BATCH * HEADS), 256>>>(qkv2, attn);
    softmax_build_M<<<BATCH, 256>>>(attn, sqk, scale, proj_w, M);

    // fused (attn@v -> proj -> +x): per-batch 96x96 matrix over v channels
    conv1x1_kernel<DIM, false, true, false><<<dim3(256, 3, BATCH), 256>>>(
        qkv2, C3 * HW, 2 * DIM, M, DIM * DIM, nullptr, nullptr, nullptr, nullptr, x, x2);

    // LN2 stats, LN-fused pin (96 -> 384)
    ln_stats_kernel<<<(BATCH * HW) / 256, 256>>>(x2, mu, rstd);
    conv1x1_kernel<DIM, true, false, false><<<dim3(256, 12, BATCH), 256>>>(
        x2, DIM * HW, 0, Wg2, 0, wgs2, wb2, mu, rstd, nullptr, tbuf);

    // grouped 3x3 conv + GELU gate (384 -> 192)
    dwgate_kernel<<<dim3(512, DIM, BATCH), 128>>>(tbuf, dw_w, gbuf);

    // pout (192 -> 96) + residual -> output
    conv1x1_kernel<HID, false, true, false><<<dim3(256, 3, BATCH), 256>>>(
        gbuf, HID * HW, 0, pout_w, 0, nullptr, nullptr, nullptr, nullptr, x2, out);
}

// round 6
// speedup vs baseline: 5.9837x; 1.7395x over previous
#include <cuda_runtime.h>
#include <cuda_bf16.h>
#include <cmath>
#include <cstdint>

// ---------------------------------------------------------------------------
// Problem constants
// ---------------------------------------------------------------------------
#define BATCH 4
#define DIM   96
#define HEADS 6
#define HDIM  16           // channels per head
#define C3    288          // 3*DIM
#define HID   192
#define HID2  384          // 2*HID
#define HW    65536        // 256*256
#define IMG   256

// conv3x3 bf16 mma tiling: chunk = 16 ic
#define NCH3   18                      // 288/16
#define BROWC  268                     // smem row stride (floats); 268 % 32 == 4
#define BSMC   (16 * 3 * BROWC)        // floats per input buffer (12864)
#define WCH3   6912                    // u32 per weight chunk: 96oc*16ic*9taps / 2
#define WP3SZ  (3 * NCH3 * WCH3)       // 373248 u32
#define SMEM3  ((2 * BSMC) * 4 + 2 * WCH3 * 4)   // 158208 bytes

// conv1x1 bf16 mma: chunk = 16 ic, block = 96 oc x 256 px
#define BR1    268

// ---------------------------------------------------------------------------
// Scratch (device globals; no allocation allowed)
// ---------------------------------------------------------------------------
__device__ float g_qkv  [(size_t)BATCH * C3  * HW];   // after qkv1 (1x1)
__device__ float g_qkv2 [(size_t)BATCH * C3  * HW];   // after qkv2 (3x3)
__device__ float g_t    [(size_t)BATCH * HID2 * HW];  // after pin (1x1)
__device__ float g_g    [(size_t)BATCH * HID * HW];   // after dwconv+gate
__device__ float g_x2   [(size_t)BATCH * DIM * HW];   // residual after attention
__device__ float g_mu   [BATCH * HW];
__device__ float g_rstd [BATCH * HW];
__device__ float g_wgs1 [C3];
__device__ float g_wb1  [C3];
__device__ float g_wgs2 [HID2];
__device__ float g_wb2  [HID2];
__device__ float g_sqk  [BATCH * 2 * DIM];
__device__ float g_attn [BATCH * HEADS * HDIM * HDIM];
__device__ __align__(16) uint32_t g_Wp1 [C3 * DIM / 2];        // packed bf16 qkv1 (LN-folded)
__device__ __align__(16) uint32_t g_Wp2 [HID2 * DIM / 2];      // packed bf16 pin (LN-folded)
__device__ __align__(16) uint32_t g_Wpo [DIM * HID / 2];       // packed bf16 pout
__device__ __align__(16) uint32_t g_Mp  [BATCH * DIM * DIM / 2]; // packed bf16 fused attn matrix
__device__ __align__(16) uint32_t g_Wp3 [WP3SZ];               // packed bf16 conv3x3 weights

// ---------------------------------------------------------------------------
// helpers
// ---------------------------------------------------------------------------
__device__ __forceinline__ void cpa16(uint32_t dst, const void* src) {
    asm volatile("cp.async.cg.shared.global [%0], [%1], 16;"
                 :: "r"(dst), "l"(src));
}
__device__ __forceinline__ void cpa16z(uint32_t dst, const void* src, bool v) {
    asm volatile("cp.async.cg.shared.global [%0], [%1], 16, %2;"
                 :: "r"(dst), "l"(src), "r"(v ? 16u : 0u));
}

// pack two fp32 -> bf16x2 (lo = first arg)
__device__ __forceinline__ uint32_t packbf(float lo, float hi) {
    uint32_t r;
    asm("cvt.rn.bf16x2.f32 %0, %1, %2;" : "=r"(r) : "f"(hi), "f"(lo));
    return r;
}

__device__ __forceinline__ void mma_bf16(float* c, const uint32_t* a,
                                         uint32_t b0, uint32_t b1) {
    asm volatile("mma.sync.aligned.m16n8k16.row.col.f32.bf16.bf16.f32 "
                 "{%0,%1,%2,%3}, {%4,%5,%6,%7}, {%8,%9}, {%0,%1,%2,%3};"
                 : "+f"(c[0]), "+f"(c[1]), "+f"(c[2]), "+f"(c[3])
                 : "r"(a[0]), "r"(a[1]), "r"(a[2]), "r"(a[3]),
                   "r"(b0), "r"(b1));
}

__device__ __forceinline__ void mma_tf32(float* c, const uint32_t* a, const uint32_t* b) {
    asm volatile("mma.sync.aligned.m16n8k8.row.col.f32.tf32.tf32.f32 "
                 "{%0,%1,%2,%3}, {%4,%5,%6,%7}, {%8,%9}, {%0,%1,%2,%3};"
                 : "+f"(c[0]), "+f"(c[1]), "+f"(c[2]), "+f"(c[3])
                 : "r"(a[0]), "r"(a[1]), "r"(a[2]), "r"(a[3]),
                   "r"(b[0]), "r"(b[1]));
}

// ---------------------------------------------------------------------------
// prep: LN row sums for folded 1x1 convs
// ---------------------------------------------------------------------------
__global__ void prep_kernel(const float* __restrict__ qkv1_w,
                            const float* __restrict__ ln1_w,
                            const float* __restrict__ ln1_b,
                            const float* __restrict__ pin_w,
                            const float* __restrict__ ln2_w,
                            const float* __restrict__ ln2_b) {
    int t = blockIdx.x * 256 + threadIdx.x;
    if (t < C3) {
        float s = 0.f, sb = 0.f;
        for (int c = 0; c < DIM; c++) {
            float w = qkv1_w[t * DIM + c];
            s += w * ln1_w[c]; sb += w * ln1_b[c];
        }
        g_wgs1[t] = s; g_wb1[t] = sb;
    } else if (t < C3 + HID2) {
        int r = t - C3;
        float s = 0.f, sb = 0.f;
        for (int c = 0; c < DIM; c++) {
            float w = pin_w[r * DIM + c];
            s += w * ln2_w[c]; sb += w * ln2_b[c];
        }
        g_wgs2[r] = s; g_wb2[r] = sb;
    }
}

// pack a 1x1 weight matrix [OC][ICt] into bf16 fragment-native u32 layout,
// optionally folding gamma: u32 idx = ((((ocT*(ICt/16)+ch)*2+og)*3+mb)*32+lane)*4+v
template <bool FOLD>
__global__ void pack1x1_kernel(const float* __restrict__ W,
                               const float* __restrict__ gamma,
                               uint32_t* __restrict__ dst, int OC, int ICt) {
    int idx = blockIdx.x * 256 + threadIdx.x;
    if (idx >= OC * ICt / 2) return;
    int r = idx;
    int v = r & 3; r >>= 2;
    int lane = r & 31; r >>= 5;
    int mb = r % 3; r /= 3;
    int og = r % 2; r /= 2;
    int nch = ICt / 16;
    int ch = r % nch; r /= nch;
    int ocT = r;
    int g = lane >> 2, t = lane & 3;
    int oc = ocT * 96 + og * 48 + mb * 16 + g + (v & 1) * 8;
    int ic = ch * 16 + 2 * t + (v >> 1) * 8;
    float w0 = W[oc * ICt + ic], w1 = W[oc * ICt + ic + 1];
    if (FOLD) { w0 *= gamma[ic]; w1 *= gamma[ic + 1]; }
    __nv_bfloat162 p = __floats2bfloat162_rn(w0, w1);
    dst[idx] = *reinterpret_cast<uint32_t*>(&p);
}

// pack conv3x3 weights: layout [ocT][ch][ky][og][kx][mb][lane][v]
__global__ void pack3x3_kernel(const float* __restrict__ W) {
    int idx = blockIdx.x * 256 + threadIdx.x;
    if (idx >= WP3SZ) return;
    int r = idx;
    int v = r & 3; r >>= 2;
    int lane = r & 31; r >>= 5;
    int mb = r % 3; r /= 3;
    int kx = r % 3; r /= 3;
    int og = r % 2; r /= 2;
    int ky = r % 3; r /= 3;
    int ch = r % NCH3; r /= NCH3;
    int ocT = r;
    int g = lane >> 2, t = lane & 3;
    int oc = ocT * 96 + og * 48 + mb * 16 + g + (v & 1) * 8;
    int ic = ch * 16 + 2 * t + (v >> 1) * 8;
    float w0 = W[(oc * C3 + ic) * 9 + ky * 3 + kx];
    float w1 = W[(oc * C3 + ic + 1) * 9 + ky * 3 + kx];
    __nv_bfloat162 p = __floats2bfloat162_rn(w0, w1);
    g_Wp3[idx] = *reinterpret_cast<uint32_t*>(&p);
}

__global__ void zero_kernel(float* __restrict__ p, int n) {
    int i = blockIdx.x * 256 + threadIdx.x;
    if (i < n) p[i] = 0.f;
}

// ---------------------------------------------------------------------------
// Per-pixel LayerNorm stats over 96 channels
// ---------------------------------------------------------------------------
__global__ __launch_bounds__(256) void ln_stats_kernel(const float* __restrict__ x,
                                                       float* __restrict__ mu,
                                                       float* __restrict__ rstd) {
    int idx = blockIdx.x * 256 + threadIdx.x;
    int b = idx >> 16;
    int p = idx & (HW - 1);
    const float* xp = x + (size_t)b * DIM * HW + p;
    float s = 0.f, s2 = 0.f;
#pragma unroll 8
    for (int c = 0; c < DIM; c++) {
        float v = xp[(size_t)c * HW];
        s += v; s2 += v * v;
    }
    float m = s * (1.f / DIM);
    float var = s2 * (1.f / DIM) - m * m;
    mu[idx] = m;
    rstd[idx] = rsqrtf(var + 1e-5f);
}

// ---------------------------------------------------------------------------
// 1x1 conv via bf16 m16n8k16 mma. Block: 96 oc x 256 px, 8 warps = 2og x 4pg.
// Warp tile 48 oc x 64 px. K chunked by 16 ic, cp.async double-buffered.
// Optional fused LN input (folded weights + per-pixel stats), residual add.
// ---------------------------------------------------------------------------
template <int IC, bool LN, bool RES>
__global__ __launch_bounds__(256) void conv1x1_bmma_kernel(
    const float* __restrict__ in, int in_bstride, int in_choff,
    const uint32_t* __restrict__ Wp, int w_bstride,
    const float* __restrict__ wgs, const float* __restrict__ wb,
    const float* __restrict__ mu, const float* __restrict__ rstd,
    const float* __restrict__ res,
    float* __restrict__ out) {
    constexpr int NCH = IC / 16;
    __shared__ __align__(16) float bsm[2][16 * BR1];
    __shared__ __align__(16) uint32_t wsm[2][768];
    __shared__ float smu[256], srstd[256];

    int b = blockIdx.z;
    int ocT = blockIdx.y;
    int px0 = blockIdx.x * 256;
    int OCtot = gridDim.y * 96;
    int tid = threadIdx.x;
    int warp = tid >> 5, lane = tid & 31;
    int og = warp >> 2, pg = warp & 3;
    int g = lane >> 2, t = lane & 3;

    if (LN) {
        if (tid < 64)
            *(float4*)&smu[tid * 4] = *(const float4*)&mu[(size_t)b * HW + px0 + tid * 4];
        else if (tid < 128) {
            int q = tid - 64;
            *(float4*)&srstd[q * 4] = *(const float4*)&rstd[(size_t)b * HW + px0 + q * 4];
        }
    }

    float acc[3][8][4];
#pragma unroll
    for (int mb = 0; mb < 3; mb++)
#pragma unroll
        for (int j = 0; j < 8; j++)
#pragma unroll
            for (int v = 0; v < 4; v++) acc[mb][j][v] = 0.f;

    const uint32_t* Wb = Wp + (size_t)b * w_bstride + (size_t)ocT * NCH * 768;

    auto issue = [&](int ch, int buf) {
#pragma unroll
        for (int k = 0; k < 4; k++) {
            int idx = tid + k * 256;
            int ic = idx >> 6, c4 = idx & 63;
            const float* src = in + (size_t)b * in_bstride +
                               (size_t)(in_choff + ch * 16 + ic) * HW + px0 + c4 * 4;
            cpa16((uint32_t)__cvta_generic_to_shared(&bsm[buf][ic * BR1 + c4 * 4]), src);
        }
        if (tid < 192)
            cpa16((uint32_t)__cvta_generic_to_shared(&wsm[buf][tid * 4]),
                  Wb + ch * 768 + tid * 4);
        asm volatile("cp.async.commit_group;");
    };

    issue(0, 0);

    for (int s = 0; s < NCH; s++) {
        if (s + 1 < NCH) {
            issue(s + 1, (s + 1) & 1);
            asm volatile("cp.async.wait_group 1;");
        } else {
            asm volatile("cp.async.wait_group 0;");
        }
        __syncthreads();

        int buf = s & 1;
        const uint32_t* wc = &wsm[buf][og * 384];
        uint32_t a[3][4];
#pragma unroll
        for (int mb = 0; mb < 3; mb++)
            *(uint4*)a[mb] = *(const uint4*)&wc[mb * 128 + lane * 4];
        const float* bB = &bsm[buf][0];
#pragma unroll
        for (int j = 0; j < 8; j++) {
            int col = pg * 64 + 8 * j + g;
            float x0 = bB[(2 * t) * BR1 + col];
            float x1 = bB[(2 * t + 1) * BR1 + col];
            float x2 = bB[(2 * t + 8) * BR1 + col];
            float x3 = bB[(2 * t + 9) * BR1 + col];
            uint32_t b0 = packbf(x0, x1), b1 = packbf(x2, x3);
#pragma unroll
            for (int mb = 0; mb < 3; mb++)
                mma_bf16(acc[mb][j], a[mb], b0, b1);
        }
        __syncthreads();
    }

    // epilogue
#pragma unroll
    for (int mb = 0; mb < 3; mb++) {
        int oc = ocT * 96 + og * 48 + mb * 16 + g;
        float gs0 = 0.f, gs8 = 0.f, bb0 = 0.f, bb8 = 0.f;
        if (LN) {
            gs0 = wgs[oc]; gs8 = wgs[oc + 8];
            bb0 = wb[oc];  bb8 = wb[oc + 8];
        }
#pragma unroll
        for (int j = 0; j < 8; j++) {
            int pl = pg * 64 + 8 * j + 2 * t;
            int px = px0 + pl;
            float v00 = acc[mb][j][0], v01 = acc[mb][j][1];
            float v10 = acc[mb][j][2], v11 = acc[mb][j][3];
            if (LN) {
                float m0 = smu[pl], m1 = smu[pl + 1];
                float r0 = srstd[pl], r1 = srstd[pl + 1];
                v00 = r0 * (v00 - m0 * gs0) + bb0;
                v01 = r1 * (v01 - m1 * gs0) + bb0;
                v10 = r0 * (v10 - m0 * gs8) + bb8;
                v11 = r1 * (v11 - m1 * gs8) + bb8;
            }
            if (RES) {
                float2 ra = *(const float2*)&res[((size_t)b * OCtot + oc) * HW + px];
                float2 rb = *(const float2*)&res[((size_t)b * OCtot + oc + 8) * HW + px];
                v00 += ra.x; v01 += ra.y; v10 += rb.x; v11 += rb.y;
            }
            *(float2*)&out[((size_t)b * OCtot + oc) * HW + px] = make_float2(v00, v01);
            *(float2*)&out[((size_t)b * OCtot + oc + 8) * HW + px] = make_float2(v10, v11);
        }
    }
}

// ---------------------------------------------------------------------------
// 3x3 conv 288 -> 288 via bf16 m16n8k16 mma implicit GEMM.
// Block: 96 oc x 256 px (one image row). Stage = 16-ic chunk (3 rows + weights),
// double-buffered cp.async. 18 stages, 216 MMA per warp per stage.
// ---------------------------------------------------------------------------
__global__ __launch_bounds__(256) void conv3x3_bmma_kernel(const float* __restrict__ in,
                                                           float* __restrict__ out) {
    extern __shared__ float dynsmem[];
    float* bsm = dynsmem;                                 // [2][16][3][BROWC], interior +4
    uint32_t* wsm = (uint32_t*)(dynsmem + 2 * BSMC);      // [2][WCH3]

    int b   = blockIdx.z;
    int ocT = blockIdx.y;
    int y   = blockIdx.x;
    int tid = threadIdx.x;
    int warp = tid >> 5, lane = tid & 31;
    int og = warp >> 2, pg = warp & 3;
    int g = lane >> 2, t = lane & 3;

    // zero halo columns (3 and 260), both buffers, all (ic, r)
    if (tid < 192) {
        int s = tid;
        int side = s & 1; s >>= 1;
        int rr = s % 3; s /= 3;
        int ic = s % 16; s /= 16;
        int bufi = s;
        bsm[bufi * BSMC + (ic * 3 + rr) * BROWC + (side ? 260 : 3)] = 0.f;
    }

    float acc[3][8][4];
#pragma unroll
    for (int mb = 0; mb < 3; mb++)
#pragma unroll
        for (int j = 0; j < 8; j++)
#pragma unroll
            for (int v = 0; v < 4; v++) acc[mb][j][v] = 0.f;

    const uint32_t* wp_base = g_Wp3 + (size_t)ocT * NCH3 * WCH3;

    auto issue = [&](int ch, int buf) {
        const float* ibase = in + ((size_t)b * C3 + ch * 16) * HW;
        float* bdst = bsm + buf * BSMC;
#pragma unroll
        for (int k = 0; k < 12; k++) {
            int idx = tid + k * 256;              // 0..3071 float4 slots
            int icr = idx >> 6, c4 = idx & 63;
            int ic = icr / 3, rr = icr - 3 * ic;
            int gy = y + rr - 1;
            bool ok = (unsigned)gy < 256u;
            const float* src = ibase + ((size_t)ic * IMG + (ok ? gy : 0)) * IMG + c4 * 4;
            cpa16z((uint32_t)__cvta_generic_to_shared(
                       bdst + (ic * 3 + rr) * BROWC + 4 + c4 * 4), src, ok);
        }
        const uint32_t* wsrc = wp_base + (size_t)ch * WCH3;
        uint32_t* wdst = wsm + buf * WCH3;
#pragma unroll
        for (int k = 0; k < 7; k++) {
            int i = tid + k * 256;
            if (i < WCH3 / 4)
                cpa16((uint32_t)__cvta_generic_to_shared(wdst + i * 4), wsrc + i * 4);
        }
        asm volatile("cp.async.commit_group;");
    };

    issue(0, 0);

    for (int s = 0; s < NCH3; s++) {
        if (s + 1 < NCH3) {
            issue(s + 1, (s + 1) & 1);
            asm volatile("cp.async.wait_group 1;");
        } else {
            asm volatile("cp.async.wait_group 0;");
        }
        __syncthreads();

        int buf = s & 1;
        const float* bB = bsm + buf * BSMC;
        const uint32_t* wc = wsm + buf * WCH3;
        int colb = 3 + pg * 64 + g;
#pragma unroll
        for (int ky = 0; ky < 3; ky++) {
#pragma unroll
            for (int kx = 0; kx < 3; kx++) {
                const uint32_t* wbp = wc + (((ky * 2 + og) * 3 + kx) * 3) * 128;
                uint32_t a[3][4];
#pragma unroll
                for (int mb = 0; mb < 3; mb++)
                    *(uint4*)a[mb] = *(const uint4*)&wbp[mb * 128 + lane * 4];
#pragma unroll
                for (int j = 0; j < 8; j++) {
                    int col = colb + 8 * j + kx;
                    float x0 = bB[((2 * t) * 3 + ky) * BROWC + col];
                    float x1 = bB[((2 * t + 1) * 3 + ky) * BROWC + col];
                    float x2 = bB[((2 * t + 8) * 3 + ky) * BROWC + col];
                    float x3 = bB[((2 * t + 9) * 3 + ky) * BROWC + col];
                    uint32_t b0 = packbf(x0, x1), b1 = packbf(x2, x3);
#pragma unroll
                    for (int mb = 0; mb < 3; mb++)
                        mma_bf16(acc[mb][j], a[mb], b0, b1);
                }
            }
        }
        __syncthreads();
    }

    // epilogue: c0,c1 -> (row g, cols 2t, 2t+1); c2,c3 -> row g+8
#pragma unroll
    for (int mb = 0; mb < 3; mb++) {
        int oc = ocT * 96 + og * 48 + mb * 16 + g;
#pragma unroll
        for (int j = 0; j < 8; j++) {
            int px = pg * 64 + 8 * j + 2 * t;
            float2 v01 = make_float2(acc[mb][j][0], acc[mb][j][1]);
            float2 v23 = make_float2(acc[mb][j][2], acc[mb][j][3]);
            *(float2*)&out[(((size_t)b * C3 + oc) * IMG + y) * IMG + px] = v01;
            *(float2*)&out[(((size_t)b * C3 + oc + 8) * IMG + y) * IMG + px] = v23;
        }
    }
}

// ---------------------------------------------------------------------------
// Sum of squares per (b, channel) over HW for q and k (float4)
// ---------------------------------------------------------------------------
__global__ __launch_bounds__(256) void sumsq_kernel(const float* __restrict__ qkv2,
                                                    float* __restrict__ sqk) {
    int c = blockIdx.x;
    int b = blockIdx.y;
    int tid = threadIdx.x;
    const float4* p = (const float4*)(qkv2 + ((size_t)b * C3 + c) * HW);
    float s = 0.f;
    for (int i = tid; i < HW / 4; i += 256) {
        float4 v = p[i];
        s += v.x * v.x + v.y * v.y + v.z * v.z + v.w * v.w;
    }
#pragma unroll
    for (int o = 16; o > 0; o >>= 1) s += __shfl_down_sync(0xffffffffu, s, o);
    __shared__ float red[8];
    if ((tid & 31) == 0) red[tid >> 5] = s;
    __syncthreads();
    if (tid == 0) {
        float tot = 0.f;
#pragma unroll
        for (int i = 0; i < 8; i++) tot += red[i];
        sqk[b * 2 * DIM + c] = tot;
    }
}

// ---------------------------------------------------------------------------
// Channel-gram via TF32 warp MMA over K = pixels (correct [c][d] orientation).
// ---------------------------------------------------------------------------
__global__ __launch_bounds__(256) void attn_mma_kernel(const float* __restrict__ qkv2,
                                                       float* __restrict__ attn_raw) {
    int bh = blockIdx.y;
    int b = bh / HEADS, h = bh - b * HEADS;
    int warp = threadIdx.x >> 5, lane = threadIdx.x & 31;
    int tg = lane >> 2, tig = lane & 3;

    const float* qb = qkv2 + ((size_t)b * C3 + h * HDIM) * HW;
    const float* kb = qkv2 + ((size_t)b * C3 + DIM + h * HDIM) * HW;
    const float* qr0 = qb + (size_t)tg * HW;
    const float* qr1 = qb + (size_t)(tg + 8) * HW;
    const float* kr0 = kb + (size_t)tg * HW;
    const float* kr1 = kb + (size_t)(tg + 8) * HW;

    float c0[4] = {0.f, 0.f, 0.f, 0.f};
    float c1[4] = {0.f, 0.f, 0.f, 0.f};

    int slab0 = (blockIdx.x * 8 + warp) * 64;
    for (int s = 0; s < 64; s++) {
        int n0 = (slab0 + s) * 32 + tig * 8;
        float qv[4][4], kv[4][4];
        *(float4*)qv[0] = *(const float4*)(qr0 + n0);
        *(float4*)qv[1] = *(const float4*)(qr1 + n0);
        *(float4*)qv[2] = *(const float4*)(qr0 + n0 + 4);
        *(float4*)qv[3] = *(const float4*)(qr1 + n0 + 4);
        *(float4*)kv[0] = *(const float4*)(kr0 + n0);
        *(float4*)kv[1] = *(const float4*)(kr0 + n0 + 4);
        *(float4*)kv[2] = *(const float4*)(kr1 + n0);
        *(float4*)kv[3] = *(const float4*)(kr1 + n0 + 4);
#pragma unroll
        for (int m = 0; m < 4; m++) {
            uint32_t a[4] = { __float_as_uint(qv[0][m]), __float_as_uint(qv[1][m]),
                              __float_as_uint(qv[2][m]), __float_as_uint(qv[3][m]) };
            uint32_t b0[2] = { __float_as_uint(kv[0][m]), __float_as_uint(kv[1][m]) };
            uint32_t b1[2] = { __float_as_uint(kv[2][m]), __float_as_uint(kv[3][m]) };
            mma_tf32(c0, a, b0);
            mma_tf32(c1, a, b1);
        }
    }

    float* dst = attn_raw + bh * 256;
    atomicAdd(dst + tg * 16 + 2 * tig,           c0[0]);
    atomicAdd(dst + tg * 16 + 2 * tig + 1,       c0[1]);
    atomicAdd(dst + (tg + 8) * 16 + 2 * tig,     c0[2]);
    atomicAdd(dst + (tg + 8) * 16 + 2 * tig + 1, c0[3]);
    atomicAdd(dst + tg * 16 + 8 + 2 * tig,           c1[0]);
    atomicAdd(dst + tg * 16 + 8 + 2 * tig + 1,       c1[1]);
    atomicAdd(dst + (tg + 8) * 16 + 8 + 2 * tig,     c1[2]);
    atomicAdd(dst + (tg + 8) * 16 + 8 + 2 * tig + 1, c1[3]);
}

// ---------------------------------------------------------------------------
// softmax + build fused per-batch 96x96 matrix M = proj @ blockdiag(attn),
// written directly in packed bf16 fragment-native layout.
// ---------------------------------------------------------------------------
__global__ __launch_bounds__(256) void softmax_build_M(const float* __restrict__ attn_raw,
                                                       const float* __restrict__ sqk,
                                                       const float* __restrict__ scale,
                                                       const float* __restrict__ proj_w,
                                                       uint32_t* __restrict__ Mp) {
    int b = blockIdx.x;
    int tdx = threadIdx.x;
    __shared__ float A[HEADS * 256];
    __shared__ float nq[DIM], nk[DIM];
    if (tdx < DIM) {
        nq[tdx] = fmaxf(sqrtf(sqk[b * 2 * DIM + tdx]), 1e-12f);
        nk[tdx] = fmaxf(sqrtf(sqk[b * 2 * DIM + DIM + tdx]), 1e-12f);
    }
    __syncthreads();
    for (int idx = tdx; idx < HEADS * 256; idx += 256) {
        int h = idx >> 8;
        int cd = idx & 255;
        int c = cd >> 4, d = cd & 15;
        A[idx] = attn_raw[b * HEADS * 256 + idx] /
                 (nq[h * HDIM + c] * nk[h * HDIM + d]) * scale[h];
    }
    __syncthreads();
    if (tdx < DIM) {
        int h = tdx >> 4, c = tdx & 15;
        float* row = &A[h * 256 + c * 16];
        float mx = row[0];
#pragma unroll
        for (int d = 1; d < 16; d++) mx = fmaxf(mx, row[d]);
        float sum = 0.f;
#pragma unroll
        for (int d = 0; d < 16; d++) { float e = expf(row[d] - mx); row[d] = e; sum += e; }
        float inv = 1.f / sum;
#pragma unroll
        for (int d = 0; d < 16; d++) row[d] *= inv;
    }
    __syncthreads();
    // packed write: u32 idx = (((ch*2+og)*3+mb)*32+lane)*4+v  (ocT = 0, NCH = 6)
    for (int idx = tdx; idx < DIM * DIM / 2; idx += 256) {
        int r = idx;
        int v = r & 3; r >>= 2;
        int lane = r & 31; r >>= 5;
        int mb = r % 3; r /= 3;
        int og = r % 2; r /= 2;
        int ch = r;
        int g = lane >> 2, t = lane & 3;
        int oc = og * 48 + mb * 16 + g + (v & 1) * 8;
        int ic = ch * 16 + 2 * t + (v >> 1) * 8;     // ic even -> ic, ic+1 same head
        int h = ic >> 4, d = ic & 15;
        float s0 = 0.f, s1 = 0.f;
#pragma unroll
        for (int cg = 0; cg < 16; cg++) {
            float pw = proj_w[oc * DIM + h * HDIM + cg];
            s0 += pw * A[h * 256 + cg * 16 + d];
            s1 += pw * A[h * 256 + cg * 16 + d + 1];
        }
        __nv_bfloat162 p = __floats2bfloat162_rn(s0, s1);
        Mp[b * (DIM * DIM / 2) + idx] = *reinterpret_cast<uint32_t*>(&p);
    }
}

// ---------------------------------------------------------------------------
// Grouped 3x3 conv (192 groups, 2 ch/group) fused with GELU gate.
// ---------------------------------------------------------------------------
__device__ __forceinline__ float gelu_tanh(float x) {
    float x3 = x * x * x;
    return 0.5f * x * (1.f + tanhf(0.7978845608028654f * (x + 0.044715f * x3)));
}

__global__ __launch_bounds__(128) void dwgate_kernel(const float* __restrict__ tin,
                                                     const float* __restrict__ dw,
                                                     float* __restrict__ g) {
    int b = blockIdx.z;
    int m = blockIdx.y;
    int y = blockIdx.x >> 1;
    int px0 = (blockIdx.x & 1) * 128;
    int tid = threadIdx.x;

    __shared__ float sin_s[4][3][132];
    __shared__ float swt[72];

    int chans[4] = {2 * m, 2 * m + 1, HID + 2 * m, HID + 2 * m + 1};

    for (int idx = tid; idx < 4 * 3 * 130; idx += 128) {
        int ch = idx / 390;
        int rem = idx - ch * 390;
        int r = rem / 130;
        int l = rem - r * 130;
        int gy = y + r - 1, gx = px0 - 1 + l;
        float v = 0.f;
        if ((unsigned)gy < 256u && (unsigned)gx < 256u)
            v = tin[(((size_t)b * HID2 + chans[ch]) * IMG + gy) * IMG + gx];
        sin_s[ch][r][l] = v;
    }
    if (tid < 72) {
        int oci = tid / 18;
        int rem = tid - oci * 18;
        swt[tid] = dw[(size_t)chans[oci] * 18 + rem];
    }
    __syncthreads();

    float u[4] = {0.f, 0.f, 0.f, 0.f};
#pragma unroll
    for (int ol = 0; ol < 4; ol++) {
        int i0 = (ol < 2) ? 0 : 2;
#pragma unroll
        for (int i = 0; i < 2; i++)
#pragma unroll
            for (int ky = 0; ky < 3; ky++)
#pragma unroll
                for (int kx = 0; kx < 3; kx++)
                    u[ol] += swt[ol * 18 + i * 9 + ky * 3 + kx] * sin_s[i0 + i][ky][tid + kx];
    }
    float r0 = gelu_tanh(u[0]) * u[2];
    float r1 = gelu_tanh(u[1]) * u[3];
    size_t o0 = (((size_t)b * HID + 2 * m) * IMG + y) * IMG + px0 + tid;
    g[o0] = r0;
    g[o0 + HW] = r1;
}

// ---------------------------------------------------------------------------
// Launch
// ---------------------------------------------------------------------------
static void* sym_addr(const void* sym) {
    void* p = nullptr;
    cudaGetSymbolAddress(&p, sym);
    return p;
}

extern "C" void kernel_launch(void* const* d_in, const int* in_sizes, int n_in,
                              void* d_out, int out_size) {
    const float* x      = (const float*)d_in[0];
    const float* ln1_w  = (const float*)d_in[1];
    const float* ln1_b  = (const float*)d_in[2];
    const float* qkv1_w = (const float*)d_in[3];
    const float* qkv2_w = (const float*)d_in[4];
    const float* proj_w = (const float*)d_in[5];
    const float* scale  = (const float*)d_in[6];
    const float* ln2_w  = (const float*)d_in[7];
    const float* ln2_b  = (const float*)d_in[8];
    const float* pin_w  = (const float*)d_in[9];
    const float* dw_w   = (const float*)d_in[10];
    const float* pout_w = (const float*)d_in[11];

    float* qkv   = (float*)sym_addr(g_qkv);
    float* qkv2  = (float*)sym_addr(g_qkv2);
    float* tbuf  = (float*)sym_addr(g_t);
    float* gbuf  = (float*)sym_addr(g_g);
    float* x2    = (float*)sym_addr(g_x2);
    float* mu    = (float*)sym_addr(g_mu);
    float* rstd  = (float*)sym_addr(g_rstd);
    float* wgs1  = (float*)sym_addr(g_wgs1);
    float* wb1   = (float*)sym_addr(g_wb1);
    float* wgs2  = (float*)sym_addr(g_wgs2);
    float* wb2   = (float*)sym_addr(g_wb2);
    float* sqk   = (float*)sym_addr(g_sqk);
    float* attn  = (float*)sym_addr(g_attn);
    uint32_t* Wp1 = (uint32_t*)sym_addr(g_Wp1);
    uint32_t* Wp2 = (uint32_t*)sym_addr(g_Wp2);
    uint32_t* Wpo = (uint32_t*)sym_addr(g_Wpo);
    uint32_t* Mp  = (uint32_t*)sym_addr(g_Mp);
    float* out   = (float*)d_out;

    static bool attr_done = false;
    if (!attr_done) {
        cudaFuncSetAttribute(conv3x3_bmma_kernel,
                             cudaFuncAttributeMaxDynamicSharedMemorySize, SMEM3);
        attr_done = true;
    }

    // weight prep (LN row sums + bf16 fragment packs) + zero attn accumulator
    prep_kernel<<<3, 256>>>(qkv1_w, ln1_w, ln1_b, pin_w, ln2_w, ln2_b);
    pack1x1_kernel<true><<<(C3 * DIM / 2 + 255) / 256, 256>>>(qkv1_w, ln1_w, Wp1, C3, DIM);
    pack1x1_kernel<true><<<(HID2 * DIM / 2 + 255) / 256, 256>>>(pin_w, ln2_w, Wp2, HID2, DIM);
    pack1x1_kernel<false><<<(DIM * HID / 2 + 255) / 256, 256>>>(pout_w, nullptr, Wpo, DIM, HID);
    pack3x3_kernel<<<(WP3SZ + 255) / 256, 256>>>(qkv2_w);
    zero_kernel<<<24, 256>>>(attn, BATCH * HEADS * 256);

    // LN1 stats, then LN-fused qkv1 (96 -> 288)
    ln_stats_kernel<<<(BATCH * HW) / 256, 256>>>(x, mu, rstd);
    conv1x1_bmma_kernel<DIM, true, false><<<dim3(256, 3, BATCH), 256>>>(
        x, DIM * HW, 0, Wp1, 0, wgs1, wb1, mu, rstd, nullptr, qkv);

    // qkv2: 3x3 conv 288 -> 288 via bf16 tensor cores
    conv3x3_bmma_kernel<<<dim3(256, 3, BATCH), 256, SMEM3>>>(qkv, qkv2);

    // attention statistics
    sumsq_kernel<<<dim3(2 * DIM, BATCH), 256>>>(qkv2, sqk);
    attn_mma_kernel<<<dim3(4, BATCH * HEADS), 256>>>(qkv2, attn);
    softmax_build_M<<<BATCH, 256>>>(attn, sqk, scale, proj_w, Mp);

    // fused (attn@v -> proj -> +x): per-batch 96x96 matrix over v channels
    conv1x1_bmma_kernel<DIM, false, true><<<dim3(256, 1, BATCH), 256>>>(
        qkv2, C3 * HW, 2 * DIM, Mp, DIM * DIM / 2, nullptr, nullptr, nullptr, nullptr, x, x2);

    // LN2 stats, LN-fused pin (96 -> 384)
    ln_stats_kernel<<<(BATCH * HW) / 256, 256>>>(x2, mu, rstd);
    conv1x1_bmma_kernel<DIM, true, false><<<dim3(256, 4, BATCH), 256>>>(
        x2, DIM * HW, 0, Wp2, 0, wgs2, wb2, mu, rstd, nullptr, tbuf);

    // grouped 3x3 conv + GELU gate (384 -> 192)
    dwgate_kernel<<<dim3(512, DIM, BATCH), 128>>>(tbuf, dw_w, gbuf);

    // pout (192 -> 96) + residual -> output
    conv1x1_bmma_kernel<HID, false, true><<<dim3(256, 1, BATCH), 256>>>(
        gbuf, HID * HW, 0, Wpo, 0, nullptr, nullptr, nullptr, nullptr, x2, out);
}

// round 7
// speedup vs baseline: 6.7571x; 1.1293x over previous
#include <cuda_runtime.h>
#include <cuda_bf16.h>
#include <cmath>
#include <cstdint>

// ---------------------------------------------------------------------------
// Problem constants
// ---------------------------------------------------------------------------
#define BATCH 4
#define DIM   96
#define HEADS 6
#define HDIM  16           // channels per head
#define C3    288          // 3*DIM
#define HID   192
#define HID2  384          // 2*HID
#define HW    65536        // 256*256
#define IMG   256

// conv3x3 bf16 mma tiling: chunk = 16 ic (= 8 u32 pair-words)
#define NCH3   18                      // 288/16
#define BROW3  280                     // smem row stride (u32); 3*280 % 32 == 8
#define BSM3   (8 * 3 * BROW3)         // u32 per input buffer (6720)
#define WCH3   6912                    // u32 per weight chunk: 96oc*16ic*9taps / 2
#define WP3SZ  (3 * NCH3 * WCH3)       // 373248 u32
#define SMEM3  ((2 * BSM3 + 2 * WCH3) * 4)   // 109056 bytes

// conv1x1 bf16 mma
#define BR1    268

// ---------------------------------------------------------------------------
// Scratch (device globals; no allocation allowed)
// ---------------------------------------------------------------------------
__device__ __align__(16) uint32_t g_qkvh [(size_t)BATCH * (C3 / 2) * HW]; // qkv bf16 pair-words
__device__ float g_qkv2 [(size_t)BATCH * C3  * HW];   // after qkv2 (3x3), fp32
__device__ __align__(16) uint32_t g_t [(size_t)BATCH * HID2 * HW / 2];   // tbuf bf16 (px pairs)
__device__ float g_g    [(size_t)BATCH * HID * HW];   // after dwconv+gate
__device__ float g_x2   [(size_t)BATCH * DIM * HW];   // residual after attention
__device__ float g_mu   [BATCH * HW];
__device__ float g_rstd [BATCH * HW];
__device__ float g_wgs1 [C3];
__device__ float g_wb1  [C3];
__device__ float g_wgs2 [HID2];
__device__ float g_wb2  [HID2];
__device__ float g_sqk  [BATCH * 2 * DIM];
__device__ float g_attn [BATCH * HEADS * HDIM * HDIM];
__device__ __align__(16) uint32_t g_Wp1 [C3 * DIM / 2];          // packed bf16 qkv1 (LN-folded)
__device__ __align__(16) uint32_t g_Wp2 [HID2 * DIM / 2];        // packed bf16 pin (LN-folded)
__device__ __align__(16) uint32_t g_Wpo [DIM * HID / 2];         // packed bf16 pout
__device__ __align__(16) uint32_t g_Mp  [BATCH * DIM * DIM / 2]; // packed bf16 fused attn matrix
__device__ __align__(16) uint32_t g_Wp3 [WP3SZ];                 // packed bf16 conv3x3 weights

// ---------------------------------------------------------------------------
// helpers
// ---------------------------------------------------------------------------
__device__ __forceinline__ void cpa16(uint32_t dst, const void* src) {
    asm volatile("cp.async.cg.shared.global [%0], [%1], 16;"
                 :: "r"(dst), "l"(src));
}
__device__ __forceinline__ void cpa16z(uint32_t dst, const void* src, bool v) {
    asm volatile("cp.async.cg.shared.global [%0], [%1], 16, %2;"
                 :: "r"(dst), "l"(src), "r"(v ? 16u : 0u));
}

// pack two fp32 -> bf16x2 (lo = first arg in low half)
__device__ __forceinline__ uint32_t packbf(float lo, float hi) {
    uint32_t r;
    asm("cvt.rn.bf16x2.f32 %0, %1, %2;" : "=r"(r) : "f"(hi), "f"(lo));
    return r;
}

__device__ __forceinline__ void mma_bf16(float* c, const uint32_t* a,
                                         uint32_t b0, uint32_t b1) {
    asm volatile("mma.sync.aligned.m16n8k16.row.col.f32.bf16.bf16.f32 "
                 "{%0,%1,%2,%3}, {%4,%5,%6,%7}, {%8,%9}, {%0,%1,%2,%3};"
                 : "+f"(c[0]), "+f"(c[1]), "+f"(c[2]), "+f"(c[3])
                 : "r"(a[0]), "r"(a[1]), "r"(a[2]), "r"(a[3]),
                   "r"(b0), "r"(b1));
}

__device__ __forceinline__ void mma_tf32(float* c, const uint32_t* a, const uint32_t* b) {
    asm volatile("mma.sync.aligned.m16n8k8.row.col.f32.tf32.tf32.f32 "
                 "{%0,%1,%2,%3}, {%4,%5,%6,%7}, {%8,%9}, {%0,%1,%2,%3};"
                 : "+f"(c[0]), "+f"(c[1]), "+f"(c[2]), "+f"(c[3])
                 : "r"(a[0]), "r"(a[1]), "r"(a[2]), "r"(a[3]),
                   "r"(b[0]), "r"(b[1]));
}

// ---------------------------------------------------------------------------
// prep: LN row sums for folded 1x1 convs
// ---------------------------------------------------------------------------
__global__ void prep_kernel(const float* __restrict__ qkv1_w,
                            const float* __restrict__ ln1_w,
                            const float* __restrict__ ln1_b,
                            const float* __restrict__ pin_w,
                            const float* __restrict__ ln2_w,
                            const float* __restrict__ ln2_b) {
    int t = blockIdx.x * 256 + threadIdx.x;
    if (t < C3) {
        float s = 0.f, sb = 0.f;
        for (int c = 0; c < DIM; c++) {
            float w = qkv1_w[t * DIM + c];
            s += w * ln1_w[c]; sb += w * ln1_b[c];
        }
        g_wgs1[t] = s; g_wb1[t] = sb;
    } else if (t < C3 + HID2) {
        int r = t - C3;
        float s = 0.f, sb = 0.f;
        for (int c = 0; c < DIM; c++) {
            float w = pin_w[r * DIM + c];
            s += w * ln2_w[c]; sb += w * ln2_b[c];
        }
        g_wgs2[r] = s; g_wb2[r] = sb;
    }
}

// pack a 1x1 weight matrix [OC][ICt] into bf16 fragment-native u32 layout.
// k mapping: k=2j <-> ic=j, k=2j+1 <-> ic=j+8 (j = 0..7) within each 16-chunk.
// NOTE: 1x1 conv inputs are fp32 packed in-register with pairing (2t,2t+1),
// so 1x1 weights keep the ORIGINAL (consecutive) pairing.
template <bool FOLD>
__global__ void pack1x1_kernel(const float* __restrict__ W,
                               const float* __restrict__ gamma,
                               uint32_t* __restrict__ dst, int OC, int ICt) {
    int idx = blockIdx.x * 256 + threadIdx.x;
    if (idx >= OC * ICt / 2) return;
    int r = idx;
    int v = r & 3; r >>= 2;
    int lane = r & 31; r >>= 5;
    int mb = r % 3; r /= 3;
    int og = r % 2; r /= 2;
    int nch = ICt / 16;
    int ch = r % nch; r /= nch;
    int ocT = r;
    int g = lane >> 2, t = lane & 3;
    int oc = ocT * 96 + og * 48 + mb * 16 + g + (v & 1) * 8;
    int ic = ch * 16 + 2 * t + (v >> 1) * 8;       // consecutive pairing
    float w0 = W[oc * ICt + ic], w1 = W[oc * ICt + ic + 1];
    if (FOLD) { w0 *= gamma[ic]; w1 *= gamma[ic + 1]; }
    dst[idx] = packbf(w0, w1);
}

// pack conv3x3 weights, layout [ocT][ch][ky][og][kx][mb][lane][v],
// with PAIR-INTERLEAVED k mapping: bf16x2 word = (ic0, ic0+8)
__global__ void pack3x3_kernel(const float* __restrict__ W) {
    int idx = blockIdx.x * 256 + threadIdx.x;
    if (idx >= WP3SZ) return;
    int r = idx;
    int v = r & 3; r >>= 2;
    int lane = r & 31; r >>= 5;
    int mb = r % 3; r /= 3;
    int kx = r % 3; r /= 3;
    int og = r % 2; r /= 2;
    int ky = r % 3; r /= 3;
    int ch = r % NCH3; r /= NCH3;
    int ocT = r;
    int g = lane >> 2, t = lane & 3;
    int oc = ocT * 96 + og * 48 + mb * 16 + g + (v & 1) * 8;
    int ic0 = ch * 16 + t + (v >> 1) * 4;          // pair (ic0, ic0+8)
    float w0 = W[(oc * C3 + ic0) * 9 + ky * 3 + kx];
    float w1 = W[(oc * C3 + ic0 + 8) * 9 + ky * 3 + kx];
    g_Wp3[idx] = packbf(w0, w1);
}

__global__ void zero_kernel(float* __restrict__ p, int n) {
    int i = blockIdx.x * 256 + threadIdx.x;
    if (i < n) p[i] = 0.f;
}

// ---------------------------------------------------------------------------
// Per-pixel LayerNorm stats over 96 channels
// ---------------------------------------------------------------------------
__global__ __launch_bounds__(256) void ln_stats_kernel(const float* __restrict__ x,
                                                       float* __restrict__ mu,
                                                       float* __restrict__ rstd) {
    int idx = blockIdx.x * 256 + threadIdx.x;
    int b = idx >> 16;
    int p = idx & (HW - 1);
    const float* xp = x + (size_t)b * DIM * HW + p;
    float s = 0.f, s2 = 0.f;
#pragma unroll 8
    for (int c = 0; c < DIM; c++) {
        float v = xp[(size_t)c * HW];
        s += v; s2 += v * v;
    }
    float m = s * (1.f / DIM);
    float var = s2 * (1.f / DIM) - m * m;
    mu[idx] = m;
    rstd[idx] = rsqrtf(var + 1e-5f);
}

// ---------------------------------------------------------------------------
// 1x1 conv via bf16 m16n8k16 mma. Block: 96 oc x 256 px, 8 warps = 2og x 4pg.
// OMODE: 0 = fp32 out; 1 = bf16 channel-pair words (c, c+8) for conv3x3 input;
//        2 = bf16 pixel-pair words (px, px+1).
// ---------------------------------------------------------------------------
template <int IC, bool LN, bool RES, int OMODE>
__global__ __launch_bounds__(256) void conv1x1_bmma_kernel(
    const float* __restrict__ in, int in_bstride, int in_choff,
    const uint32_t* __restrict__ Wp, int w_bstride,
    const float* __restrict__ wgs, const float* __restrict__ wb,
    const float* __restrict__ mu, const float* __restrict__ rstd,
    const float* __restrict__ res,
    void* __restrict__ outv) {
    constexpr int NCH = IC / 16;
    __shared__ __align__(16) float bsm[2][16 * BR1];
    __shared__ __align__(16) uint32_t wsm[2][768];
    __shared__ float smu[256], srstd[256];

    int b = blockIdx.z;
    int ocT = blockIdx.y;
    int px0 = blockIdx.x * 256;
    int OCtot = gridDim.y * 96;
    int tid = threadIdx.x;
    int warp = tid >> 5, lane = tid & 31;
    int og = warp >> 2, pg = warp & 3;
    int g = lane >> 2, t = lane & 3;

    if (LN) {
        if (tid < 64)
            *(float4*)&smu[tid * 4] = *(const float4*)&mu[(size_t)b * HW + px0 + tid * 4];
        else if (tid < 128) {
            int q = tid - 64;
            *(float4*)&srstd[q * 4] = *(const float4*)&rstd[(size_t)b * HW + px0 + q * 4];
        }
    }

    float acc[3][8][4];
#pragma unroll
    for (int mb = 0; mb < 3; mb++)
#pragma unroll
        for (int j = 0; j < 8; j++)
#pragma unroll
            for (int v = 0; v < 4; v++) acc[mb][j][v] = 0.f;

    const uint32_t* Wb = Wp + (size_t)b * w_bstride + (size_t)ocT * NCH * 768;

    auto issue = [&](int ch, int buf) {
#pragma unroll
        for (int k = 0; k < 4; k++) {
            int idx = tid + k * 256;
            int ic = idx >> 6, c4 = idx & 63;
            const float* src = in + (size_t)b * in_bstride +
                               (size_t)(in_choff + ch * 16 + ic) * HW + px0 + c4 * 4;
            cpa16((uint32_t)__cvta_generic_to_shared(&bsm[buf][ic * BR1 + c4 * 4]), src);
        }
        if (tid < 192)
            cpa16((uint32_t)__cvta_generic_to_shared(&wsm[buf][tid * 4]),
                  Wb + ch * 768 + tid * 4);
        asm volatile("cp.async.commit_group;");
    };

    issue(0, 0);

    for (int s = 0; s < NCH; s++) {
        if (s + 1 < NCH) {
            issue(s + 1, (s + 1) & 1);
            asm volatile("cp.async.wait_group 1;");
        } else {
            asm volatile("cp.async.wait_group 0;");
        }
        __syncthreads();

        int buf = s & 1;
        const uint32_t* wc = &wsm[buf][og * 384];
        uint32_t a[3][4];
#pragma unroll
        for (int mb = 0; mb < 3; mb++)
            *(uint4*)a[mb] = *(const uint4*)&wc[mb * 128 + lane * 4];
        const float* bB = &bsm[buf][0];
#pragma unroll
        for (int j = 0; j < 8; j++) {
            int col = pg * 64 + 8 * j + g;
            float x0 = bB[(2 * t) * BR1 + col];
            float x1 = bB[(2 * t + 1) * BR1 + col];
            float x2 = bB[(2 * t + 8) * BR1 + col];
            float x3 = bB[(2 * t + 9) * BR1 + col];
            uint32_t b0 = packbf(x0, x1), b1 = packbf(x2, x3);
#pragma unroll
            for (int mb = 0; mb < 3; mb++)
                mma_bf16(acc[mb][j], a[mb], b0, b1);
        }
        __syncthreads();
    }

    // epilogue
#pragma unroll
    for (int mb = 0; mb < 3; mb++) {
        int oc = ocT * 96 + og * 48 + mb * 16 + g;
        float gs0 = 0.f, gs8 = 0.f, bb0 = 0.f, bb8 = 0.f;
        if (LN) {
            gs0 = wgs[oc]; gs8 = wgs[oc + 8];
            bb0 = wb[oc];  bb8 = wb[oc + 8];
        }
#pragma unroll
        for (int j = 0; j < 8; j++) {
            int pl = pg * 64 + 8 * j + 2 * t;
            int px = px0 + pl;
            float v00 = acc[mb][j][0], v01 = acc[mb][j][1];
            float v10 = acc[mb][j][2], v11 = acc[mb][j][3];
            if (LN) {
                float m0 = smu[pl], m1 = smu[pl + 1];
                float r0 = srstd[pl], r1 = srstd[pl + 1];
                v00 = r0 * (v00 - m0 * gs0) + bb0;
                v01 = r1 * (v01 - m1 * gs0) + bb0;
                v10 = r0 * (v10 - m0 * gs8) + bb8;
                v11 = r1 * (v11 - m1 * gs8) + bb8;
            }
            if (RES) {
                const float* rr = res;
                float2 ra = *(const float2*)&rr[((size_t)b * OCtot + oc) * HW + px];
                float2 rb = *(const float2*)&rr[((size_t)b * OCtot + oc + 8) * HW + px];
                v00 += ra.x; v01 += ra.y; v10 += rb.x; v11 += rb.y;
            }
            if (OMODE == 0) {
                float* out = (float*)outv;
                *(float2*)&out[((size_t)b * OCtot + oc) * HW + px] = make_float2(v00, v01);
                *(float2*)&out[((size_t)b * OCtot + oc + 8) * HW + px] = make_float2(v10, v11);
            } else if (OMODE == 1) {
                // channel-pair words (oc, oc+8)
                uint32_t* out = (uint32_t*)outv;
                int ch = ocT * 6 + og * 3 + mb;
                int c2 = ch * 8 + g;
                uint2 val = make_uint2(packbf(v00, v10), packbf(v01, v11));
                *(uint2*)&out[((size_t)b * (OCtot / 2) + c2) * HW + px] = val;
            } else {
                // pixel-pair words
                uint32_t* out = (uint32_t*)outv;
                out[(((size_t)b * OCtot + oc) * HW + px) >> 1] = packbf(v00, v01);
                out[(((size_t)b * OCtot + oc + 8) * HW + px) >> 1] = packbf(v10, v11);
            }
        }
    }
}

// ---------------------------------------------------------------------------
// 3x3 conv 288 -> 288 via bf16 m16n8k16 mma, input = bf16 channel-pair words.
// Block: 96 oc x 256 px (one image row). Stage = 16-ic chunk (8 words x 3 rows),
// double-buffered cp.async. Fused q/k sum-of-squares epilogue (atomics).
// ---------------------------------------------------------------------------
__global__ __launch_bounds__(256) void conv3x3_bmma_kernel(const uint32_t* __restrict__ in,
                                                           float* __restrict__ out,
                                                           float* __restrict__ sqk) {
    extern __shared__ uint32_t dynsmem[];
    uint32_t* bsm = dynsmem;                       // [2][8 words][3 rows][BROW3]
    uint32_t* wsm = dynsmem + 2 * BSM3;            // [2][WCH3]

    int b   = blockIdx.z;
    int ocT = blockIdx.y;
    int y   = blockIdx.x;
    int tid = threadIdx.x;
    int warp = tid >> 5, lane = tid & 31;
    int og = warp >> 2, pg = warp & 3;
    int g = lane >> 2, t = lane & 3;

    // zero halo cols (3 and 260) for all 24 (word,row) pairs, both buffers
    if (tid < 96) {
        int s = tid;
        int side = s & 1; s >>= 1;                 // 0..47
        int wr = s % 24; int bufi = s / 24;
        bsm[bufi * BSM3 + wr * BROW3 + (side ? 260 : 3)] = 0u;
    }

    float acc[3][8][4];
#pragma unroll
    for (int mb = 0; mb < 3; mb++)
#pragma unroll
        for (int j = 0; j < 8; j++)
#pragma unroll
            for (int v = 0; v < 4; v++) acc[mb][j][v] = 0.f;

    const uint32_t* wp_base = g_Wp3 + (size_t)ocT * NCH3 * WCH3;

    auto issue = [&](int ch, int buf) {
        const uint32_t* ibase = in + ((size_t)b * (C3 / 2) + ch * 8) * HW;
        uint32_t* bdst = bsm + buf * BSM3;
#pragma unroll
        for (int k = 0; k < 6; k++) {
            int idx = tid + k * 256;               // 0..1535
            int wr = idx >> 6, c4 = idx & 63;
            int w = wr / 3, rr = wr - 3 * w;
            int gy = y + rr - 1;
            bool ok = (unsigned)gy < 256u;
            const uint32_t* src = ibase + (size_t)w * HW + (ok ? gy : 0) * IMG + c4 * 4;
            cpa16z((uint32_t)__cvta_generic_to_shared(
                       bdst + wr * BROW3 + 4 + c4 * 4), src, ok);
        }
        const uint32_t* wsrc = wp_base + (size_t)ch * WCH3;
        uint32_t* wdst = wsm + buf * WCH3;
#pragma unroll
        for (int k = 0; k < 7; k++) {
            int i = tid + k * 256;
            if (i < WCH3 / 4)
                cpa16((uint32_t)__cvta_generic_to_shared(wdst + i * 4), wsrc + i * 4);
        }
        asm volatile("cp.async.commit_group;");
    };

    issue(0, 0);

    for (int s = 0; s < NCH3; s++) {
        if (s + 1 < NCH3) {
            issue(s + 1, (s + 1) & 1);
            asm volatile("cp.async.wait_group 1;");
        } else {
            asm volatile("cp.async.wait_group 0;");
        }
        __syncthreads();

        int buf = s & 1;
        const uint32_t* bB = bsm + buf * BSM3;
        const uint32_t* wc = wsm + buf * WCH3;
        int colb = 3 + pg * 64 + g;
#pragma unroll
        for (int ky = 0; ky < 3; ky++) {
#pragma unroll
            for (int kx = 0; kx < 3; kx++) {
                const uint32_t* wbp = wc + (((ky * 2 + og) * 3 + kx) * 3) * 128;
                uint32_t a[3][4];
#pragma unroll
                for (int mb = 0; mb < 3; mb++)
                    *(uint4*)a[mb] = *(const uint4*)&wbp[mb * 128 + lane * 4];
#pragma unroll
                for (int j = 0; j < 8; j++) {
                    int col = colb + 8 * j + kx;
                    uint32_t b0 = bB[(t * 3 + ky) * BROW3 + col];
                    uint32_t b1 = bB[((t + 4) * 3 + ky) * BROW3 + col];
#pragma unroll
                    for (int mb = 0; mb < 3; mb++)
                        mma_bf16(acc[mb][j], a[mb], b0, b1);
                }
            }
        }
        __syncthreads();
    }

    // fused q/k sum-of-squares (channels 0..191 => ocT 0,1)
    if (ocT < 2) {
#pragma unroll
        for (int mb = 0; mb < 3; mb++) {
            float s0 = 0.f, s8 = 0.f;
#pragma unroll
            for (int j = 0; j < 8; j++) {
                s0 += acc[mb][j][0] * acc[mb][j][0] + acc[mb][j][1] * acc[mb][j][1];
                s8 += acc[mb][j][2] * acc[mb][j][2] + acc[mb][j][3] * acc[mb][j][3];
            }
            s0 += __shfl_xor_sync(0xffffffffu, s0, 1);
            s0 += __shfl_xor_sync(0xffffffffu, s0, 2);
            s8 += __shfl_xor_sync(0xffffffffu, s8, 1);
            s8 += __shfl_xor_sync(0xffffffffu, s8, 2);
            if (t == 0) {
                int oc = ocT * 96 + og * 48 + mb * 16 + g;
                atomicAdd(&sqk[b * 2 * DIM + oc], s0);
                atomicAdd(&sqk[b * 2 * DIM + oc + 8], s8);
            }
        }
    }

    // store
#pragma unroll
    for (int mb = 0; mb < 3; mb++) {
        int oc = ocT * 96 + og * 48 + mb * 16 + g;
#pragma unroll
        for (int j = 0; j < 8; j++) {
            int px = pg * 64 + 8 * j + 2 * t;
            float2 v01 = make_float2(acc[mb][j][0], acc[mb][j][1]);
            float2 v23 = make_float2(acc[mb][j][2], acc[mb][j][3]);
            *(float2*)&out[(((size_t)b * C3 + oc) * IMG + y) * IMG + px] = v01;
            *(float2*)&out[(((size_t)b * C3 + oc + 8) * IMG + y) * IMG + px] = v23;
        }
    }
}

// ---------------------------------------------------------------------------
// Channel-gram via TF32 warp MMA over K = pixels (correct [c][d] orientation).
// ---------------------------------------------------------------------------
__global__ __launch_bounds__(256) void attn_mma_kernel(const float* __restrict__ qkv2,
                                                       float* __restrict__ attn_raw) {
    int bh = blockIdx.y;
    int b = bh / HEADS, h = bh - b * HEADS;
    int warp = threadIdx.x >> 5, lane = threadIdx.x & 31;
    int tg = lane >> 2, tig = lane & 3;

    const float* qb = qkv2 + ((size_t)b * C3 + h * HDIM) * HW;
    const float* kb = qkv2 + ((size_t)b * C3 + DIM + h * HDIM) * HW;
    const float* qr0 = qb + (size_t)tg * HW;
    const float* qr1 = qb + (size_t)(tg + 8) * HW;
    const float* kr0 = kb + (size_t)tg * HW;
    const float* kr1 = kb + (size_t)(tg + 8) * HW;

    float c0[4] = {0.f, 0.f, 0.f, 0.f};
    float c1[4] = {0.f, 0.f, 0.f, 0.f};

    int slab0 = (blockIdx.x * 8 + warp) * 64;
    for (int s = 0; s < 64; s++) {
        int n0 = (slab0 + s) * 32 + tig * 8;
        float qv[4][4], kv[4][4];
        *(float4*)qv[0] = *(const float4*)(qr0 + n0);
        *(float4*)qv[1] = *(const float4*)(qr1 + n0);
        *(float4*)qv[2] = *(const float4*)(qr0 + n0 + 4);
        *(float4*)qv[3] = *(const float4*)(qr1 + n0 + 4);
        *(float4*)kv[0] = *(const float4*)(kr0 + n0);
        *(float4*)kv[1] = *(const float4*)(kr0 + n0 + 4);
        *(float4*)kv[2] = *(const float4*)(kr1 + n0);
        *(float4*)kv[3] = *(const float4*)(kr1 + n0 + 4);
#pragma unroll
        for (int m = 0; m < 4; m++) {
            uint32_t a[4] = { __float_as_uint(qv[0][m]), __float_as_uint(qv[1][m]),
                              __float_as_uint(qv[2][m]), __float_as_uint(qv[3][m]) };
            uint32_t b0[2] = { __float_as_uint(kv[0][m]), __float_as_uint(kv[1][m]) };
            uint32_t b1[2] = { __float_as_uint(kv[2][m]), __float_as_uint(kv[3][m]) };
            mma_tf32(c0, a, b0);
            mma_tf32(c1, a, b1);
        }
    }

    float* dst = attn_raw + bh * 256;
    atomicAdd(dst + tg * 16 + 2 * tig,           c0[0]);
    atomicAdd(dst + tg * 16 + 2 * tig + 1,       c0[1]);
    atomicAdd(dst + (tg + 8) * 16 + 2 * tig,     c0[2]);
    atomicAdd(dst + (tg + 8) * 16 + 2 * tig + 1, c0[3]);
    atomicAdd(dst + tg * 16 + 8 + 2 * tig,           c1[0]);
    atomicAdd(dst + tg * 16 + 8 + 2 * tig + 1,       c1[1]);
    atomicAdd(dst + (tg + 8) * 16 + 8 + 2 * tig,     c1[2]);
    atomicAdd(dst + (tg + 8) * 16 + 8 + 2 * tig + 1, c1[3]);
}

// ---------------------------------------------------------------------------
// softmax + build fused per-batch 96x96 matrix M = proj @ blockdiag(attn),
// written directly in packed bf16 fragment-native layout (consecutive pairing).
// ---------------------------------------------------------------------------
__global__ __launch_bounds__(256) void softmax_build_M(const float* __restrict__ attn_raw,
                                                       const float* __restrict__ sqk,
                                                       const float* __restrict__ scale,
                                                       const float* __restrict__ proj_w,
                                                       uint32_t* __restrict__ Mp) {
    int b = blockIdx.x;
    int tdx = threadIdx.x;
    __shared__ float A[HEADS * 256];
    __shared__ float nq[DIM], nk[DIM];
    if (tdx < DIM) {
        nq[tdx] = fmaxf(sqrtf(sqk[b * 2 * DIM + tdx]), 1e-12f);
        nk[tdx] = fmaxf(sqrtf(sqk[b * 2 * DIM + DIM + tdx]), 1e-12f);
    }
    __syncthreads();
    for (int idx = tdx; idx < HEADS * 256; idx += 256) {
        int h = idx >> 8;
        int cd = idx & 255;
        int c = cd >> 4, d = cd & 15;
        A[idx] = attn_raw[b * HEADS * 256 + idx] /
                 (nq[h * HDIM + c] * nk[h * HDIM + d]) * scale[h];
    }
    __syncthreads();
    if (tdx < DIM) {
        int h = tdx >> 4, c = tdx & 15;
        float* row = &A[h * 256 + c * 16];
        float mx = row[0];
#pragma unroll
        for (int d = 1; d < 16; d++) mx = fmaxf(mx, row[d]);
        float sum = 0.f;
#pragma unroll
        for (int d = 0; d < 16; d++) { float e = expf(row[d] - mx); row[d] = e; sum += e; }
        float inv = 1.f / sum;
#pragma unroll
        for (int d = 0; d < 16; d++) row[d] *= inv;
    }
    __syncthreads();
    // packed write matching pack1x1 (consecutive k pairing), ocT=0, nch=6
    for (int idx = tdx; idx < DIM * DIM / 2; idx += 256) {
        int r = idx;
        int v = r & 3; r >>= 2;
        int lane = r & 31; r >>= 5;
        int mb = r % 3; r /= 3;
        int og = r % 2; r /= 2;
        int ch = r;
        int g = lane >> 2, t = lane & 3;
        int oc = og * 48 + mb * 16 + g + (v & 1) * 8;
        int ic = ch * 16 + 2 * t + (v >> 1) * 8;
        int h = ic >> 4, d = ic & 15;
        float s0 = 0.f, s1 = 0.f;
#pragma unroll
        for (int cg = 0; cg < 16; cg++) {
            float pw = proj_w[oc * DIM + h * HDIM + cg];
            s0 += pw * A[h * 256 + cg * 16 + d];
            s1 += pw * A[h * 256 + cg * 16 + d + 1];
        }
        Mp[b * (DIM * DIM / 2) + idx] = packbf(s0, s1);
    }
}

// ---------------------------------------------------------------------------
// Grouped 3x3 conv (192 groups, 2 ch/group) fused with GELU gate.
// Input tbuf is bf16.
// ---------------------------------------------------------------------------
__device__ __forceinline__ float gelu_tanh(float x) {
    float x3 = x * x * x;
    return 0.5f * x * (1.f + tanhf(0.7978845608028654f * (x + 0.044715f * x3)));
}

__global__ __launch_bounds__(128) void dwgate_kernel(const __nv_bfloat16* __restrict__ tin,
                                                     const float* __restrict__ dw,
                                                     float* __restrict__ g) {
    int b = blockIdx.z;
    int m = blockIdx.y;
    int y = blockIdx.x >> 1;
    int px0 = (blockIdx.x & 1) * 128;
    int tid = threadIdx.x;

    __shared__ float sin_s[4][3][132];
    __shared__ float swt[72];

    int chans[4] = {2 * m, 2 * m + 1, HID + 2 * m, HID + 2 * m + 1};

    for (int idx = tid; idx < 4 * 3 * 130; idx += 128) {
        int ch = idx / 390;
        int rem = idx - ch * 390;
        int r = rem / 130;
        int l = rem - r * 130;
        int gy = y + r - 1, gx = px0 - 1 + l;
        float v = 0.f;
        if ((unsigned)gy < 256u && (unsigned)gx < 256u)
            v = __bfloat162float(tin[(((size_t)b * HID2 + chans[ch]) * IMG + gy) * IMG + gx]);
        sin_s[ch][r][l] = v;
    }
    if (tid < 72) {
        int oci = tid / 18;
        int rem = tid - oci * 18;
        swt[tid] = dw[(size_t)chans[oci] * 18 + rem];
    }
    __syncthreads();

    float u[4] = {0.f, 0.f, 0.f, 0.f};
#pragma unroll
    for (int ol = 0; ol < 4; ol++) {
        int i0 = (ol < 2) ? 0 : 2;
#pragma unroll
        for (int i = 0; i < 2; i++)
#pragma unroll
            for (int ky = 0; ky < 3; ky++)
#pragma unroll
                for (int kx = 0; kx < 3; kx++)
                    u[ol] += swt[ol * 18 + i * 9 + ky * 3 + kx] * sin_s[i0 + i][ky][tid + kx];
    }
    float r0 = gelu_tanh(u[0]) * u[2];
    float r1 = gelu_tanh(u[1]) * u[3];
    size_t o0 = (((size_t)b * HID + 2 * m) * IMG + y) * IMG + px0 + tid;
    g[o0] = r0;
    g[o0 + HW] = r1;
}

// ---------------------------------------------------------------------------
// Launch
// ---------------------------------------------------------------------------
static void* sym_addr(const void* sym) {
    void* p = nullptr;
    cudaGetSymbolAddress(&p, sym);
    return p;
}

extern "C" void kernel_launch(void* const* d_in, const int* in_sizes, int n_in,
                              void* d_out, int out_size) {
    const float* x      = (const float*)d_in[0];
    const float* ln1_w  = (const float*)d_in[1];
    const float* ln1_b  = (const float*)d_in[2];
    const float* qkv1_w = (const float*)d_in[3];
    const float* qkv2_w = (const float*)d_in[4];
    const float* proj_w = (const float*)d_in[5];
    const float* scale  = (const float*)d_in[6];
    const float* ln2_w  = (const float*)d_in[7];
    const float* ln2_b  = (const float*)d_in[8];
    const float* pin_w  = (const float*)d_in[9];
    const float* dw_w   = (const float*)d_in[10];
    const float* pout_w = (const float*)d_in[11];

    uint32_t* qkvh = (uint32_t*)sym_addr(g_qkvh);
    float* qkv2  = (float*)sym_addr(g_qkv2);
    uint32_t* tbuf = (uint32_t*)sym_addr(g_t);
    float* gbuf  = (float*)sym_addr(g_g);
    float* x2    = (float*)sym_addr(g_x2);
    float* mu    = (float*)sym_addr(g_mu);
    float* rstd  = (float*)sym_addr(g_rstd);
    float* wgs1  = (float*)sym_addr(g_wgs1);
    float* wb1   = (float*)sym_addr(g_wb1);
    float* wgs2  = (float*)sym_addr(g_wgs2);
    float* wb2   = (float*)sym_addr(g_wb2);
    float* sqk   = (float*)sym_addr(g_sqk);
    float* attn  = (float*)sym_addr(g_attn);
    uint32_t* Wp1 = (uint32_t*)sym_addr(g_Wp1);
    uint32_t* Wp2 = (uint32_t*)sym_addr(g_Wp2);
    uint32_t* Wpo = (uint32_t*)sym_addr(g_Wpo);
    uint32_t* Mp  = (uint32_t*)sym_addr(g_Mp);
    float* out   = (float*)d_out;

    static bool attr_done = false;
    if (!attr_done) {
        cudaFuncSetAttribute(conv3x3_bmma_kernel,
                             cudaFuncAttributeMaxDynamicSharedMemorySize, SMEM3);
        attr_done = true;
    }

    // weight prep (LN row sums + bf16 fragment packs) + zero accumulators
    prep_kernel<<<3, 256>>>(qkv1_w, ln1_w, ln1_b, pin_w, ln2_w, ln2_b);
    pack1x1_kernel<true><<<(C3 * DIM / 2 + 255) / 256, 256>>>(qkv1_w, ln1_w, Wp1, C3, DIM);
    pack1x1_kernel<true><<<(HID2 * DIM / 2 + 255) / 256, 256>>>(pin_w, ln2_w, Wp2, HID2, DIM);
    pack1x1_kernel<false><<<(DIM * HID / 2 + 255) / 256, 256>>>(pout_w, nullptr, Wpo, DIM, HID);
    pack3x3_kernel<<<(WP3SZ + 255) / 256, 256>>>(qkv2_w);
    zero_kernel<<<24, 256>>>(attn, BATCH * HEADS * 256);
    zero_kernel<<<3, 256>>>(sqk, BATCH * 2 * DIM);

    // LN1 stats, then LN-fused qkv1 (96 -> 288) written as bf16 pair-words
    ln_stats_kernel<<<(BATCH * HW) / 256, 256>>>(x, mu, rstd);
    conv1x1_bmma_kernel<DIM, true, false, 1><<<dim3(256, 3, BATCH), 256>>>(
        x, DIM * HW, 0, Wp1, 0, wgs1, wb1, mu, rstd, nullptr, qkvh);

    // qkv2: 3x3 conv 288 -> 288 via bf16 tensor cores (+ fused q/k sumsq)
    conv3x3_bmma_kernel<<<dim3(256, 3, BATCH), 256, SMEM3>>>(qkvh, qkv2, sqk);

    // attention statistics
    attn_mma_kernel<<<dim3(4, BATCH * HEADS), 256>>>(qkv2, attn);
    softmax_build_M<<<BATCH, 256>>>(attn, sqk, scale, proj_w, Mp);

    // fused (attn@v -> proj -> +x): per-batch 96x96 matrix over v channels
    conv1x1_bmma_kernel<DIM, false, true, 0><<<dim3(256, 1, BATCH), 256>>>(
        qkv2, C3 * HW, 2 * DIM, Mp, DIM * DIM / 2, nullptr, nullptr, nullptr, nullptr, x, x2);

    // LN2 stats, LN-fused pin (96 -> 384) written as bf16 (pixel-pair words)
    ln_stats_kernel<<<(BATCH * HW) / 256, 256>>>(x2, mu, rstd);
    conv1x1_bmma_kernel<DIM, true, false, 2><<<dim3(256, 4, BATCH), 256>>>(
        x2, DIM * HW, 0, Wp2, 0, wgs2, wb2, mu, rstd, nullptr, tbuf);

    // grouped 3x3 conv + GELU gate (384 -> 192), bf16 input
    dwgate_kernel<<<dim3(512, DIM, BATCH), 128>>>((const __nv_bfloat16*)tbuf, dw_w, gbuf);

    // pout (192 -> 96) + residual -> output
    conv1x1_bmma_kernel<HID, false, true, 0><<<dim3(256, 1, BATCH), 256>>>(
        gbuf, HID * HW, 0, Wpo, 0, nullptr, nullptr, nullptr, nullptr, x2, out);
}

// round 8
// speedup vs baseline: 6.9015x; 1.0214x over previous
#include <cuda_runtime.h>
#include <cuda_bf16.h>
#include <cmath>
#include <cstdint>

// ---------------------------------------------------------------------------
// Problem constants
// ---------------------------------------------------------------------------
#define BATCH 4
#define DIM   96
#define HEADS 6
#define HDIM  16
#define C3    288
#define HID   192
#define HID2  384
#define HW    65536
#define IMG   256

// conv3x3 bf16 mma tiling: chunk = 16 ic (= 8 u32 pair-words)
#define NCH3   18
#define BROW3  280                     // 3*280 % 32 == 8 -> conflict-free
#define BSM3   (8 * 3 * BROW3)
#define WCH3   6912
#define WP3SZ  (3 * NCH3 * WCH3)
#define SMEM3  ((2 * BSM3 + 2 * WCH3) * 4)   // 109056 bytes

#define BR1    268                     // fp32-input conv1x1 smem stride
#define BRW    264                     // u32-input conv1x1 smem stride (264%32==8)

// ---------------------------------------------------------------------------
// Scratch (device globals)
// ---------------------------------------------------------------------------
__device__ __align__(16) uint32_t g_qkvh [(size_t)BATCH * (C3 / 2) * HW];  // qkv1 out, ch-pair
__device__ __align__(16) uint32_t g_qkpp [(size_t)BATCH * 192 * (HW / 2)]; // q,k px-pair bf16
__device__ __align__(16) uint32_t g_vcp  [(size_t)BATCH * 48 * HW];        // v ch-pair bf16
__device__ __align__(16) uint32_t g_t    [(size_t)BATCH * HID2 * HW / 2];  // pin out, px-pair
__device__ __align__(16) uint32_t g_gw   [(size_t)BATCH * 96 * HW];        // dwgate out, ch-pair
__device__ float g_x2   [(size_t)BATCH * DIM * HW];
__device__ float g_mu   [BATCH * HW];
__device__ float g_rstd [BATCH * HW];
__device__ float g_wgs1 [C3];
__device__ float g_wb1  [C3];
__device__ float g_wgs2 [HID2];
__device__ float g_wb2  [HID2];
__device__ float g_sqk  [BATCH * 2 * DIM];
__device__ float g_attn [BATCH * HEADS * HDIM * HDIM];
__device__ __align__(16) uint32_t g_Wp1 [C3 * DIM / 2];
__device__ __align__(16) uint32_t g_Wp2 [HID2 * DIM / 2];
__device__ __align__(16) uint32_t g_Wpo [DIM * HID / 2];
__device__ __align__(16) uint32_t g_Mp  [BATCH * DIM * DIM / 2];
__device__ __align__(16) uint32_t g_Wp3 [WP3SZ];

// ---------------------------------------------------------------------------
// helpers
// ---------------------------------------------------------------------------
__device__ __forceinline__ void cpa16(uint32_t dst, const void* src) {
    asm volatile("cp.async.cg.shared.global [%0], [%1], 16;"
                 :: "r"(dst), "l"(src));
}
__device__ __forceinline__ void cpa16z(uint32_t dst, const void* src, bool v) {
    asm volatile("cp.async.cg.shared.global [%0], [%1], 16, %2;"
                 :: "r"(dst), "l"(src), "r"(v ? 16u : 0u));
}

__device__ __forceinline__ uint32_t packbf(float lo, float hi) {
    uint32_t r;
    asm("cvt.rn.bf16x2.f32 %0, %1, %2;" : "=r"(r) : "f"(hi), "f"(lo));
    return r;
}

__device__ __forceinline__ void mma_bf16(float* c, const uint32_t* a,
                                         uint32_t b0, uint32_t b1) {
    asm volatile("mma.sync.aligned.m16n8k16.row.col.f32.bf16.bf16.f32 "
                 "{%0,%1,%2,%3}, {%4,%5,%6,%7}, {%8,%9}, {%0,%1,%2,%3};"
                 : "+f"(c[0]), "+f"(c[1]), "+f"(c[2]), "+f"(c[3])
                 : "r"(a[0]), "r"(a[1]), "r"(a[2]), "r"(a[3]),
                   "r"(b0), "r"(b1));
}

// ---------------------------------------------------------------------------
// prep: LN row sums for folded 1x1 convs
// ---------------------------------------------------------------------------
__global__ void prep_kernel(const float* __restrict__ qkv1_w,
                            const float* __restrict__ ln1_w,
                            const float* __restrict__ ln1_b,
                            const float* __restrict__ pin_w,
                            const float* __restrict__ ln2_w,
                            const float* __restrict__ ln2_b) {
    int t = blockIdx.x * 256 + threadIdx.x;
    if (t < C3) {
        float s = 0.f, sb = 0.f;
        for (int c = 0; c < DIM; c++) {
            float w = qkv1_w[t * DIM + c];
            s += w * ln1_w[c]; sb += w * ln1_b[c];
        }
        g_wgs1[t] = s; g_wb1[t] = sb;
    } else if (t < C3 + HID2) {
        int r = t - C3;
        float s = 0.f, sb = 0.f;
        for (int c = 0; c < DIM; c++) {
            float w = pin_w[r * DIM + c];
            s += w * ln2_w[c]; sb += w * ln2_b[c];
        }
        g_wgs2[r] = s; g_wb2[r] = sb;
    }
}

// pack a 1x1 weight matrix into bf16 fragment-native layout (consecutive pairing)
template <bool FOLD>
__global__ void pack1x1_kernel(const float* __restrict__ W,
                               const float* __restrict__ gamma,
                               uint32_t* __restrict__ dst, int OC, int ICt) {
    int idx = blockIdx.x * 256 + threadIdx.x;
    if (idx >= OC * ICt / 2) return;
    int r = idx;
    int v = r & 3; r >>= 2;
    int lane = r & 31; r >>= 5;
    int mb = r % 3; r /= 3;
    int og = r % 2; r /= 2;
    int nch = ICt / 16;
    int ch = r % nch; r /= nch;
    int ocT = r;
    int g = lane >> 2, t = lane & 3;
    int oc = ocT * 96 + og * 48 + mb * 16 + g + (v & 1) * 8;
    int ic = ch * 16 + 2 * t + (v >> 1) * 8;
    float w0 = W[oc * ICt + ic], w1 = W[oc * ICt + ic + 1];
    if (FOLD) { w0 *= gamma[ic]; w1 *= gamma[ic + 1]; }
    dst[idx] = packbf(w0, w1);
}

// pack conv3x3 weights, pair-interleaved (ic0, ic0+8)
__global__ void pack3x3_kernel(const float* __restrict__ W) {
    int idx = blockIdx.x * 256 + threadIdx.x;
    if (idx >= WP3SZ) return;
    int r = idx;
    int v = r & 3; r >>= 2;
    int lane = r & 31; r >>= 5;
    int mb = r % 3; r /= 3;
    int kx = r % 3; r /= 3;
    int og = r % 2; r /= 2;
    int ky = r % 3; r /= 3;
    int ch = r % NCH3; r /= NCH3;
    int ocT = r;
    int g = lane >> 2, t = lane & 3;
    int oc = ocT * 96 + og * 48 + mb * 16 + g + (v & 1) * 8;
    int ic0 = ch * 16 + t + (v >> 1) * 4;
    float w0 = W[(oc * C3 + ic0) * 9 + ky * 3 + kx];
    float w1 = W[(oc * C3 + ic0 + 8) * 9 + ky * 3 + kx];
    g_Wp3[idx] = packbf(w0, w1);
}

__global__ void zero_kernel(float* __restrict__ p, int n) {
    int i = blockIdx.x * 256 + threadIdx.x;
    if (i < n) p[i] = 0.f;
}

// ---------------------------------------------------------------------------
// Per-pixel LayerNorm stats over 96 channels, 4 px/thread
// ---------------------------------------------------------------------------
__global__ __launch_bounds__(256) void ln_stats_kernel(const float* __restrict__ x,
                                                       float* __restrict__ mu,
                                                       float* __restrict__ rstd) {
    int i4 = blockIdx.x * 256 + threadIdx.x;          // 0 .. BATCH*HW/4-1
    int b = i4 >> 14;
    int p = (i4 & 16383) << 2;
    const float* xp = x + (size_t)b * DIM * HW + p;
    float4 s = make_float4(0.f, 0.f, 0.f, 0.f);
    float4 s2 = make_float4(0.f, 0.f, 0.f, 0.f);
#pragma unroll 8
    for (int c = 0; c < DIM; c++) {
        float4 v = *(const float4*)&xp[(size_t)c * HW];
        s.x += v.x; s.y += v.y; s.z += v.z; s.w += v.w;
        s2.x += v.x * v.x; s2.y += v.y * v.y; s2.z += v.z * v.z; s2.w += v.w * v.w;
    }
    const float inv = 1.f / DIM;
    float4 m = make_float4(s.x * inv, s.y * inv, s.z * inv, s.w * inv);
    float4 rs;
    rs.x = rsqrtf(s2.x * inv - m.x * m.x + 1e-5f);
    rs.y = rsqrtf(s2.y * inv - m.y * m.y + 1e-5f);
    rs.z = rsqrtf(s2.z * inv - m.z * m.z + 1e-5f);
    rs.w = rsqrtf(s2.w * inv - m.w * m.w + 1e-5f);
    *(float4*)&mu[(size_t)b * HW + p] = m;
    *(float4*)&rstd[(size_t)b * HW + p] = rs;
}

// ---------------------------------------------------------------------------
// 1x1 conv, fp32 input, bf16 mma. OMODE: 1 = ch-pair words out; 2 = px-pair out.
// ---------------------------------------------------------------------------
template <int IC, int OMODE>
__global__ __launch_bounds__(256) void conv1x1_bmma_kernel(
    const float* __restrict__ in,
    const uint32_t* __restrict__ Wp,
    const float* __restrict__ wgs, const float* __restrict__ wb,
    const float* __restrict__ mu, const float* __restrict__ rstd,
    uint32_t* __restrict__ outv) {
    constexpr int NCH = IC / 16;
    __shared__ __align__(16) float bsm[2][16 * BR1];
    __shared__ __align__(16) uint32_t wsm[2][768];
    __shared__ float smu[256], srstd[256];

    int b = blockIdx.z;
    int ocT = blockIdx.y;
    int px0 = blockIdx.x * 256;
    int OCtot = gridDim.y * 96;
    int tid = threadIdx.x;
    int warp = tid >> 5, lane = tid & 31;
    int og = warp >> 2, pg = warp & 3;
    int g = lane >> 2, t = lane & 3;

    if (tid < 64)
        *(float4*)&smu[tid * 4] = *(const float4*)&mu[(size_t)b * HW + px0 + tid * 4];
    else if (tid < 128) {
        int q = tid - 64;
        *(float4*)&srstd[q * 4] = *(const float4*)&rstd[(size_t)b * HW + px0 + q * 4];
    }

    float acc[3][8][4];
#pragma unroll
    for (int mb = 0; mb < 3; mb++)
#pragma unroll
        for (int j = 0; j < 8; j++)
#pragma unroll
            for (int v = 0; v < 4; v++) acc[mb][j][v] = 0.f;

    const uint32_t* Wb = Wp + (size_t)ocT * NCH * 768;

    auto issue = [&](int ch, int buf) {
#pragma unroll
        for (int k = 0; k < 4; k++) {
            int idx = tid + k * 256;
            int ic = idx >> 6, c4 = idx & 63;
            const float* src = in + ((size_t)b * IC + ch * 16 + ic) * HW + px0 + c4 * 4;
            cpa16((uint32_t)__cvta_generic_to_shared(&bsm[buf][ic * BR1 + c4 * 4]), src);
        }
        if (tid < 192)
            cpa16((uint32_t)__cvta_generic_to_shared(&wsm[buf][tid * 4]),
                  Wb + ch * 768 + tid * 4);
        asm volatile("cp.async.commit_group;");
    };

    issue(0, 0);

    for (int s = 0; s < NCH; s++) {
        if (s + 1 < NCH) {
            issue(s + 1, (s + 1) & 1);
            asm volatile("cp.async.wait_group 1;");
        } else {
            asm volatile("cp.async.wait_group 0;");
        }
        __syncthreads();

        int buf = s & 1;
        const uint32_t* wc = &wsm[buf][og * 384];
        uint32_t a[3][4];
#pragma unroll
        for (int mb = 0; mb < 3; mb++)
            *(uint4*)a[mb] = *(const uint4*)&wc[mb * 128 + lane * 4];
        const float* bB = &bsm[buf][0];
#pragma unroll
        for (int j = 0; j < 8; j++) {
            int col = pg * 64 + 8 * j + g;
            float x0 = bB[(2 * t) * BR1 + col];
            float x1 = bB[(2 * t + 1) * BR1 + col];
            float x2 = bB[(2 * t + 8) * BR1 + col];
            float x3 = bB[(2 * t + 9) * BR1 + col];
            uint32_t b0 = packbf(x0, x1), b1 = packbf(x2, x3);
#pragma unroll
            for (int mb = 0; mb < 3; mb++)
                mma_bf16(acc[mb][j], a[mb], b0, b1);
        }
        __syncthreads();
    }

#pragma unroll
    for (int mb = 0; mb < 3; mb++) {
        int oc = ocT * 96 + og * 48 + mb * 16 + g;
        float gs0 = wgs[oc], gs8 = wgs[oc + 8];
        float bb0 = wb[oc], bb8 = wb[oc + 8];
#pragma unroll
        for (int j = 0; j < 8; j++) {
            int pl = pg * 64 + 8 * j + 2 * t;
            int px = px0 + pl;
            float m0 = smu[pl], m1 = smu[pl + 1];
            float r0 = srstd[pl], r1 = srstd[pl + 1];
            float v00 = r0 * (acc[mb][j][0] - m0 * gs0) + bb0;
            float v01 = r1 * (acc[mb][j][1] - m1 * gs0) + bb0;
            float v10 = r0 * (acc[mb][j][2] - m0 * gs8) + bb8;
            float v11 = r1 * (acc[mb][j][3] - m1 * gs8) + bb8;
            if (OMODE == 1) {
                int ch = ocT * 6 + og * 3 + mb;
                int c2 = ch * 8 + g;
                uint2 val = make_uint2(packbf(v00, v10), packbf(v01, v11));
                *(uint2*)&outv[((size_t)b * (OCtot / 2) + c2) * HW + px] = val;
            } else {
                outv[(((size_t)b * OCtot + oc) * HW + px) >> 1] = packbf(v00, v01);
                outv[(((size_t)b * OCtot + oc + 8) * HW + px) >> 1] = packbf(v10, v11);
            }
        }
    }
}

// ---------------------------------------------------------------------------
// 1x1 conv, u32 pair-word input (8 words/chunk), fp32 out + residual.
// OC fixed at 96 (gridDim.y == 1).
// ---------------------------------------------------------------------------
template <int ICW>
__global__ __launch_bounds__(256) void conv1x1u_bmma_kernel(
    const uint32_t* __restrict__ in, int in_bstride,
    const uint32_t* __restrict__ Wp, int w_bstride,
    const float* __restrict__ res,
    float* __restrict__ out) {
    constexpr int NCH = ICW / 8;
    __shared__ __align__(16) uint32_t bsmw[2][8 * BRW];
    __shared__ __align__(16) uint32_t wsm[2][768];

    int b = blockIdx.z;
    int px0 = blockIdx.x * 256;
    int tid = threadIdx.x;
    int warp = tid >> 5, lane = tid & 31;
    int og = warp >> 2, pg = warp & 3;
    int g = lane >> 2, t = lane & 3;

    float acc[3][8][4];
#pragma unroll
    for (int mb = 0; mb < 3; mb++)
#pragma unroll
        for (int j = 0; j < 8; j++)
#pragma unroll
            for (int v = 0; v < 4; v++) acc[mb][j][v] = 0.f;

    const uint32_t* Wb = Wp + (size_t)b * w_bstride;

    auto issue = [&](int ch, int buf) {
#pragma unroll
        for (int k = 0; k < 2; k++) {
            int idx = tid + k * 256;
            int row = idx >> 6, c4 = idx & 63;
            const uint32_t* src = in + (size_t)b * in_bstride +
                                  (size_t)(ch * 8 + row) * HW + px0 + c4 * 4;
            cpa16((uint32_t)__cvta_generic_to_shared(&bsmw[buf][row * BRW + c4 * 4]), src);
        }
        if (tid < 192)
            cpa16((uint32_t)__cvta_generic_to_shared(&wsm[buf][tid * 4]),
                  Wb + ch * 768 + tid * 4);
        asm volatile("cp.async.commit_group;");
    };

    issue(0, 0);

    for (int s = 0; s < NCH; s++) {
        if (s + 1 < NCH) {
            issue(s + 1, (s + 1) & 1);
            asm volatile("cp.async.wait_group 1;");
        } else {
            asm volatile("cp.async.wait_group 0;");
        }
        __syncthreads();

        int buf = s & 1;
        const uint32_t* wc = &wsm[buf][og * 384];
        uint32_t a[3][4];
#pragma unroll
        for (int mb = 0; mb < 3; mb++)
            *(uint4*)a[mb] = *(const uint4*)&wc[mb * 128 + lane * 4];
        const uint32_t* bB = &bsmw[buf][0];
#pragma unroll
        for (int j = 0; j < 8; j++) {
            int col = pg * 64 + 8 * j + g;
            uint32_t b0 = bB[t * BRW + col];
            uint32_t b1 = bB[(t + 4) * BRW + col];
#pragma unroll
            for (int mb = 0; mb < 3; mb++)
                mma_bf16(acc[mb][j], a[mb], b0, b1);
        }
        __syncthreads();
    }

#pragma unroll
    for (int mb = 0; mb < 3; mb++) {
        int oc = og * 48 + mb * 16 + g;
#pragma unroll
        for (int j = 0; j < 8; j++) {
            int px = px0 + pg * 64 + 8 * j + 2 * t;
            float2 ra = *(const float2*)&res[((size_t)b * 96 + oc) * HW + px];
            float2 rb = *(const float2*)&res[((size_t)b * 96 + oc + 8) * HW + px];
            float2 v01 = make_float2(acc[mb][j][0] + ra.x, acc[mb][j][1] + ra.y);
            float2 v23 = make_float2(acc[mb][j][2] + rb.x, acc[mb][j][3] + rb.y);
            *(float2*)&out[((size_t)b * 96 + oc) * HW + px] = v01;
            *(float2*)&out[((size_t)b * 96 + oc + 8) * HW + px] = v23;
        }
    }
}

// ---------------------------------------------------------------------------
// 3x3 conv 288 -> 288, bf16 mma, bf16 pair-word input.
// Outputs: q,k as bf16 pixel-pair words; v as bf16 channel-pair words.
// Fused q/k sum-of-squares epilogue (fp32 accumulators, atomics).
// ---------------------------------------------------------------------------
__global__ __launch_bounds__(256) void conv3x3_bmma_kernel(const uint32_t* __restrict__ in,
                                                           uint32_t* __restrict__ qk,
                                                           uint32_t* __restrict__ vout,
                                                           float* __restrict__ sqk) {
    extern __shared__ uint32_t dynsmem[];
    uint32_t* bsm = dynsmem;
    uint32_t* wsm = dynsmem + 2 * BSM3;

    int b   = blockIdx.z;
    int ocT = blockIdx.y;
    int y   = blockIdx.x;
    int tid = threadIdx.x;
    int warp = tid >> 5, lane = tid & 31;
    int og = warp >> 2, pg = warp & 3;
    int g = lane >> 2, t = lane & 3;

    if (tid < 96) {
        int s = tid;
        int side = s & 1; s >>= 1;
        int wr = s % 24; int bufi = s / 24;
        bsm[bufi * BSM3 + wr * BROW3 + (side ? 260 : 3)] = 0u;
    }

    float acc[3][8][4];
#pragma unroll
    for (int mb = 0; mb < 3; mb++)
#pragma unroll
        for (int j = 0; j < 8; j++)
#pragma unroll
            for (int v = 0; v < 4; v++) acc[mb][j][v] = 0.f;

    const uint32_t* wp_base = g_Wp3 + (size_t)ocT * NCH3 * WCH3;

    auto issue = [&](int ch, int buf) {
        const uint32_t* ibase = in + ((size_t)b * (C3 / 2) + ch * 8) * HW;
        uint32_t* bdst = bsm + buf * BSM3;
#pragma unroll
        for (int k = 0; k < 6; k++) {
            int idx = tid + k * 256;
            int wr = idx >> 6, c4 = idx & 63;
            int w = wr / 3, rr = wr - 3 * w;
            int gy = y + rr - 1;
            bool ok = (unsigned)gy < 256u;
            const uint32_t* src = ibase + (size_t)w * HW + (ok ? gy : 0) * IMG + c4 * 4;
            cpa16z((uint32_t)__cvta_generic_to_shared(
                       bdst + wr * BROW3 + 4 + c4 * 4), src, ok);
        }
        const uint32_t* wsrc = wp_base + (size_t)ch * WCH3;
        uint32_t* wdst = wsm + buf * WCH3;
#pragma unroll
        for (int k = 0; k < 7; k++) {
            int i = tid + k * 256;
            if (i < WCH3 / 4)
                cpa16((uint32_t)__cvta_generic_to_shared(wdst + i * 4), wsrc + i * 4);
        }
        asm volatile("cp.async.commit_group;");
    };

    issue(0, 0);

    for (int s = 0; s < NCH3; s++) {
        if (s + 1 < NCH3) {
            issue(s + 1, (s + 1) & 1);
            asm volatile("cp.async.wait_group 1;");
        } else {
            asm volatile("cp.async.wait_group 0;");
        }
        __syncthreads();

        int buf = s & 1;
        const uint32_t* bB = bsm + buf * BSM3;
        const uint32_t* wc = wsm + buf * WCH3;
        int colb = 3 + pg * 64 + g;
#pragma unroll
        for (int ky = 0; ky < 3; ky++) {
#pragma unroll
            for (int kx = 0; kx < 3; kx++) {
                const uint32_t* wbp = wc + (((ky * 2 + og) * 3 + kx) * 3) * 128;
                uint32_t a[3][4];
#pragma unroll
                for (int mb = 0; mb < 3; mb++)
                    *(uint4*)a[mb] = *(const uint4*)&wbp[mb * 128 + lane * 4];
#pragma unroll
                for (int j = 0; j < 8; j++) {
                    int col = colb + 8 * j + kx;
                    uint32_t b0 = bB[(t * 3 + ky) * BROW3 + col];
                    uint32_t b1 = bB[((t + 4) * 3 + ky) * BROW3 + col];
#pragma unroll
                    for (int mb = 0; mb < 3; mb++)
                        mma_bf16(acc[mb][j], a[mb], b0, b1);
                }
            }
        }
        __syncthreads();
    }

    if (ocT < 2) {
        // fused sum-of-squares + pixel-pair bf16 store for q,k
#pragma unroll
        for (int mb = 0; mb < 3; mb++) {
            float s0 = 0.f, s8 = 0.f;
#pragma unroll
            for (int j = 0; j < 8; j++) {
                s0 += acc[mb][j][0] * acc[mb][j][0] + acc[mb][j][1] * acc[mb][j][1];
                s8 += acc[mb][j][2] * acc[mb][j][2] + acc[mb][j][3] * acc[mb][j][3];
            }
            s0 += __shfl_xor_sync(0xffffffffu, s0, 1);
            s0 += __shfl_xor_sync(0xffffffffu, s0, 2);
            s8 += __shfl_xor_sync(0xffffffffu, s8, 1);
            s8 += __shfl_xor_sync(0xffffffffu, s8, 2);
            int oc = ocT * 96 + og * 48 + mb * 16 + g;
            if (t == 0) {
                atomicAdd(&sqk[b * 2 * DIM + oc], s0);
                atomicAdd(&sqk[b * 2 * DIM + oc + 8], s8);
            }
#pragma unroll
            for (int j = 0; j < 8; j++) {
                int px = pg * 64 + 8 * j + 2 * t;
                size_t base = (size_t)(b * 192 + oc) * (HW / 2) + ((y * IMG + px) >> 1);
                qk[base] = packbf(acc[mb][j][0], acc[mb][j][1]);
                qk[base + (size_t)8 * (HW / 2)] = packbf(acc[mb][j][2], acc[mb][j][3]);
            }
        }
    } else {
        // v: channel-pair bf16 words (oc_local, oc_local+8)
#pragma unroll
        for (int mb = 0; mb < 3; mb++) {
            int c2 = (og * 3 + mb) * 8 + g;
#pragma unroll
            for (int j = 0; j < 8; j++) {
                int px = pg * 64 + 8 * j + 2 * t;
                uint2 val = make_uint2(packbf(acc[mb][j][0], acc[mb][j][2]),
                                       packbf(acc[mb][j][1], acc[mb][j][3]));
                *(uint2*)&vout[((size_t)(b * 48 + c2)) * HW + y * IMG + px] = val;
            }
        }
    }
}

// ---------------------------------------------------------------------------
// Channel-gram via bf16 warp MMA over K = pixels, reading pixel-pair words.
// Slot permutation identical on A and B sides -> exact gram.
// ---------------------------------------------------------------------------
__global__ __launch_bounds__(256) void attn_bmma_kernel(const uint32_t* __restrict__ qk,
                                                        float* __restrict__ attn_raw) {
    int bh = blockIdx.y;
    int b = bh / HEADS, h = bh - b * HEADS;
    int warp = threadIdx.x >> 5, lane = threadIdx.x & 31;
    int tg = lane >> 2, t = lane & 3;

    const uint32_t* q0 = qk + (size_t)(b * 192 + h * HDIM + tg) * (HW / 2);
    const uint32_t* q1 = q0 + (size_t)8 * (HW / 2);
    const uint32_t* k0 = qk + (size_t)(b * 192 + 96 + h * HDIM + tg) * (HW / 2);
    const uint32_t* k1 = k0 + (size_t)8 * (HW / 2);

    float c0[4] = {0.f, 0.f, 0.f, 0.f};
    float c1[4] = {0.f, 0.f, 0.f, 0.f};

    int slab0 = (blockIdx.x * 8 + warp) * 32;     // 32 slabs of 32 words (64 px)
    for (int s = 0; s < 32; s++) {
        int w0 = (slab0 + s) * 32 + 4 * t;
        uint32_t qa[4], qb[4], qc[4], qd[4], ka[4], kc[4], kb[4], kd[4];
        *(uint4*)qa = *(const uint4*)(q0 + w0);
        *(uint4*)qb = *(const uint4*)(q1 + w0);
        *(uint4*)qc = *(const uint4*)(q0 + w0 + 16);
        *(uint4*)qd = *(const uint4*)(q1 + w0 + 16);
        *(uint4*)ka = *(const uint4*)(k0 + w0);
        *(uint4*)kc = *(const uint4*)(k0 + w0 + 16);
        *(uint4*)kb = *(const uint4*)(k1 + w0);
        *(uint4*)kd = *(const uint4*)(k1 + w0 + 16);
#pragma unroll
        for (int m = 0; m < 4; m++) {
            uint32_t a[4] = { qa[m], qb[m], qc[m], qd[m] };
            mma_bf16(c0, a, ka[m], kc[m]);
            mma_bf16(c1, a, kb[m], kd[m]);
        }
    }

    float* dst = attn_raw + bh * 256;
    atomicAdd(dst + tg * 16 + 2 * t,           c0[0]);
    atomicAdd(dst + tg * 16 + 2 * t + 1,       c0[1]);
    atomicAdd(dst + (tg + 8) * 16 + 2 * t,     c0[2]);
    atomicAdd(dst + (tg + 8) * 16 + 2 * t + 1, c0[3]);
    atomicAdd(dst + tg * 16 + 8 + 2 * t,           c1[0]);
    atomicAdd(dst + tg * 16 + 8 + 2 * t + 1,       c1[1]);
    atomicAdd(dst + (tg + 8) * 16 + 8 + 2 * t,     c1[2]);
    atomicAdd(dst + (tg + 8) * 16 + 8 + 2 * t + 1, c1[3]);
}

// ---------------------------------------------------------------------------
// softmax + fused 96x96 matrix M = proj @ blockdiag(attn), packed bf16 with
// (ic0, ic0+8) pairing matching the v channel-pair words.
// ---------------------------------------------------------------------------
__global__ __launch_bounds__(256) void softmax_build_M(const float* __restrict__ attn_raw,
                                                       const float* __restrict__ sqk,
                                                       const float* __restrict__ scale,
                                                       const float* __restrict__ proj_w,
                                                       uint32_t* __restrict__ Mp) {
    int b = blockIdx.x;
    int tdx = threadIdx.x;
    __shared__ float A[HEADS * 256];
    __shared__ float nq[DIM], nk[DIM];
    if (tdx < DIM) {
        nq[tdx] = fmaxf(sqrtf(sqk[b * 2 * DIM + tdx]), 1e-12f);
        nk[tdx] = fmaxf(sqrtf(sqk[b * 2 * DIM + DIM + tdx]), 1e-12f);
    }
    __syncthreads();
    for (int idx = tdx; idx < HEADS * 256; idx += 256) {
        int h = idx >> 8;
        int cd = idx & 255;
        int c = cd >> 4, d = cd & 15;
        A[idx] = attn_raw[b * HEADS * 256 + idx] /
                 (nq[h * HDIM + c] * nk[h * HDIM + d]) * scale[h];
    }
    __syncthreads();
    if (tdx < DIM) {
        int h = tdx >> 4, c = tdx & 15;
        float* row = &A[h * 256 + c * 16];
        float mx = row[0];
#pragma unroll
        for (int d = 1; d < 16; d++) mx = fmaxf(mx, row[d]);
        float sum = 0.f;
#pragma unroll
        for (int d = 0; d < 16; d++) { float e = expf(row[d] - mx); row[d] = e; sum += e; }
        float inv = 1.f / sum;
#pragma unroll
        for (int d = 0; d < 16; d++) row[d] *= inv;
    }
    __syncthreads();
    for (int idx = tdx; idx < DIM * DIM / 2; idx += 256) {
        int r = idx;
        int v = r & 3; r >>= 2;
        int lane = r & 31; r >>= 5;
        int mb = r % 3; r /= 3;
        int og = r % 2; r /= 2;
        int ch = r;
        int g = lane >> 2, t = lane & 3;
        int oc = og * 48 + mb * 16 + g + (v & 1) * 8;
        int d = t + (v >> 1) * 4;         // ic0 = ch*16 + d, pair (ic0, ic0+8)
        int h = ch;
        float s0 = 0.f, s1 = 0.f;
#pragma unroll
        for (int cg = 0; cg < 16; cg++) {
            float pw = proj_w[oc * DIM + h * HDIM + cg];
            s0 += pw * A[h * 256 + cg * 16 + d];
            s1 += pw * A[h * 256 + cg * 16 + d + 8];
        }
        Mp[b * (DIM * DIM / 2) + idx] = packbf(s0, s1);
    }
}

// ---------------------------------------------------------------------------
// Grouped 3x3 conv + GELU gate, bf16 in, bf16 channel-pair words out.
// ---------------------------------------------------------------------------
__device__ __forceinline__ float gelu_tanh(float x) {
    float x3 = x * x * x;
    return 0.5f * x * (1.f + tanhf(0.7978845608028654f * (x + 0.044715f * x3)));
}

__global__ __launch_bounds__(128) void dwgate_kernel(const __nv_bfloat16* __restrict__ tin,
                                                     const float* __restrict__ dw,
                                                     uint32_t* __restrict__ gw) {
    int b = blockIdx.z;
    int m = blockIdx.y;
    int y = blockIdx.x >> 1;
    int px0 = (blockIdx.x & 1) * 128;
    int tid = threadIdx.x;

    __shared__ float sin_s[4][3][132];
    __shared__ float swt[72];

    int chans[4] = {2 * m, 2 * m + 1, HID + 2 * m, HID + 2 * m + 1};

    for (int idx = tid; idx < 4 * 3 * 130; idx += 128) {
        int ch = idx / 390;
        int rem = idx - ch * 390;
        int r = rem / 130;
        int l = rem - r * 130;
        int gy = y + r - 1, gx = px0 - 1 + l;
        float v = 0.f;
        if ((unsigned)gy < 256u && (unsigned)gx < 256u)
            v = __bfloat162float(tin[(((size_t)b * HID2 + chans[ch]) * IMG + gy) * IMG + gx]);
        sin_s[ch][r][l] = v;
    }
    if (tid < 72) {
        int oci = tid / 18;
        int rem = tid - oci * 18;
        swt[tid] = dw[(size_t)chans[oci] * 18 + rem];
    }
    __syncthreads();

    float u[4] = {0.f, 0.f, 0.f, 0.f};
#pragma unroll
    for (int ol = 0; ol < 4; ol++) {
        int i0 = (ol < 2) ? 0 : 2;
#pragma unroll
        for (int i = 0; i < 2; i++)
#pragma unroll
            for (int ky = 0; ky < 3; ky++)
#pragma unroll
                for (int kx = 0; kx < 3; kx++)
                    u[ol] += swt[ol * 18 + i * 9 + ky * 3 + kx] * sin_s[i0 + i][ky][tid + kx];
    }
    float r0 = gelu_tanh(u[0]) * u[2];
    float r1 = gelu_tanh(u[1]) * u[3];
    gw[((size_t)b * 96 + m) * HW + y * IMG + px0 + tid] = packbf(r0, r1);
}

// ---------------------------------------------------------------------------
// Launch
// ---------------------------------------------------------------------------
static void* sym_addr(const void* sym) {
    void* p = nullptr;
    cudaGetSymbolAddress(&p, sym);
    return p;
}

extern "C" void kernel_launch(void* const* d_in, const int* in_sizes, int n_in,
                              void* d_out, int out_size) {
    const float* x      = (const float*)d_in[0];
    const float* ln1_w  = (const float*)d_in[1];
    const float* ln1_b  = (const float*)d_in[2];
    const float* qkv1_w = (const float*)d_in[3];
    const float* qkv2_w = (const float*)d_in[4];
    const float* proj_w = (const float*)d_in[5];
    const float* scale  = (const float*)d_in[6];
    const float* ln2_w  = (const float*)d_in[7];
    const float* ln2_b  = (const float*)d_in[8];
    const float* pin_w  = (const float*)d_in[9];
    const float* dw_w   = (const float*)d_in[10];
    const float* pout_w = (const float*)d_in[11];

    uint32_t* qkvh = (uint32_t*)sym_addr(g_qkvh);
    uint32_t* qkpp = (uint32_t*)sym_addr(g_qkpp);
    uint32_t* vcp  = (uint32_t*)sym_addr(g_vcp);
    uint32_t* tbuf = (uint32_t*)sym_addr(g_t);
    uint32_t* gw   = (uint32_t*)sym_addr(g_gw);
    float* x2    = (float*)sym_addr(g_x2);
    float* mu    = (float*)sym_addr(g_mu);
    float* rstd  = (float*)sym_addr(g_rstd);
    float* wgs1  = (float*)sym_addr(g_wgs1);
    float* wb1   = (float*)sym_addr(g_wb1);
    float* wgs2  = (float*)sym_addr(g_wgs2);
    float* wb2   = (float*)sym_addr(g_wb2);
    float* sqk   = (float*)sym_addr(g_sqk);
    float* attn  = (float*)sym_addr(g_attn);
    uint32_t* Wp1 = (uint32_t*)sym_addr(g_Wp1);
    uint32_t* Wp2 = (uint32_t*)sym_addr(g_Wp2);
    uint32_t* Wpo = (uint32_t*)sym_addr(g_Wpo);
    uint32_t* Mp  = (uint32_t*)sym_addr(g_Mp);
    float* out   = (float*)d_out;

    static bool attr_done = false;
    if (!attr_done) {
        cudaFuncSetAttribute(conv3x3_bmma_kernel,
                             cudaFuncAttributeMaxDynamicSharedMemorySize, SMEM3);
        attr_done = true;
    }

    // weight prep + zero accumulators
    prep_kernel<<<3, 256>>>(qkv1_w, ln1_w, ln1_b, pin_w, ln2_w, ln2_b);
    pack1x1_kernel<true><<<(C3 * DIM / 2 + 255) / 256, 256>>>(qkv1_w, ln1_w, Wp1, C3, DIM);
    pack1x1_kernel<true><<<(HID2 * DIM / 2 + 255) / 256, 256>>>(pin_w, ln2_w, Wp2, HID2, DIM);
    pack1x1_kernel<false><<<(DIM * HID / 2 + 255) / 256, 256>>>(pout_w, nullptr, Wpo, DIM, HID);
    pack3x3_kernel<<<(WP3SZ + 255) / 256, 256>>>(qkv2_w);
    zero_kernel<<<24, 256>>>(attn, BATCH * HEADS * 256);
    zero_kernel<<<3, 256>>>(sqk, BATCH * 2 * DIM);

    // LN1 stats, then LN-fused qkv1 (96 -> 288) -> bf16 channel-pair words
    ln_stats_kernel<<<BATCH * HW / 4 / 256, 256>>>(x, mu, rstd);
    conv1x1_bmma_kernel<DIM, 1><<<dim3(256, 3, BATCH), 256>>>(
        x, Wp1, wgs1, wb1, mu, rstd, qkvh);

    // qkv2: 3x3 conv 288 -> 288 (bf16 mma), q/k px-pair out + v ch-pair out + sumsq
    conv3x3_bmma_kernel<<<dim3(256, 3, BATCH), 256, SMEM3>>>(qkvh, qkpp, vcp, sqk);

    // attention statistics (bf16 gram)
    attn_bmma_kernel<<<dim3(4, BATCH * HEADS), 256>>>(qkpp, attn);
    softmax_build_M<<<BATCH, 256>>>(attn, sqk, scale, proj_w, Mp);

    // fused (attn@v -> proj -> +x) over bf16 v words
    conv1x1u_bmma_kernel<48><<<dim3(256, 1, BATCH), 256>>>(
        vcp, 48 * HW, Mp, DIM * DIM / 2, x, x2);

    // LN2 stats, LN-fused pin (96 -> 384) -> bf16 pixel-pair words
    ln_stats_kernel<<<BATCH * HW / 4 / 256, 256>>>(x2, mu, rstd);
    conv1x1_bmma_kernel<DIM, 2><<<dim3(256, 4, BATCH), 256>>>(
        x2, Wp2, wgs2, wb2, mu, rstd, tbuf);

    // grouped 3x3 conv + GELU gate -> bf16 channel-pair words
    dwgate_kernel<<<dim3(512, DIM, BATCH), 128>>>((const __nv_bfloat16*)tbuf, dw_w, gw);

    // pout (192 -> 96) + residual -> output
    conv1x1u_bmma_kernel<96><<<dim3(256, 1, BATCH), 256>>>(
        gw, 96 * HW, Wpo, 0, x2, out);
}

// round 11
// speedup vs baseline: 10.0034x; 1.4495x over previous
#include <cuda_runtime.h>
#include <cuda_bf16.h>
#include <cmath>
#include <cstdint>

#define BATCH 4
#define DIM   96
#define HEADS 6
#define HDIM  16
#define C3    288
#define HID   192
#define HID2  384
#define HW    65536
#define IMG   256

// conv3x3 bf16 mma tiling: chunk = 16 ic (= 8 u32 pair-words)
#define NCH3   18
#define BROW3  280
#define BSM3   (8 * 3 * BROW3)
#define WCH3   6912
#define WP3SZ  (3 * NCH3 * WCH3)
#define SMEM3  ((2 * BSM3 + 2 * WCH3) * 4)   // 109056 bytes

#define BR1    268
#define BRW    264

// ---------------- scratch ----------------
__device__ __align__(16) uint32_t g_qkvh [(size_t)BATCH * (C3 / 2) * HW];
__device__ __align__(16) uint32_t g_qkpp [(size_t)BATCH * 192 * (HW / 2)];
__device__ __align__(16) uint32_t g_vcp  [(size_t)BATCH * 48 * HW];
__device__ __align__(16) uint32_t g_t    [(size_t)BATCH * HID2 * HW / 2];
__device__ __align__(16) uint32_t g_gw   [(size_t)BATCH * 96 * HW];
__device__ float g_x2   [(size_t)BATCH * DIM * HW];
__device__ float g_mu   [BATCH * HW];
__device__ float g_rstd [BATCH * HW];
__device__ float g_wgs1 [C3];
__device__ float g_wb1  [C3];
__device__ float g_wgs2 [HID2];
__device__ float g_wb2  [HID2];
__device__ float g_sqk  [BATCH * 2 * DIM];
__device__ float g_attn [BATCH * HEADS * HDIM * HDIM];
__device__ __align__(16) uint32_t g_Wp1 [C3 * DIM / 2];
__device__ __align__(16) uint32_t g_Wp2 [HID2 * DIM / 2];
__device__ __align__(16) uint32_t g_Wpo [DIM * HID / 2];
__device__ __align__(16) uint32_t g_Mp  [BATCH * DIM * DIM / 2];
__device__ __align__(16) uint32_t g_Wp3 [WP3SZ];

// ---------------- helpers ----------------
__device__ __forceinline__ void cpa16(uint32_t dst, const void* src) {
    asm volatile("cp.async.cg.shared.global [%0], [%1], 16;" :: "r"(dst), "l"(src));
}
__device__ __forceinline__ void cpa16z(uint32_t dst, const void* src, bool v) {
    asm volatile("cp.async.cg.shared.global [%0], [%1], 16, %2;"
                 :: "r"(dst), "l"(src), "r"(v ? 16u : 0u));
}
__device__ __forceinline__ uint32_t packbf(float lo, float hi) {
    uint32_t r;
    asm("cvt.rn.bf16x2.f32 %0, %1, %2;" : "=r"(r) : "f"(hi), "f"(lo));
    return r;
}
__device__ __forceinline__ void mma_bf16(float* c, const uint32_t* a,
                                         uint32_t b0, uint32_t b1) {
    asm volatile("mma.sync.aligned.m16n8k16.row.col.f32.bf16.bf16.f32 "
                 "{%0,%1,%2,%3}, {%4,%5,%6,%7}, {%8,%9}, {%0,%1,%2,%3};"
                 : "+f"(c[0]), "+f"(c[1]), "+f"(c[2]), "+f"(c[3])
                 : "r"(a[0]), "r"(a[1]), "r"(a[2]), "r"(a[3]), "r"(b0), "r"(b1));
}

// ---------------- prep ----------------
__global__ void prep_kernel(const float* __restrict__ qkv1_w, const float* __restrict__ ln1_w,
                            const float* __restrict__ ln1_b, const float* __restrict__ pin_w,
                            const float* __restrict__ ln2_w, const float* __restrict__ ln2_b) {
    int t = blockIdx.x * 256 + threadIdx.x;
    if (t < C3) {
        float s = 0.f, sb = 0.f;
        for (int c = 0; c < DIM; c++) {
            float w = qkv1_w[t * DIM + c];
            s += w * ln1_w[c]; sb += w * ln1_b[c];
        }
        g_wgs1[t] = s; g_wb1[t] = sb;
    } else if (t < C3 + HID2) {
        int r = t - C3;
        float s = 0.f, sb = 0.f;
        for (int c = 0; c < DIM; c++) {
            float w = pin_w[r * DIM + c];
            s += w * ln2_w[c]; sb += w * ln2_b[c];
        }
        g_wgs2[r] = s; g_wb2[r] = sb;
    }
}

template <bool FOLD>
__global__ void pack1x1_kernel(const float* __restrict__ W, const float* __restrict__ gamma,
                               uint32_t* __restrict__ dst, int OC, int ICt) {
    int idx = blockIdx.x * 256 + threadIdx.x;
    if (idx >= OC * ICt / 2) return;
    int r = idx;
    int v = r & 3; r >>= 2;
    int lane = r & 31; r >>= 5;
    int mb = r % 3; r /= 3;
    int og = r % 2; r /= 2;
    int nch = ICt / 16;
    int ch = r % nch; r /= nch;
    int ocT = r;
    int g = lane >> 2, t = lane & 3;
    int oc = ocT * 96 + og * 48 + mb * 16 + g + (v & 1) * 8;
    int ic = ch * 16 + 2 * t + (v >> 1) * 8;
    float w0 = W[oc * ICt + ic], w1 = W[oc * ICt + ic + 1];
    if (FOLD) { w0 *= gamma[ic]; w1 *= gamma[ic + 1]; }
    dst[idx] = packbf(w0, w1);
}

__global__ void pack3x3_kernel(const float* __restrict__ W) {
    int idx = blockIdx.x * 256 + threadIdx.x;
    if (idx >= WP3SZ) return;
    int r = idx;
    int v = r & 3; r >>= 2;
    int lane = r & 31; r >>= 5;
    int mb = r % 3; r /= 3;
    int kx = r % 3; r /= 3;
    int og = r % 2; r /= 2;
    int ky = r % 3; r /= 3;
    int ch = r % NCH3; r /= NCH3;
    int ocT = r;
    int g = lane >> 2, t = lane & 3;
    int oc = ocT * 96 + og * 48 + mb * 16 + g + (v & 1) * 8;
    int ic0 = ch * 16 + t + (v >> 1) * 4;
    float w0 = W[(oc * C3 + ic0) * 9 + ky * 3 + kx];
    float w1 = W[(oc * C3 + ic0 + 8) * 9 + ky * 3 + kx];
    g_Wp3[idx] = packbf(w0, w1);
}

__global__ void zero_kernel(float* __restrict__ p, int n) {
    int i = blockIdx.x * 256 + threadIdx.x;
    if (i < n) p[i] = 0.f;
}

// ---------------- LN stats (float4, 4 px/thread) ----------------
__global__ __launch_bounds__(256) void ln_stats_kernel(const float* __restrict__ x,
                                                       float* __restrict__ mu,
                                                       float* __restrict__ rstd) {
    int i4 = blockIdx.x * 256 + threadIdx.x;
    int b = i4 >> 14;
    int p = (i4 & 16383) << 2;
    const float* xp = x + (size_t)b * DIM * HW + p;
    float4 s = make_float4(0.f, 0.f, 0.f, 0.f);
    float4 s2 = make_float4(0.f, 0.f, 0.f, 0.f);
#pragma unroll 8
    for (int c = 0; c < DIM; c++) {
        float4 v = *(const float4*)&xp[(size_t)c * HW];
        s.x += v.x; s.y += v.y; s.z += v.z; s.w += v.w;
        s2.x += v.x * v.x; s2.y += v.y * v.y; s2.z += v.z * v.z; s2.w += v.w * v.w;
    }
    const float inv = 1.f / DIM;
    float4 m = make_float4(s.x * inv, s.y * inv, s.z * inv, s.w * inv);
    float4 rs;
    rs.x = rsqrtf(s2.x * inv - m.x * m.x + 1e-5f);
    rs.y = rsqrtf(s2.y * inv - m.y * m.y + 1e-5f);
    rs.z = rsqrtf(s2.z * inv - m.z * m.z + 1e-5f);
    rs.w = rsqrtf(s2.w * inv - m.w * m.w + 1e-5f);
    *(float4*)&mu[(size_t)b * HW + p] = m;
    *(float4*)&rstd[(size_t)b * HW + p] = rs;
}

// ---------------- 1x1 conv, fp32 in (R8, unchanged) ----------------
template <int IC, int OMODE>
__global__ __launch_bounds__(256) void conv1x1_bmma_kernel(
    const float* __restrict__ in, const uint32_t* __restrict__ Wp,
    const float* __restrict__ wgs, const float* __restrict__ wb,
    const float* __restrict__ mu, const float* __restrict__ rstd,
    uint32_t* __restrict__ outv) {
    constexpr int NCH = IC / 16;
    __shared__ __align__(16) float bsm[2][16 * BR1];
    __shared__ __align__(16) uint32_t wsm[2][768];
    __shared__ float smu[256], srstd[256];

    int b = blockIdx.z, ocT = blockIdx.y, px0 = blockIdx.x * 256;
    int OCtot = gridDim.y * 96;
    int tid = threadIdx.x, warp = tid >> 5, lane = tid & 31;
    int og = warp >> 2, pg = warp & 3, g = lane >> 2, t = lane & 3;

    if (tid < 64)
        *(float4*)&smu[tid * 4] = *(const float4*)&mu[(size_t)b * HW + px0 + tid * 4];
    else if (tid < 128) {
        int q = tid - 64;
        *(float4*)&srstd[q * 4] = *(const float4*)&rstd[(size_t)b * HW + px0 + q * 4];
    }

    float acc[3][8][4];
#pragma unroll
    for (int mb = 0; mb < 3; mb++)
#pragma unroll
        for (int j = 0; j < 8; j++)
#pragma unroll
            for (int v = 0; v < 4; v++) acc[mb][j][v] = 0.f;

    const uint32_t* Wb = Wp + (size_t)ocT * NCH * 768;
    auto issue = [&](int ch, int buf) {
#pragma unroll
        for (int k = 0; k < 4; k++) {
            int idx = tid + k * 256;
            int ic = idx >> 6, c4 = idx & 63;
            const float* src = in + ((size_t)b * IC + ch * 16 + ic) * HW + px0 + c4 * 4;
            cpa16((uint32_t)__cvta_generic_to_shared(&bsm[buf][ic * BR1 + c4 * 4]), src);
        }
        if (tid < 192)
            cpa16((uint32_t)__cvta_generic_to_shared(&wsm[buf][tid * 4]), Wb + ch * 768 + tid * 4);
        asm volatile("cp.async.commit_group;");
    };
    issue(0, 0);
    for (int s = 0; s < NCH; s++) {
        if (s + 1 < NCH) { issue(s + 1, (s + 1) & 1); asm volatile("cp.async.wait_group 1;"); }
        else asm volatile("cp.async.wait_group 0;");
        __syncthreads();
        int buf = s & 1;
        const uint32_t* wc = &wsm[buf][og * 384];
        uint32_t a[3][4];
#pragma unroll
        for (int mb = 0; mb < 3; mb++) *(uint4*)a[mb] = *(const uint4*)&wc[mb * 128 + lane * 4];
        const float* bB = &bsm[buf][0];
#pragma unroll
        for (int j = 0; j < 8; j++) {
            int col = pg * 64 + 8 * j + g;
            float x0 = bB[(2 * t) * BR1 + col], x1 = bB[(2 * t + 1) * BR1 + col];
            float x2 = bB[(2 * t + 8) * BR1 + col], x3 = bB[(2 * t + 9) * BR1 + col];
            uint32_t b0 = packbf(x0, x1), b1 = packbf(x2, x3);
#pragma unroll
            for (int mb = 0; mb < 3; mb++) mma_bf16(acc[mb][j], a[mb], b0, b1);
        }
        __syncthreads();
    }
#pragma unroll
    for (int mb = 0; mb < 3; mb++) {
        int oc = ocT * 96 + og * 48 + mb * 16 + g;
        float gs0 = wgs[oc], gs8 = wgs[oc + 8], bb0 = wb[oc], bb8 = wb[oc + 8];
#pragma unroll
        for (int j = 0; j < 8; j++) {
            int pl = pg * 64 + 8 * j + 2 * t;
            int px = px0 + pl;
            float m0 = smu[pl], m1 = smu[pl + 1], r0 = srstd[pl], r1 = srstd[pl + 1];
            float v00 = r0 * (acc[mb][j][0] - m0 * gs0) + bb0;
            float v01 = r1 * (acc[mb][j][1] - m1 * gs0) + bb0;
            float v10 = r0 * (acc[mb][j][2] - m0 * gs8) + bb8;
            float v11 = r1 * (acc[mb][j][3] - m1 * gs8) + bb8;
            if (OMODE == 1) {
                int ch = ocT * 6 + og * 3 + mb;
                int c2 = ch * 8 + g;
                uint2 val = make_uint2(packbf(v00, v10), packbf(v01, v11));
                *(uint2*)&outv[((size_t)b * (OCtot / 2) + c2) * HW + px] = val;
            } else {
                outv[(((size_t)b * OCtot + oc) * HW + px) >> 1] = packbf(v00, v01);
                outv[(((size_t)b * OCtot + oc + 8) * HW + px) >> 1] = packbf(v10, v11);
            }
        }
    }
}

// ---------------- 1x1 conv, u32 pair-word in (R8, unchanged) ----------------
template <int ICW>
__global__ __launch_bounds__(256) void conv1x1u_bmma_kernel(
    const uint32_t* __restrict__ in, int in_bstride,
    const uint32_t* __restrict__ Wp, int w_bstride,
    const float* __restrict__ res, float* __restrict__ out) {
    constexpr int NCH = ICW / 8;
    __shared__ __align__(16) uint32_t bsmw[2][8 * BRW];
    __shared__ __align__(16) uint32_t wsm[2][768];
    int b = blockIdx.z, px0 = blockIdx.x * 256;
    int tid = threadIdx.x, warp = tid >> 5, lane = tid & 31;
    int og = warp >> 2, pg = warp & 3, g = lane >> 2, t = lane & 3;
    float acc[3][8][4];
#pragma unroll
    for (int mb = 0; mb < 3; mb++)
#pragma unroll
        for (int j = 0; j < 8; j++)
#pragma unroll
            for (int v = 0; v < 4; v++) acc[mb][j][v] = 0.f;
    const uint32_t* Wb = Wp + (size_t)b * w_bstride;
    auto issue = [&](int ch, int buf) {
#pragma unroll
        for (int k = 0; k < 2; k++) {
            int idx = tid + k * 256;
            int row = idx >> 6, c4 = idx & 63;
            const uint32_t* src = in + (size_t)b * in_bstride + (size_t)(ch * 8 + row) * HW + px0 + c4 * 4;
            cpa16((uint32_t)__cvta_generic_to_shared(&bsmw[buf][row * BRW + c4 * 4]), src);
        }
        if (tid < 192)
            cpa16((uint32_t)__cvta_generic_to_shared(&wsm[buf][tid * 4]), Wb + ch * 768 + tid * 4);
        asm volatile("cp.async.commit_group;");
    };
    issue(0, 0);
    for (int s = 0; s < NCH; s++) {
        if (s + 1 < NCH) { issue(s + 1, (s + 1) & 1); asm volatile("cp.async.wait_group 1;"); }
        else asm volatile("cp.async.wait_group 0;");
        __syncthreads();
        int buf = s & 1;
        const uint32_t* wc = &wsm[buf][og * 384];
        uint32_t a[3][4];
#pragma unroll
        for (int mb = 0; mb < 3; mb++) *(uint4*)a[mb] = *(const uint4*)&wc[mb * 128 + lane * 4];
        const uint32_t* bB = &bsmw[buf][0];
#pragma unroll
        for (int j = 0; j < 8; j++) {
            int col = pg * 64 + 8 * j + g;
            uint32_t b0 = bB[t * BRW + col], b1 = bB[(t + 4) * BRW + col];
#pragma unroll
            for (int mb = 0; mb < 3; mb++) mma_bf16(acc[mb][j], a[mb], b0, b1);
        }
        __syncthreads();
    }
#pragma unroll
    for (int mb = 0; mb < 3; mb++) {
        int oc = og * 48 + mb * 16 + g;
#pragma unroll
        for (int j = 0; j < 8; j++) {
            int px = px0 + pg * 64 + 8 * j + 2 * t;
            float2 ra = *(const float2*)&res[((size_t)b * 96 + oc) * HW + px];
            float2 rb = *(const float2*)&res[((size_t)b * 96 + oc + 8) * HW + px];
            *(float2*)&out[((size_t)b * 96 + oc) * HW + px] =
                make_float2(acc[mb][j][0] + ra.x, acc[mb][j][1] + ra.y);
            *(float2*)&out[((size_t)b * 96 + oc + 8) * HW + px] =
                make_float2(acc[mb][j][2] + rb.x, acc[mb][j][3] + rb.y);
        }
    }
}

// ---------------- conv3x3 (R8 proven bf16 mma version) ----------------
__global__ __launch_bounds__(256) void conv3x3_bmma_kernel(const uint32_t* __restrict__ in,
                                                           uint32_t* __restrict__ qk,
                                                           uint32_t* __restrict__ vout,
                                                           float* __restrict__ sqk) {
    extern __shared__ uint32_t dynsmem[];
    uint32_t* bsm = dynsmem;
    uint32_t* wsm = dynsmem + 2 * BSM3;

    int b = blockIdx.z, ocT = blockIdx.y, y = blockIdx.x;
    int tid = threadIdx.x, warp = tid >> 5, lane = tid & 31;
    int og = warp >> 2, pg = warp & 3, g = lane >> 2, t = lane & 3;

    if (tid < 96) {
        int s = tid;
        int side = s & 1; s >>= 1;
        int wr = s % 24; int bufi = s / 24;
        bsm[bufi * BSM3 + wr * BROW3 + (side ? 260 : 3)] = 0u;
    }

    float acc[3][8][4];
#pragma unroll
    for (int mb = 0; mb < 3; mb++)
#pragma unroll
        for (int j = 0; j < 8; j++)
#pragma unroll
            for (int v = 0; v < 4; v++) acc[mb][j][v] = 0.f;

    const uint32_t* wp_base = g_Wp3 + (size_t)ocT * NCH3 * WCH3;

    auto issue = [&](int ch, int buf) {
        const uint32_t* ibase = in + ((size_t)b * (C3 / 2) + ch * 8) * HW;
        uint32_t* bdst = bsm + buf * BSM3;
#pragma unroll
        for (int k = 0; k < 6; k++) {
            int idx = tid + k * 256;
            int wr = idx >> 6, c4 = idx & 63;
            int w = wr / 3, rr = wr - 3 * w;
            int gy = y + rr - 1;
            bool ok = (unsigned)gy < 256u;
            const uint32_t* src = ibase + (size_t)w * HW + (ok ? gy : 0) * IMG + c4 * 4;
            cpa16z((uint32_t)__cvta_generic_to_shared(bdst + wr * BROW3 + 4 + c4 * 4), src, ok);
        }
        const uint32_t* wsrc = wp_base + (size_t)ch * WCH3;
        uint32_t* wdst = wsm + buf * WCH3;
#pragma unroll
        for (int k = 0; k < 7; k++) {
            int i = tid + k * 256;
            if (i < WCH3 / 4)
                cpa16((uint32_t)__cvta_generic_to_shared(wdst + i * 4), wsrc + i * 4);
        }
        asm volatile("cp.async.commit_group;");
    };

    issue(0, 0);
    for (int s = 0; s < NCH3; s++) {
        if (s + 1 < NCH3) { issue(s + 1, (s + 1) & 1); asm volatile("cp.async.wait_group 1;"); }
        else asm volatile("cp.async.wait_group 0;");
        __syncthreads();
        int buf = s & 1;
        const uint32_t* bB = bsm + buf * BSM3;
        const uint32_t* wc = wsm + buf * WCH3;
        int colb = 3 + pg * 64 + g;
#pragma unroll
        for (int ky = 0; ky < 3; ky++) {
#pragma unroll
            for (int kx = 0; kx < 3; kx++) {
                const uint32_t* wbp = wc + (((ky * 2 + og) * 3 + kx) * 3) * 128;
                uint32_t a[3][4];
#pragma unroll
                for (int mb = 0; mb < 3; mb++)
                    *(uint4*)a[mb] = *(const uint4*)&wbp[mb * 128 + lane * 4];
#pragma unroll
                for (int j = 0; j < 8; j++) {
                    int col = colb + 8 * j + kx;
                    uint32_t b0 = bB[(t * 3 + ky) * BROW3 + col];
                    uint32_t b1 = bB[((t + 4) * 3 + ky) * BROW3 + col];
#pragma unroll
                    for (int mb = 0; mb < 3; mb++) mma_bf16(acc[mb][j], a[mb], b0, b1);
                }
            }
        }
        __syncthreads();
    }

    if (ocT < 2) {
#pragma unroll
        for (int mb = 0; mb < 3; mb++) {
            float s0 = 0.f, s8 = 0.f;
#pragma unroll
            for (int j = 0; j < 8; j++) {
                s0 += acc[mb][j][0] * acc[mb][j][0] + acc[mb][j][1] * acc[mb][j][1];
                s8 += acc[mb][j][2] * acc[mb][j][2] + acc[mb][j][3] * acc[mb][j][3];
            }
            s0 += __shfl_xor_sync(0xffffffffu, s0, 1);
            s0 += __shfl_xor_sync(0xffffffffu, s0, 2);
            s8 += __shfl_xor_sync(0xffffffffu, s8, 1);
            s8 += __shfl_xor_sync(0xffffffffu, s8, 2);
            int oc = ocT * 96 + og * 48 + mb * 16 + g;
            if (t == 0) {
                atomicAdd(&sqk[b * 2 * DIM + oc], s0);
                atomicAdd(&sqk[b * 2 * DIM + oc + 8], s8);
            }
#pragma unroll
            for (int j = 0; j < 8; j++) {
                int px = pg * 64 + 8 * j + 2 * t;
                size_t base = (size_t)(b * 192 + oc) * (HW / 2) + ((y * IMG + px) >> 1);
                qk[base] = packbf(acc[mb][j][0], acc[mb][j][1]);
                qk[base + (size_t)8 * (HW / 2)] = packbf(acc[mb][j][2], acc[mb][j][3]);
            }
        }
    } else {
#pragma unroll
        for (int mb = 0; mb < 3; mb++) {
            int c2 = (og * 3 + mb) * 8 + g;
#pragma unroll
            for (int j = 0; j < 8; j++) {
                int px = pg * 64 + 8 * j + 2 * t;
                uint2 val = make_uint2(packbf(acc[mb][j][0], acc[mb][j][2]),
                                       packbf(acc[mb][j][1], acc[mb][j][3]));
                *(uint2*)&vout[((size_t)(b * 48 + c2)) * HW + y * IMG + px] = val;
            }
        }
    }
}

// ---------------- attention gram (R8, unchanged) ----------------
__global__ __launch_bounds__(256) void attn_bmma_kernel(const uint32_t* __restrict__ qk,
                                                        float* __restrict__ attn_raw) {
    int bh = blockIdx.y;
    int b = bh / HEADS, h = bh - b * HEADS;
    int warp = threadIdx.x >> 5, lane = threadIdx.x & 31;
    int tg = lane >> 2, t = lane & 3;
    const uint32_t* q0 = qk + (size_t)(b * 192 + h * HDIM + tg) * (HW / 2);
    const uint32_t* q1 = q0 + (size_t)8 * (HW / 2);
    const uint32_t* k0 = qk + (size_t)(b * 192 + 96 + h * HDIM + tg) * (HW / 2);
    const uint32_t* k1 = k0 + (size_t)8 * (HW / 2);
    float c0[4] = {0.f, 0.f, 0.f, 0.f};
    float c1[4] = {0.f, 0.f, 0.f, 0.f};
    int slab0 = (blockIdx.x * 8 + warp) * 32;
    for (int s = 0; s < 32; s++) {
        int w0 = (slab0 + s) * 32 + 4 * t;
        uint32_t qa[4], qb[4], qc[4], qd[4], ka[4], kc[4], kb[4], kd[4];
        *(uint4*)qa = *(const uint4*)(q0 + w0);
        *(uint4*)qb = *(const uint4*)(q1 + w0);
        *(uint4*)qc = *(const uint4*)(q0 + w0 + 16);
        *(uint4*)qd = *(const uint4*)(q1 + w0 + 16);
        *(uint4*)ka = *(const uint4*)(k0 + w0);
        *(uint4*)kc = *(const uint4*)(k0 + w0 + 16);
        *(uint4*)kb = *(const uint4*)(k1 + w0);
        *(uint4*)kd = *(const uint4*)(k1 + w0 + 16);
#pragma unroll
        for (int m = 0; m < 4; m++) {
            uint32_t a[4] = { qa[m], qb[m], qc[m], qd[m] };
            mma_bf16(c0, a, ka[m], kc[m]);
            mma_bf16(c1, a, kb[m], kd[m]);
        }
    }
    float* dst = attn_raw + bh * 256;
    atomicAdd(dst + tg * 16 + 2 * t, c0[0]);
    atomicAdd(dst + tg * 16 + 2 * t + 1, c0[1]);
    atomicAdd(dst + (tg + 8) * 16 + 2 * t, c0[2]);
    atomicAdd(dst + (tg + 8) * 16 + 2 * t + 1, c0[3]);
    atomicAdd(dst + tg * 16 + 8 + 2 * t, c1[0]);
    atomicAdd(dst + tg * 16 + 8 + 2 * t + 1, c1[1]);
    atomicAdd(dst + (tg + 8) * 16 + 8 + 2 * t, c1[2]);
    atomicAdd(dst + (tg + 8) * 16 + 8 + 2 * t + 1, c1[3]);
}

// ---------------- softmax + fused M (R8, unchanged) ----------------
__global__ __launch_bounds__(256) void softmax_build_M(const float* __restrict__ attn_raw,
                                                       const float* __restrict__ sqk,
                                                       const float* __restrict__ scale,
                                                       const float* __restrict__ proj_w,
                                                       uint32_t* __restrict__ Mp) {
    int b = blockIdx.x;
    int tdx = threadIdx.x;
    __shared__ float A[HEADS * 256];
    __shared__ float nq[DIM], nk[DIM];
    if (tdx < DIM) {
        nq[tdx] = fmaxf(sqrtf(sqk[b * 2 * DIM + tdx]), 1e-12f);
        nk[tdx] = fmaxf(sqrtf(sqk[b * 2 * DIM + DIM + tdx]), 1e-12f);
    }
    __syncthreads();
    for (int idx = tdx; idx < HEADS * 256; idx += 256) {
        int h = idx >> 8;
        int cd = idx & 255;
        int c = cd >> 4, d = cd & 15;
        A[idx] = attn_raw[b * HEADS * 256 + idx] /
                 (nq[h * HDIM + c] * nk[h * HDIM + d]) * scale[h];
    }
    __syncthreads();
    if (tdx < DIM) {
        int h = tdx >> 4, c = tdx & 15;
        float* row = &A[h * 256 + c * 16];
        float mx = row[0];
#pragma unroll
        for (int d = 1; d < 16; d++) mx = fmaxf(mx, row[d]);
        float sum = 0.f;
#pragma unroll
        for (int d = 0; d < 16; d++) { float e = expf(row[d] - mx); row[d] = e; sum += e; }
        float inv = 1.f / sum;
#pragma unroll
        for (int d = 0; d < 16; d++) row[d] *= inv;
    }
    __syncthreads();
    for (int idx = tdx; idx < DIM * DIM / 2; idx += 256) {
        int r = idx;
        int v = r & 3; r >>= 2;
        int lane = r & 31; r >>= 5;
        int mb = r % 3; r /= 3;
        int og = r % 2; r /= 2;
        int ch = r;
        int g = lane >> 2, t = lane & 3;
        int oc = og * 48 + mb * 16 + g + (v & 1) * 8;
        int d = t + (v >> 1) * 4;
        int h = ch;
        float s0 = 0.f, s1 = 0.f;
#pragma unroll
        for (int cg = 0; cg < 16; cg++) {
            float pw = proj_w[oc * DIM + h * HDIM + cg];
            s0 += pw * A[h * 256 + cg * 16 + d];
            s1 += pw * A[h * 256 + cg * 16 + d + 8];
        }
        Mp[b * (DIM * DIM / 2) + idx] = packbf(s0, s1);
    }
}

// ---------------- dwconv + gate v2: LDG-direct, 8 px/thread ----------------
__device__ __forceinline__ float gelu_tanh(float x) {
    float x3 = x * x * x;
    return 0.5f * x * (1.f + tanhf(0.7978845608028654f * (x + 0.044715f * x3)));
}

__global__ __launch_bounds__(256) void dwgate_kernel(const uint32_t* __restrict__ tin,
                                                     const float* __restrict__ dw,
                                                     uint32_t* __restrict__ gw) {
    int b = blockIdx.z, m = blockIdx.y;
    int y = blockIdx.x * 8 + (threadIdx.x >> 5);    // 32 y-blocks of 8 rows
    int px0 = (threadIdx.x & 31) * 8;
    int tid = threadIdx.x;

    __shared__ float swt[72];
    int chans[4] = {2 * m, 2 * m + 1, HID + 2 * m, HID + 2 * m + 1};
    if (tid < 72) {
        int oci = tid / 18;
        swt[tid] = dw[(size_t)chans[oci] * 18 + (tid - oci * 18)];
    }
    __syncthreads();

    float u[4][8];
#pragma unroll
    for (int ol = 0; ol < 4; ol++)
#pragma unroll
        for (int j = 0; j < 8; j++) u[ol][j] = 0.f;

    int wbase = px0 >> 1;                           // first word index - 1 applied below
#pragma unroll
    for (int ic = 0; ic < 4; ic++) {
        const uint32_t* chb = tin + ((size_t)(b * HID2 + chans[ic]) * HW) / 2;
        int olb = (ic >> 1) << 1;                   // 0 or 2
        int wi0 = (ic & 1) * 9;
#pragma unroll
        for (int ky = 0; ky < 3; ky++) {
            int gy = y + ky - 1;
            bool rok = (unsigned)gy < 256u;
            const uint32_t* rowp = chb + gy * 128;
            float v[12];
#pragma unroll
            for (int w = 0; w < 6; w++) {
                int wi = wbase - 1 + w;
                uint32_t word = (rok && (unsigned)wi < 128u) ? __ldg(rowp + wi) : 0u;
                __nv_bfloat162 bb = *reinterpret_cast<__nv_bfloat162*>(&word);
                v[2 * w] = __bfloat162float(bb.x);
                v[2 * w + 1] = __bfloat162float(bb.y);
            }
#pragma unroll
            for (int kx = 0; kx < 3; kx++) {
                float w0 = swt[olb * 18 + wi0 + ky * 3 + kx];
                float w1 = swt[(olb + 1) * 18 + wi0 + ky * 3 + kx];
#pragma unroll
                for (int j = 0; j < 8; j++) {
                    float xv = v[j + kx + 1];
                    u[olb][j] += w0 * xv;
                    u[olb + 1][j] += w1 * xv;
                }
            }
        }
    }

    uint32_t outw[8];
#pragma unroll
    for (int j = 0; j < 8; j++)
        outw[j] = packbf(gelu_tanh(u[0][j]) * u[2][j], gelu_tanh(u[1][j]) * u[3][j]);
    uint32_t* dst = gw + ((size_t)b * 96 + m) * HW + y * IMG + px0;
    *(uint4*)dst = *(uint4*)&outw[0];
    *(uint4*)(dst + 4) = *(uint4*)&outw[4];
}

// ---------------- launch ----------------
static void* sym_addr(const void* sym) {
    void* p = nullptr;
    cudaGetSymbolAddress(&p, sym);
    return p;
}

extern "C" void kernel_launch(void* const* d_in, const int* in_sizes, int n_in,
                              void* d_out, int out_size) {
    const float* x      = (const float*)d_in[0];
    const float* ln1_w  = (const float*)d_in[1];
    const float* ln1_b  = (const float*)d_in[2];
    const float* qkv1_w = (const float*)d_in[3];
    const float* qkv2_w = (const float*)d_in[4];
    const float* proj_w = (const float*)d_in[5];
    const float* scale  = (const float*)d_in[6];
    const float* ln2_w  = (const float*)d_in[7];
    const float* ln2_b  = (const float*)d_in[8];
    const float* pin_w  = (const float*)d_in[9];
    const float* dw_w   = (const float*)d_in[10];
    const float* pout_w = (const float*)d_in[11];

    uint32_t* qkvh = (uint32_t*)sym_addr(g_qkvh);
    uint32_t* qkpp = (uint32_t*)sym_addr(g_qkpp);
    uint32_t* vcp  = (uint32_t*)sym_addr(g_vcp);
    uint32_t* tbuf = (uint32_t*)sym_addr(g_t);
    uint32_t* gw   = (uint32_t*)sym_addr(g_gw);
    float* x2   = (float*)sym_addr(g_x2);
    float* mu   = (float*)sym_addr(g_mu);
    float* rstd = (float*)sym_addr(g_rstd);
    float* wgs1 = (float*)sym_addr(g_wgs1);
    float* wb1  = (float*)sym_addr(g_wb1);
    float* wgs2 = (float*)sym_addr(g_wgs2);
    float* wb2  = (float*)sym_addr(g_wb2);
    float* sqk  = (float*)sym_addr(g_sqk);
    float* attn = (float*)sym_addr(g_attn);
    uint32_t* Wp1 = (uint32_t*)sym_addr(g_Wp1);
    uint32_t* Wp2 = (uint32_t*)sym_addr(g_Wp2);
    uint32_t* Wpo = (uint32_t*)sym_addr(g_Wpo);
    uint32_t* Mp  = (uint32_t*)sym_addr(g_Mp);
    float* out = (float*)d_out;

    static bool attr_done = false;
    if (!attr_done) {
        cudaFuncSetAttribute(conv3x3_bmma_kernel,
                             cudaFuncAttributeMaxDynamicSharedMemorySize, SMEM3);
        attr_done = true;
    }

    prep_kernel<<<3, 256>>>(qkv1_w, ln1_w, ln1_b, pin_w, ln2_w, ln2_b);
    pack1x1_kernel<true><<<(C3 * DIM / 2 + 255) / 256, 256>>>(qkv1_w, ln1_w, Wp1, C3, DIM);
    pack1x1_kernel<true><<<(HID2 * DIM / 2 + 255) / 256, 256>>>(pin_w, ln2_w, Wp2, HID2, DIM);
    pack1x1_kernel<false><<<(DIM * HID / 2 + 255) / 256, 256>>>(pout_w, nullptr, Wpo, DIM, HID);
    pack3x3_kernel<<<(WP3SZ + 255) / 256, 256>>>(qkv2_w);
    zero_kernel<<<24, 256>>>(attn, BATCH * HEADS * 256);
    zero_kernel<<<3, 256>>>(sqk, BATCH * 2 * DIM);

    ln_stats_kernel<<<BATCH * HW / 4 / 256, 256>>>(x, mu, rstd);
    conv1x1_bmma_kernel<DIM, 1><<<dim3(256, 3, BATCH), 256>>>(
        x, Wp1, wgs1, wb1, mu, rstd, qkvh);

    conv3x3_bmma_kernel<<<dim3(256, 3, BATCH), 256, SMEM3>>>(qkvh, qkpp, vcp, sqk);

    attn_bmma_kernel<<<dim3(4, BATCH * HEADS), 256>>>(qkpp, attn);
    softmax_build_M<<<BATCH, 256>>>(attn, sqk, scale, proj_w, Mp);

    conv1x1u_bmma_kernel<48><<<dim3(256, 1, BATCH), 256>>>(
        vcp, 48 * HW, Mp, DIM * DIM / 2, x, x2);

    ln_stats_kernel<<<BATCH * HW / 4 / 256, 256>>>(x2, mu, rstd);
    conv1x1_bmma_kernel<DIM, 2><<<dim3(256, 4, BATCH), 256>>>(
        x2, Wp2, wgs2, wb2, mu, rstd, tbuf);

    dwgate_kernel<<<dim3(32, DIM, BATCH), 256>>>(tbuf, dw_w, gw);

    conv1x1u_bmma_kernel<96><<<dim3(256, 1, BATCH), 256>>>(
        gw, 96 * HW, Wpo, 0, x2, out);
}

// round 12
// speedup vs baseline: 10.3105x; 1.0307x over previous
#include <cuda_runtime.h>
#include <cuda_bf16.h>
#include <cmath>
#include <cstdint>

#define BATCH 4
#define DIM   96
#define HEADS 6
#define HDIM  16
#define C3    288
#define HID   192
#define HID2  384
#define HW    65536
#define IMG   256

// conv3x3 bf16 mma tiling: chunk = 16 ic (= 8 u32 pair-words)
#define NCH3   18
#define BROW3  280
#define BSM3   (8 * 3 * BROW3)
#define WCH3   6912
#define WP3SZ  (3 * NCH3 * WCH3)
#define SMEM3  ((2 * BSM3 + 2 * WCH3) * 4)   // 109056 bytes

#define BRW    264

// ---------------- scratch ----------------
__device__ __align__(16) uint32_t g_xh   [(size_t)BATCH * 48 * HW];        // x bf16 ch-pair
__device__ __align__(16) uint32_t g_x2h  [(size_t)BATCH * 48 * HW];        // x2 bf16 ch-pair
__device__ __align__(16) uint32_t g_qkvh [(size_t)BATCH * (C3 / 2) * HW];  // qkv1 out, ch-pair
__device__ __align__(16) uint32_t g_qkpp [(size_t)BATCH * 192 * (HW / 2)]; // q,k px-pair
__device__ __align__(16) uint32_t g_vcp  [(size_t)BATCH * 48 * HW];        // v ch-pair
__device__ __align__(16) uint32_t g_t    [(size_t)BATCH * HID2 * HW / 2];  // pin out, px-pair
__device__ __align__(16) uint32_t g_gw   [(size_t)BATCH * 96 * HW];        // dwgate out, px... ch-consecutive pair
__device__ float g_x2   [(size_t)BATCH * DIM * HW];
__device__ float g_wgs1 [C3];
__device__ float g_wb1  [C3];
__device__ float g_wgs2 [HID2];
__device__ float g_wb2  [HID2];
__device__ float g_sqk  [BATCH * 2 * DIM];
__device__ float g_attn [BATCH * HEADS * HDIM * HDIM];
__device__ __align__(16) uint32_t g_Wp1 [C3 * DIM / 2];
__device__ __align__(16) uint32_t g_Wp2 [HID2 * DIM / 2];
__device__ __align__(16) uint32_t g_Wpo [DIM * HID / 2];
__device__ __align__(16) uint32_t g_Mp  [BATCH * DIM * DIM / 2];
__device__ __align__(16) uint32_t g_Wp3 [WP3SZ];

// ---------------- helpers ----------------
__device__ __forceinline__ void cpa16(uint32_t dst, const void* src) {
    asm volatile("cp.async.cg.shared.global [%0], [%1], 16;" :: "r"(dst), "l"(src));
}
__device__ __forceinline__ void cpa16z(uint32_t dst, const void* src, bool v) {
    asm volatile("cp.async.cg.shared.global [%0], [%1], 16, %2;"
                 :: "r"(dst), "l"(src), "r"(v ? 16u : 0u));
}
__device__ __forceinline__ uint32_t packbf(float lo, float hi) {
    uint32_t r;
    asm("cvt.rn.bf16x2.f32 %0, %1, %2;" : "=r"(r) : "f"(hi), "f"(lo));
    return r;
}
__device__ __forceinline__ void mma_bf16(float* c, const uint32_t* a,
                                         uint32_t b0, uint32_t b1) {
    asm volatile("mma.sync.aligned.m16n8k16.row.col.f32.bf16.bf16.f32 "
                 "{%0,%1,%2,%3}, {%4,%5,%6,%7}, {%8,%9}, {%0,%1,%2,%3};"
                 : "+f"(c[0]), "+f"(c[1]), "+f"(c[2]), "+f"(c[3])
                 : "r"(a[0]), "r"(a[1]), "r"(a[2]), "r"(a[3]), "r"(b0), "r"(b1));
}

// ---------------- prep ----------------
__global__ void prep_kernel(const float* __restrict__ qkv1_w, const float* __restrict__ ln1_w,
                            const float* __restrict__ ln1_b, const float* __restrict__ pin_w,
                            const float* __restrict__ ln2_w, const float* __restrict__ ln2_b) {
    int t = blockIdx.x * 256 + threadIdx.x;
    if (t < C3) {
        float s = 0.f, sb = 0.f;
        for (int c = 0; c < DIM; c++) {
            float w = qkv1_w[t * DIM + c];
            s += w * ln1_w[c]; sb += w * ln1_b[c];
        }
        g_wgs1[t] = s; g_wb1[t] = sb;
    } else if (t < C3 + HID2) {
        int r = t - C3;
        float s = 0.f, sb = 0.f;
        for (int c = 0; c < DIM; c++) {
            float w = pin_w[r * DIM + c];
            s += w * ln2_w[c]; sb += w * ln2_b[c];
        }
        g_wgs2[r] = s; g_wb2[r] = sb;
    }
}

// consecutive-pair pack (for pout over gw's (2m,2m+1) words)
template <bool FOLD>
__global__ void pack1x1_kernel(const float* __restrict__ W, const float* __restrict__ gamma,
                               uint32_t* __restrict__ dst, int OC, int ICt) {
    int idx = blockIdx.x * 256 + threadIdx.x;
    if (idx >= OC * ICt / 2) return;
    int r = idx;
    int v = r & 3; r >>= 2;
    int lane = r & 31; r >>= 5;
    int mb = r % 3; r /= 3;
    int og = r % 2; r /= 2;
    int nch = ICt / 16;
    int ch = r % nch; r /= nch;
    int ocT = r;
    int g = lane >> 2, t = lane & 3;
    int oc = ocT * 96 + og * 48 + mb * 16 + g + (v & 1) * 8;
    int ic = ch * 16 + 2 * t + (v >> 1) * 8;
    float w0 = W[oc * ICt + ic], w1 = W[oc * ICt + ic + 1];
    if (FOLD) { w0 *= gamma[ic]; w1 *= gamma[ic + 1]; }
    dst[idx] = packbf(w0, w1);
}

// (ic, ic+8)-pair pack + gamma fold (for ch-pair word activations)
__global__ void pack1x1p_kernel(const float* __restrict__ W, const float* __restrict__ gamma,
                                uint32_t* __restrict__ dst, int OC, int ICt) {
    int idx = blockIdx.x * 256 + threadIdx.x;
    if (idx >= OC * ICt / 2) return;
    int r = idx;
    int v = r & 3; r >>= 2;
    int lane = r & 31; r >>= 5;
    int mb = r % 3; r /= 3;
    int og = r % 2; r /= 2;
    int nch = ICt / 16;
    int ch = r % nch; r /= nch;
    int ocT = r;
    int g = lane >> 2, t = lane & 3;
    int oc = ocT * 96 + og * 48 + mb * 16 + g + (v & 1) * 8;
    int ic0 = ch * 16 + t + (v >> 1) * 4;
    float w0 = W[oc * ICt + ic0] * gamma[ic0];
    float w1 = W[oc * ICt + ic0 + 8] * gamma[ic0 + 8];
    dst[idx] = packbf(w0, w1);
}

__global__ void pack3x3_kernel(const float* __restrict__ W) {
    int idx = blockIdx.x * 256 + threadIdx.x;
    if (idx >= WP3SZ) return;
    int r = idx;
    int v = r & 3; r >>= 2;
    int lane = r & 31; r >>= 5;
    int mb = r % 3; r /= 3;
    int kx = r % 3; r /= 3;
    int og = r % 2; r /= 2;
    int ky = r % 3; r /= 3;
    int ch = r % NCH3; r /= NCH3;
    int ocT = r;
    int g = lane >> 2, t = lane & 3;
    int oc = ocT * 96 + og * 48 + mb * 16 + g + (v & 1) * 8;
    int ic0 = ch * 16 + t + (v >> 1) * 4;
    float w0 = W[(oc * C3 + ic0) * 9 + ky * 3 + kx];
    float w1 = W[(oc * C3 + ic0 + 8) * 9 + ky * 3 + kx];
    g_Wp3[idx] = packbf(w0, w1);
}

__global__ void zero_kernel(float* __restrict__ p, int n) {
    int i = blockIdx.x * 256 + threadIdx.x;
    if (i < n) p[i] = 0.f;
}

// ---------------- x -> bf16 ch-pair convert ----------------
__global__ __launch_bounds__(256) void cvt_x_kernel(const float* __restrict__ x,
                                                    uint32_t* __restrict__ xh) {
    // one thread = one word-index (b, w, px4): 4 px
    int idx = blockIdx.x * 256 + threadIdx.x;       // 0 .. BATCH*48*HW/4-1
    int b = idx / (48 * HW / 4);
    int rem = idx - b * (48 * HW / 4);
    int w = rem / (HW / 4);
    int p = (rem - w * (HW / 4)) * 4;
    int clo = (w >> 3) * 16 + (w & 7);
    const float* lo = x + ((size_t)b * DIM + clo) * HW + p;
    const float* hi = lo + (size_t)8 * HW;
    float4 l4 = *(const float4*)lo;
    float4 h4 = *(const float4*)hi;
    uint4 o;
    o.x = packbf(l4.x, h4.x); o.y = packbf(l4.y, h4.y);
    o.z = packbf(l4.z, h4.z); o.w = packbf(l4.w, h4.w);
    *(uint4*)&xh[((size_t)b * 48 + w) * HW + p] = o;
}

// ---------------- 1x1 conv, u32 ch-pair in, fused LN stats ----------------
// ICW = input words (48 => 96 ch). OMODE: 1 = ch-pair out; 2 = px-pair out.
template <int ICW, int OMODE>
__global__ __launch_bounds__(256) void conv1x1uln_kernel(
    const uint32_t* __restrict__ in,
    const uint32_t* __restrict__ Wp,
    const float* __restrict__ wgs, const float* __restrict__ wb,
    uint32_t* __restrict__ outv) {
    constexpr int NCH = ICW / 8;
    __shared__ __align__(16) uint32_t bsmw[2][8 * BRW];
    __shared__ __align__(16) uint32_t wsm[2][768];
    __shared__ float smu[256], srstd[256];

    int b = blockIdx.z, ocT = blockIdx.y, px0 = blockIdx.x * 256;
    int OCtot = gridDim.y * 96;
    int tid = threadIdx.x, warp = tid >> 5, lane = tid & 31;
    int og = warp >> 2, pg = warp & 3, g = lane >> 2, t = lane & 3;

    float acc[3][8][4];
#pragma unroll
    for (int mb = 0; mb < 3; mb++)
#pragma unroll
        for (int j = 0; j < 8; j++)
#pragma unroll
            for (int v = 0; v < 4; v++) acc[mb][j][v] = 0.f;

    float psum = 0.f, psq = 0.f;

    const uint32_t* Wb = Wp + (size_t)ocT * NCH * 768;
    auto issue = [&](int ch, int buf) {
#pragma unroll
        for (int k = 0; k < 2; k++) {
            int idx = tid + k * 256;
            int row = idx >> 6, c4 = idx & 63;
            const uint32_t* src = in + ((size_t)b * ICW + ch * 8 + row) * HW + px0 + c4 * 4;
            cpa16((uint32_t)__cvta_generic_to_shared(&bsmw[buf][row * BRW + c4 * 4]), src);
        }
        if (tid < 192)
            cpa16((uint32_t)__cvta_generic_to_shared(&wsm[buf][tid * 4]), Wb + ch * 768 + tid * 4);
        asm volatile("cp.async.commit_group;");
    };
    issue(0, 0);
    for (int s = 0; s < NCH; s++) {
        if (s + 1 < NCH) { issue(s + 1, (s + 1) & 1); asm volatile("cp.async.wait_group 1;"); }
        else asm volatile("cp.async.wait_group 0;");
        __syncthreads();
        int buf = s & 1;
        const uint32_t* bB = &bsmw[buf][0];
        // LN stats: this thread's pixel = tid
#pragma unroll
        for (int w = 0; w < 8; w++) {
            uint32_t word = bB[w * BRW + tid];
            __nv_bfloat162 bb = *reinterpret_cast<__nv_bfloat162*>(&word);
            float a0 = __bfloat162float(bb.x), a1 = __bfloat162float(bb.y);
            psum += a0 + a1; psq += a0 * a0 + a1 * a1;
        }
        const uint32_t* wc = &wsm[buf][og * 384];
        uint32_t a[3][4];
#pragma unroll
        for (int mb = 0; mb < 3; mb++) *(uint4*)a[mb] = *(const uint4*)&wc[mb * 128 + lane * 4];
#pragma unroll
        for (int j = 0; j < 8; j++) {
            int col = pg * 64 + 8 * j + g;
            uint32_t b0 = bB[t * BRW + col], b1 = bB[(t + 4) * BRW + col];
#pragma unroll
            for (int mb = 0; mb < 3; mb++) mma_bf16(acc[mb][j], a[mb], b0, b1);
        }
        __syncthreads();
    }

    {
        float mu = psum * (1.f / DIM);
        float var = psq * (1.f / DIM) - mu * mu;
        smu[tid] = mu;
        srstd[tid] = rsqrtf(var + 1e-5f);
    }
    __syncthreads();

#pragma unroll
    for (int mb = 0; mb < 3; mb++) {
        int oc = ocT * 96 + og * 48 + mb * 16 + g;
        float gs0 = wgs[oc], gs8 = wgs[oc + 8], bb0 = wb[oc], bb8 = wb[oc + 8];
#pragma unroll
        for (int j = 0; j < 8; j++) {
            int pl = pg * 64 + 8 * j + 2 * t;
            int px = px0 + pl;
            float m0 = smu[pl], m1 = smu[pl + 1], r0 = srstd[pl], r1 = srstd[pl + 1];
            float v00 = r0 * (acc[mb][j][0] - m0 * gs0) + bb0;
            float v01 = r1 * (acc[mb][j][1] - m1 * gs0) + bb0;
            float v10 = r0 * (acc[mb][j][2] - m0 * gs8) + bb8;
            float v11 = r1 * (acc[mb][j][3] - m1 * gs8) + bb8;
            if (OMODE == 1) {
                int ch = ocT * 6 + og * 3 + mb;
                int c2 = ch * 8 + g;
                uint2 val = make_uint2(packbf(v00, v10), packbf(v01, v11));
                *(uint2*)&outv[((size_t)b * (OCtot / 2) + c2) * HW + px] = val;
            } else {
                outv[(((size_t)b * OCtot + oc) * HW + px) >> 1] = packbf(v00, v01);
                outv[(((size_t)b * OCtot + oc + 8) * HW + px) >> 1] = packbf(v10, v11);
            }
        }
    }
}

// ---------------- 1x1 conv, u32 pair-word in, fp32 out + residual ----------------
// WH: additionally write bf16 ch-pair copy of output (x2h)
template <int ICW, bool WH>
__global__ __launch_bounds__(256) void conv1x1u_bmma_kernel(
    const uint32_t* __restrict__ in, int in_bstride,
    const uint32_t* __restrict__ Wp, int w_bstride,
    const float* __restrict__ res, float* __restrict__ out,
    uint32_t* __restrict__ outh) {
    constexpr int NCH = ICW / 8;
    __shared__ __align__(16) uint32_t bsmw[2][8 * BRW];
    __shared__ __align__(16) uint32_t wsm[2][768];
    int b = blockIdx.z, px0 = blockIdx.x * 256;
    int tid = threadIdx.x, warp = tid >> 5, lane = tid & 31;
    int og = warp >> 2, pg = warp & 3, g = lane >> 2, t = lane & 3;
    float acc[3][8][4];
#pragma unroll
    for (int mb = 0; mb < 3; mb++)
#pragma unroll
        for (int j = 0; j < 8; j++)
#pragma unroll
            for (int v = 0; v < 4; v++) acc[mb][j][v] = 0.f;
    const uint32_t* Wb = Wp + (size_t)b * w_bstride;
    auto issue = [&](int ch, int buf) {
#pragma unroll
        for (int k = 0; k < 2; k++) {
            int idx = tid + k * 256;
            int row = idx >> 6, c4 = idx & 63;
            const uint32_t* src = in + (size_t)b * in_bstride + (size_t)(ch * 8 + row) * HW + px0 + c4 * 4;
            cpa16((uint32_t)__cvta_generic_to_shared(&bsmw[buf][row * BRW + c4 * 4]), src);
        }
        if (tid < 192)
            cpa16((uint32_t)__cvta_generic_to_shared(&wsm[buf][tid * 4]), Wb + ch * 768 + tid * 4);
        asm volatile("cp.async.commit_group;");
    };
    issue(0, 0);
    for (int s = 0; s < NCH; s++) {
        if (s + 1 < NCH) { issue(s + 1, (s + 1) & 1); asm volatile("cp.async.wait_group 1;"); }
        else asm volatile("cp.async.wait_group 0;");
        __syncthreads();
        int buf = s & 1;
        const uint32_t* wc = &wsm[buf][og * 384];
        uint32_t a[3][4];
#pragma unroll
        for (int mb = 0; mb < 3; mb++) *(uint4*)a[mb] = *(const uint4*)&wc[mb * 128 + lane * 4];
        const uint32_t* bB = &bsmw[buf][0];
#pragma unroll
        for (int j = 0; j < 8; j++) {
            int col = pg * 64 + 8 * j + g;
            uint32_t b0 = bB[t * BRW + col], b1 = bB[(t + 4) * BRW + col];
#pragma unroll
            for (int mb = 0; mb < 3; mb++) mma_bf16(acc[mb][j], a[mb], b0, b1);
        }
        __syncthreads();
    }
#pragma unroll
    for (int mb = 0; mb < 3; mb++) {
        int oc = og * 48 + mb * 16 + g;
#pragma unroll
        for (int j = 0; j < 8; j++) {
            int px = px0 + pg * 64 + 8 * j + 2 * t;
            float2 ra = *(const float2*)&res[((size_t)b * 96 + oc) * HW + px];
            float2 rb = *(const float2*)&res[((size_t)b * 96 + oc + 8) * HW + px];
            float v00 = acc[mb][j][0] + ra.x, v01 = acc[mb][j][1] + ra.y;
            float v10 = acc[mb][j][2] + rb.x, v11 = acc[mb][j][3] + rb.y;
            *(float2*)&out[((size_t)b * 96 + oc) * HW + px] = make_float2(v00, v01);
            *(float2*)&out[((size_t)b * 96 + oc + 8) * HW + px] = make_float2(v10, v11);
            if (WH) {
                int w = (og * 3 + mb) * 8 + g;
                uint2 val = make_uint2(packbf(v00, v10), packbf(v01, v11));
                *(uint2*)&outh[((size_t)b * 48 + w) * HW + px] = val;
            }
        }
    }
}

// ---------------- conv3x3 (proven bf16 mma) ----------------
__global__ __launch_bounds__(256) void conv3x3_bmma_kernel(const uint32_t* __restrict__ in,
                                                           uint32_t* __restrict__ qk,
                                                           uint32_t* __restrict__ vout,
                                                           float* __restrict__ sqk) {
    extern __shared__ uint32_t dynsmem[];
    uint32_t* bsm = dynsmem;
    uint32_t* wsm = dynsmem + 2 * BSM3;

    int b = blockIdx.z, ocT = blockIdx.y, y = blockIdx.x;
    int tid = threadIdx.x, warp = tid >> 5, lane = tid & 31;
    int og = warp >> 2, pg = warp & 3, g = lane >> 2, t = lane & 3;

    if (tid < 96) {
        int s = tid;
        int side = s & 1; s >>= 1;
        int wr = s % 24; int bufi = s / 24;
        bsm[bufi * BSM3 + wr * BROW3 + (side ? 260 : 3)] = 0u;
    }

    float acc[3][8][4];
#pragma unroll
    for (int mb = 0; mb < 3; mb++)
#pragma unroll
        for (int j = 0; j < 8; j++)
#pragma unroll
            for (int v = 0; v < 4; v++) acc[mb][j][v] = 0.f;

    const uint32_t* wp_base = g_Wp3 + (size_t)ocT * NCH3 * WCH3;

    auto issue = [&](int ch, int buf) {
        const uint32_t* ibase = in + ((size_t)b * (C3 / 2) + ch * 8) * HW;
        uint32_t* bdst = bsm + buf * BSM3;
#pragma unroll
        for (int k = 0; k < 6; k++) {
            int idx = tid + k * 256;
            int wr = idx >> 6, c4 = idx & 63;
            int w = wr / 3, rr = wr - 3 * w;
            int gy = y + rr - 1;
            bool ok = (unsigned)gy < 256u;
            const uint32_t* src = ibase + (size_t)w * HW + (ok ? gy : 0) * IMG + c4 * 4;
            cpa16z((uint32_t)__cvta_generic_to_shared(bdst + wr * BROW3 + 4 + c4 * 4), src, ok);
        }
        const uint32_t* wsrc = wp_base + (size_t)ch * WCH3;
        uint32_t* wdst = wsm + buf * WCH3;
#pragma unroll
        for (int k = 0; k < 7; k++) {
            int i = tid + k * 256;
            if (i < WCH3 / 4)
                cpa16((uint32_t)__cvta_generic_to_shared(wdst + i * 4), wsrc + i * 4);
        }
        asm volatile("cp.async.commit_group;");
    };

    issue(0, 0);
    for (int s = 0; s < NCH3; s++) {
        if (s + 1 < NCH3) { issue(s + 1, (s + 1) & 1); asm volatile("cp.async.wait_group 1;"); }
        else asm volatile("cp.async.wait_group 0;");
        __syncthreads();
        int buf = s & 1;
        const uint32_t* bB = bsm + buf * BSM3;
        const uint32_t* wc = wsm + buf * WCH3;
        int colb = 3 + pg * 64 + g;
#pragma unroll
        for (int ky = 0; ky < 3; ky++) {
#pragma unroll
            for (int kx = 0; kx < 3; kx++) {
                const uint32_t* wbp = wc + (((ky * 2 + og) * 3 + kx) * 3) * 128;
                uint32_t a[3][4];
#pragma unroll
                for (int mb = 0; mb < 3; mb++)
                    *(uint4*)a[mb] = *(const uint4*)&wbp[mb * 128 + lane * 4];
#pragma unroll
                for (int j = 0; j < 8; j++) {
                    int col = colb + 8 * j + kx;
                    uint32_t b0 = bB[(t * 3 + ky) * BROW3 + col];
                    uint32_t b1 = bB[((t + 4) * 3 + ky) * BROW3 + col];
#pragma unroll
                    for (int mb = 0; mb < 3; mb++) mma_bf16(acc[mb][j], a[mb], b0, b1);
                }
            }
        }
        __syncthreads();
    }

    if (ocT < 2) {
#pragma unroll
        for (int mb = 0; mb < 3; mb++) {
            float s0 = 0.f, s8 = 0.f;
#pragma unroll
            for (int j = 0; j < 8; j++) {
                s0 += acc[mb][j][0] * acc[mb][j][0] + acc[mb][j][1] * acc[mb][j][1];
                s8 += acc[mb][j][2] * acc[mb][j][2] + acc[mb][j][3] * acc[mb][j][3];
            }
            s0 += __shfl_xor_sync(0xffffffffu, s0, 1);
            s0 += __shfl_xor_sync(0xffffffffu, s0, 2);
            s8 += __shfl_xor_sync(0xffffffffu, s8, 1);
            s8 += __shfl_xor_sync(0xffffffffu, s8, 2);
            int oc = ocT * 96 + og * 48 + mb * 16 + g;
            if (t == 0) {
                atomicAdd(&sqk[b * 2 * DIM + oc], s0);
                atomicAdd(&sqk[b * 2 * DIM + oc + 8], s8);
            }
#pragma unroll
            for (int j = 0; j < 8; j++) {
                int px = pg * 64 + 8 * j + 2 * t;
                size_t base = (size_t)(b * 192 + oc) * (HW / 2) + ((y * IMG + px) >> 1);
                qk[base] = packbf(acc[mb][j][0], acc[mb][j][1]);
                qk[base + (size_t)8 * (HW / 2)] = packbf(acc[mb][j][2], acc[mb][j][3]);
            }
        }
    } else {
#pragma unroll
        for (int mb = 0; mb < 3; mb++) {
            int c2 = (og * 3 + mb) * 8 + g;
#pragma unroll
            for (int j = 0; j < 8; j++) {
                int px = pg * 64 + 8 * j + 2 * t;
                uint2 val = make_uint2(packbf(acc[mb][j][0], acc[mb][j][2]),
                                       packbf(acc[mb][j][1], acc[mb][j][3]));
                *(uint2*)&vout[((size_t)(b * 48 + c2)) * HW + y * IMG + px] = val;
            }
        }
    }
}

// ---------------- attention gram ----------------
__global__ __launch_bounds__(256) void attn_bmma_kernel(const uint32_t* __restrict__ qk,
                                                        float* __restrict__ attn_raw) {
    int bh = blockIdx.y;
    int b = bh / HEADS, h = bh - b * HEADS;
    int warp = threadIdx.x >> 5, lane = threadIdx.x & 31;
    int tg = lane >> 2, t = lane & 3;
    const uint32_t* q0 = qk + (size_t)(b * 192 + h * HDIM + tg) * (HW / 2);
    const uint32_t* q1 = q0 + (size_t)8 * (HW / 2);
    const uint32_t* k0 = qk + (size_t)(b * 192 + 96 + h * HDIM + tg) * (HW / 2);
    const uint32_t* k1 = k0 + (size_t)8 * (HW / 2);
    float c0[4] = {0.f, 0.f, 0.f, 0.f};
    float c1[4] = {0.f, 0.f, 0.f, 0.f};
    int slab0 = (blockIdx.x * 8 + warp) * 32;
    for (int s = 0; s < 32; s++) {
        int w0 = (slab0 + s) * 32 + 4 * t;
        uint32_t qa[4], qb[4], qc[4], qd[4], ka[4], kc[4], kb[4], kd[4];
        *(uint4*)qa = *(const uint4*)(q0 + w0);
        *(uint4*)qb = *(const uint4*)(q1 + w0);
        *(uint4*)qc = *(const uint4*)(q0 + w0 + 16);
        *(uint4*)qd = *(const uint4*)(q1 + w0 + 16);
        *(uint4*)ka = *(const uint4*)(k0 + w0);
        *(uint4*)kc = *(const uint4*)(k0 + w0 + 16);
        *(uint4*)kb = *(const uint4*)(k1 + w0);
        *(uint4*)kd = *(const uint4*)(k1 + w0 + 16);
#pragma unroll
        for (int m = 0; m < 4; m++) {
            uint32_t a[4] = { qa[m], qb[m], qc[m], qd[m] };
            mma_bf16(c0, a, ka[m], kc[m]);
            mma_bf16(c1, a, kb[m], kd[m]);
        }
    }
    float* dst = attn_raw + bh * 256;
    atomicAdd(dst + tg * 16 + 2 * t, c0[0]);
    atomicAdd(dst + tg * 16 + 2 * t + 1, c0[1]);
    atomicAdd(dst + (tg + 8) * 16 + 2 * t, c0[2]);
    atomicAdd(dst + (tg + 8) * 16 + 2 * t + 1, c0[3]);
    atomicAdd(dst + tg * 16 + 8 + 2 * t, c1[0]);
    atomicAdd(dst + tg * 16 + 8 + 2 * t + 1, c1[1]);
    atomicAdd(dst + (tg + 8) * 16 + 8 + 2 * t, c1[2]);
    atomicAdd(dst + (tg + 8) * 16 + 8 + 2 * t + 1, c1[3]);
}

// ---------------- softmax + fused M (packed bf16, (d, d+8) pairing) ----------------
__global__ __launch_bounds__(256) void softmax_build_M(const float* __restrict__ attn_raw,
                                                       const float* __restrict__ sqk,
                                                       const float* __restrict__ scale,
                                                       const float* __restrict__ proj_w,
                                                       uint32_t* __restrict__ Mp) {
    int b = blockIdx.x;
    int tdx = threadIdx.x;
    __shared__ float A[HEADS * 256];
    __shared__ float nq[DIM], nk[DIM];
    if (tdx < DIM) {
        nq[tdx] = fmaxf(sqrtf(sqk[b * 2 * DIM + tdx]), 1e-12f);
        nk[tdx] = fmaxf(sqrtf(sqk[b * 2 * DIM + DIM + tdx]), 1e-12f);
    }
    __syncthreads();
    for (int idx = tdx; idx < HEADS * 256; idx += 256) {
        int h = idx >> 8;
        int cd = idx & 255;
        int c = cd >> 4, d = cd & 15;
        A[idx] = attn_raw[b * HEADS * 256 + idx] /
                 (nq[h * HDIM + c] * nk[h * HDIM + d]) * scale[h];
    }
    __syncthreads();
    if (tdx < DIM) {
        int h = tdx >> 4, c = tdx & 15;
        float* row = &A[h * 256 + c * 16];
        float mx = row[0];
#pragma unroll
        for (int d = 1; d < 16; d++) mx = fmaxf(mx, row[d]);
        float sum = 0.f;
#pragma unroll
        for (int d = 0; d < 16; d++) { float e = expf(row[d] - mx); row[d] = e; sum += e; }
        float inv = 1.f / sum;
#pragma unroll
        for (int d = 0; d < 16; d++) row[d] *= inv;
    }
    __syncthreads();
    for (int idx = tdx; idx < DIM * DIM / 2; idx += 256) {
        int r = idx;
        int v = r & 3; r >>= 2;
        int lane = r & 31; r >>= 5;
        int mb = r % 3; r /= 3;
        int og = r % 2; r /= 2;
        int ch = r;
        int g = lane >> 2, t = lane & 3;
        int oc = og * 48 + mb * 16 + g + (v & 1) * 8;
        int d = t + (v >> 1) * 4;
        int h = ch;
        float s0 = 0.f, s1 = 0.f;
#pragma unroll
        for (int cg = 0; cg < 16; cg++) {
            float pw = proj_w[oc * DIM + h * HDIM + cg];
            s0 += pw * A[h * 256 + cg * 16 + d];
            s1 += pw * A[h * 256 + cg * 16 + d + 8];
        }
        Mp[b * (DIM * DIM / 2) + idx] = packbf(s0, s1);
    }
}

// ---------------- dwconv + gate (LDG-direct, 8 px/thread) ----------------
__device__ __forceinline__ float gelu_tanh(float x) {
    float x3 = x * x * x;
    return 0.5f * x * (1.f + tanhf(0.7978845608028654f * (x + 0.044715f * x3)));
}

__global__ __launch_bounds__(256) void dwgate_kernel(const uint32_t* __restrict__ tin,
                                                     const float* __restrict__ dw,
                                                     uint32_t* __restrict__ gw) {
    int b = blockIdx.z, m = blockIdx.y;
    int y = blockIdx.x * 8 + (threadIdx.x >> 5);
    int px0 = (threadIdx.x & 31) * 8;
    int tid = threadIdx.x;

    __shared__ float swt[72];
    int chans[4] = {2 * m, 2 * m + 1, HID + 2 * m, HID + 2 * m + 1};
    if (tid < 72) {
        int oci = tid / 18;
        swt[tid] = dw[(size_t)chans[oci] * 18 + (tid - oci * 18)];
    }
    __syncthreads();

    float u[4][8];
#pragma unroll
    for (int ol = 0; ol < 4; ol++)
#pragma unroll
        for (int j = 0; j < 8; j++) u[ol][j] = 0.f;

    int wbase = px0 >> 1;
#pragma unroll
    for (int ic = 0; ic < 4; ic++) {
        const uint32_t* chb = tin + ((size_t)(b * HID2 + chans[ic]) * HW) / 2;
        int olb = (ic >> 1) << 1;
        int wi0 = (ic & 1) * 9;
#pragma unroll
        for (int ky = 0; ky < 3; ky++) {
            int gy = y + ky - 1;
            bool rok = (unsigned)gy < 256u;
            const uint32_t* rowp = chb + gy * 128;
            float v[12];
#pragma unroll
            for (int w = 0; w < 6; w++) {
                int wi = wbase - 1 + w;
                uint32_t word = (rok && (unsigned)wi < 128u) ? __ldg(rowp + wi) : 0u;
                __nv_bfloat162 bb = *reinterpret_cast<__nv_bfloat162*>(&word);
                v[2 * w] = __bfloat162float(bb.x);
                v[2 * w + 1] = __bfloat162float(bb.y);
            }
#pragma unroll
            for (int kx = 0; kx < 3; kx++) {
                float w0 = swt[olb * 18 + wi0 + ky * 3 + kx];
                float w1 = swt[(olb + 1) * 18 + wi0 + ky * 3 + kx];
#pragma unroll
                for (int j = 0; j < 8; j++) {
                    float xv = v[j + kx + 1];
                    u[olb][j] += w0 * xv;
                    u[olb + 1][j] += w1 * xv;
                }
            }
        }
    }

    uint32_t outw[8];
#pragma unroll
    for (int j = 0; j < 8; j++)
        outw[j] = packbf(gelu_tanh(u[0][j]) * u[2][j], gelu_tanh(u[1][j]) * u[3][j]);
    uint32_t* dst = gw + ((size_t)b * 96 + m) * HW + y * IMG + px0;
    *(uint4*)dst = *(uint4*)&outw[0];
    *(uint4*)(dst + 4) = *(uint4*)&outw[4];
}

// ---------------- launch ----------------
static void* sym_addr(const void* sym) {
    void* p = nullptr;
    cudaGetSymbolAddress(&p, sym);
    return p;
}

extern "C" void kernel_launch(void* const* d_in, const int* in_sizes, int n_in,
                              void* d_out, int out_size) {
    const float* x      = (const float*)d_in[0];
    const float* ln1_w  = (const float*)d_in[1];
    const float* ln1_b  = (const float*)d_in[2];
    const float* qkv1_w = (const float*)d_in[3];
    const float* qkv2_w = (const float*)d_in[4];
    const float* proj_w = (const float*)d_in[5];
    const float* scale  = (const float*)d_in[6];
    const float* ln2_w  = (const float*)d_in[7];
    const float* ln2_b  = (const float*)d_in[8];
    const float* pin_w  = (const float*)d_in[9];
    const float* dw_w   = (const float*)d_in[10];
    const float* pout_w = (const float*)d_in[11];

    uint32_t* xh   = (uint32_t*)sym_addr(g_xh);
    uint32_t* x2h  = (uint32_t*)sym_addr(g_x2h);
    uint32_t* qkvh = (uint32_t*)sym_addr(g_qkvh);
    uint32_t* qkpp = (uint32_t*)sym_addr(g_qkpp);
    uint32_t* vcp  = (uint32_t*)sym_addr(g_vcp);
    uint32_t* tbuf = (uint32_t*)sym_addr(g_t);
    uint32_t* gw   = (uint32_t*)sym_addr(g_gw);
    float* x2   = (float*)sym_addr(g_x2);
    float* wgs1 = (float*)sym_addr(g_wgs1);
    float* wb1  = (float*)sym_addr(g_wb1);
    float* wgs2 = (float*)sym_addr(g_wgs2);
    float* wb2  = (float*)sym_addr(g_wb2);
    float* sqk  = (float*)sym_addr(g_sqk);
    float* attn = (float*)sym_addr(g_attn);
    uint32_t* Wp1 = (uint32_t*)sym_addr(g_Wp1);
    uint32_t* Wp2 = (uint32_t*)sym_addr(g_Wp2);
    uint32_t* Wpo = (uint32_t*)sym_addr(g_Wpo);
    uint32_t* Mp  = (uint32_t*)sym_addr(g_Mp);
    float* out = (float*)d_out;

    static bool attr_done = false;
    if (!attr_done) {
        cudaFuncSetAttribute(conv3x3_bmma_kernel,
                             cudaFuncAttributeMaxDynamicSharedMemorySize, SMEM3);
        attr_done = true;
    }

    prep_kernel<<<3, 256>>>(qkv1_w, ln1_w, ln1_b, pin_w, ln2_w, ln2_b);
    pack1x1p_kernel<<<(C3 * DIM / 2 + 255) / 256, 256>>>(qkv1_w, ln1_w, Wp1, C3, DIM);
    pack1x1p_kernel<<<(HID2 * DIM / 2 + 255) / 256, 256>>>(pin_w, ln2_w, Wp2, HID2, DIM);
    pack1x1_kernel<false><<<(DIM * HID / 2 + 255) / 256, 256>>>(pout_w, nullptr, Wpo, DIM, HID);
    pack3x3_kernel<<<(WP3SZ + 255) / 256, 256>>>(qkv2_w);
    zero_kernel<<<24, 256>>>(attn, BATCH * HEADS * 256);
    zero_kernel<<<3, 256>>>(sqk, BATCH * 2 * DIM);

    // x -> bf16 ch-pair words, then LN-fused qkv1 (96 -> 288) with internal stats
    cvt_x_kernel<<<BATCH * 48 * HW / 4 / 256, 256>>>(x, xh);
    conv1x1uln_kernel<48, 1><<<dim3(256, 3, BATCH), 256>>>(
        xh, Wp1, wgs1, wb1, qkvh);

    // qkv2: 3x3 conv 288 -> 288 (bf16 mma), q/k px-pair + v ch-pair + fused sumsq
    conv3x3_bmma_kernel<<<dim3(256, 3, BATCH), 256, SMEM3>>>(qkvh, qkpp, vcp, sqk);

    // attention statistics (bf16 gram) + fused M
    attn_bmma_kernel<<<dim3(4, BATCH * HEADS), 256>>>(qkpp, attn);
    softmax_build_M<<<BATCH, 256>>>(attn, sqk, scale, proj_w, Mp);

    // fused (attn@v -> proj -> +x) over bf16 v words; writes x2 fp32 + x2h bf16
    conv1x1u_bmma_kernel<48, true><<<dim3(256, 1, BATCH), 256>>>(
        vcp, 48 * HW, Mp, DIM * DIM / 2, x, x2, x2h);

    // LN-fused pin (96 -> 384) from x2h with internal stats -> bf16 px-pair words
    conv1x1uln_kernel<48, 2><<<dim3(256, 4, BATCH), 256>>>(
        x2h, Wp2, wgs2, wb2, tbuf);

    // grouped 3x3 conv + GELU gate -> bf16 consecutive-pair words
    dwgate_kernel<<<dim3(32, DIM, BATCH), 256>>>(tbuf, dw_w, gw);

    // pout (192 -> 96) + residual -> output
    conv1x1u_bmma_kernel<96, false><<<dim3(256, 1, BATCH), 256>>>(
        gw, 96 * HW, Wpo, 0, x2, out, nullptr);
}

// round 13
// speedup vs baseline: 10.8261x; 1.0500x over previous
#include <cuda_runtime.h>
#include <cuda_bf16.h>
#include <cmath>
#include <cstdint>

#define BATCH 4
#define DIM   96
#define HEADS 6
#define HDIM  16
#define C3    288
#define HID   192
#define HID2  384
#define HW    65536
#define IMG   256

// conv3x3 bf16 mma tiling: chunk = 16 ic (= 8 u32 pair-words)
#define NCH3   18
#define BROW3  280
#define BSM3   (8 * 3 * BROW3)
#define WCH3   6912
#define WP3SZ  (3 * NCH3 * WCH3)
#define SMEM3  ((2 * BSM3 + 2 * WCH3) * 4)   // 109056 bytes

#define BRW    264

// ---------------- scratch ----------------
__device__ __align__(16) uint32_t g_xh   [(size_t)BATCH * 48 * HW];        // x bf16 ch-pair
__device__ __align__(16) uint32_t g_x2h  [(size_t)BATCH * 48 * HW];        // x2 bf16 ch-pair
__device__ __align__(16) uint32_t g_qkvh [(size_t)BATCH * (C3 / 2) * HW];  // qkv1 out, ch-pair
__device__ __align__(16) uint32_t g_qkpp [(size_t)BATCH * 192 * (HW / 2)]; // q,k px-pair
__device__ __align__(16) uint32_t g_vcp  [(size_t)BATCH * 48 * HW];        // v ch-pair
__device__ __align__(16) uint32_t g_t    [(size_t)BATCH * HID2 * HW / 2];  // pin out, px-pair
__device__ __align__(16) uint32_t g_gw   [(size_t)BATCH * 96 * HW];        // dwgate out, ch-consecutive pair
__device__ float g_x2   [(size_t)BATCH * DIM * HW];
__device__ float g_wgs1 [C3];
__device__ float g_wb1  [C3];
__device__ float g_wgs2 [HID2];
__device__ float g_wb2  [HID2];
__device__ float g_sqk  [BATCH * 2 * DIM];
__device__ float g_attn [BATCH * HEADS * HDIM * HDIM];
__device__ __align__(16) uint32_t g_Wp1 [C3 * DIM / 2];
__device__ __align__(16) uint32_t g_Wp2 [HID2 * DIM / 2];
__device__ __align__(16) uint32_t g_Wpo [DIM * HID / 2];
__device__ __align__(16) uint32_t g_Mp  [BATCH * DIM * DIM / 2];
__device__ __align__(16) uint32_t g_Wp3 [WP3SZ];

// ---------------- helpers ----------------
__device__ __forceinline__ void cpa16(uint32_t dst, const void* src) {
    asm volatile("cp.async.cg.shared.global [%0], [%1], 16;" :: "r"(dst), "l"(src));
}
__device__ __forceinline__ void cpa16z(uint32_t dst, const void* src, bool v) {
    asm volatile("cp.async.cg.shared.global [%0], [%1], 16, %2;"
                 :: "r"(dst), "l"(src), "r"(v ? 16u : 0u));
}
__device__ __forceinline__ uint32_t packbf(float lo, float hi) {
    uint32_t r;
    asm("cvt.rn.bf16x2.f32 %0, %1, %2;" : "=r"(r) : "f"(hi), "f"(lo));
    return r;
}
__device__ __forceinline__ void mma_bf16(float* c, const uint32_t* a,
                                         uint32_t b0, uint32_t b1) {
    asm volatile("mma.sync.aligned.m16n8k16.row.col.f32.bf16.bf16.f32 "
                 "{%0,%1,%2,%3}, {%4,%5,%6,%7}, {%8,%9}, {%0,%1,%2,%3};"
                 : "+f"(c[0]), "+f"(c[1]), "+f"(c[2]), "+f"(c[3])
                 : "r"(a[0]), "r"(a[1]), "r"(a[2]), "r"(a[3]), "r"(b0), "r"(b1));
}

// ---------------- prep ----------------
__global__ void prep_kernel(const float* __restrict__ qkv1_w, const float* __restrict__ ln1_w,
                            const float* __restrict__ ln1_b, const float* __restrict__ pin_w,
                            const float* __restrict__ ln2_w, const float* __restrict__ ln2_b) {
    int t = blockIdx.x * 256 + threadIdx.x;
    if (t < C3) {
        float s = 0.f, sb = 0.f;
        for (int c = 0; c < DIM; c++) {
            float w = qkv1_w[t * DIM + c];
            s += w * ln1_w[c]; sb += w * ln1_b[c];
        }
        g_wgs1[t] = s; g_wb1[t] = sb;
    } else if (t < C3 + HID2) {
        int r = t - C3;
        float s = 0.f, sb = 0.f;
        for (int c = 0; c < DIM; c++) {
            float w = pin_w[r * DIM + c];
            s += w * ln2_w[c]; sb += w * ln2_b[c];
        }
        g_wgs2[r] = s; g_wb2[r] = sb;
    }
}

// consecutive-pair pack (for pout over gw's (2m,2m+1) words)
template <bool FOLD>
__global__ void pack1x1_kernel(const float* __restrict__ W, const float* __restrict__ gamma,
                               uint32_t* __restrict__ dst, int OC, int ICt) {
    int idx = blockIdx.x * 256 + threadIdx.x;
    if (idx >= OC * ICt / 2) return;
    int r = idx;
    int v = r & 3; r >>= 2;
    int lane = r & 31; r >>= 5;
    int mb = r % 3; r /= 3;
    int og = r % 2; r /= 2;
    int nch = ICt / 16;
    int ch = r % nch; r /= nch;
    int ocT = r;
    int g = lane >> 2, t = lane & 3;
    int oc = ocT * 96 + og * 48 + mb * 16 + g + (v & 1) * 8;
    int ic = ch * 16 + 2 * t + (v >> 1) * 8;
    float w0 = W[oc * ICt + ic], w1 = W[oc * ICt + ic + 1];
    if (FOLD) { w0 *= gamma[ic]; w1 *= gamma[ic + 1]; }
    dst[idx] = packbf(w0, w1);
}

// (ic, ic+8)-pair pack + gamma fold (for ch-pair word activations)
__global__ void pack1x1p_kernel(const float* __restrict__ W, const float* __restrict__ gamma,
                                uint32_t* __restrict__ dst, int OC, int ICt) {
    int idx = blockIdx.x * 256 + threadIdx.x;
    if (idx >= OC * ICt / 2) return;
    int r = idx;
    int v = r & 3; r >>= 2;
    int lane = r & 31; r >>= 5;
    int mb = r % 3; r /= 3;
    int og = r % 2; r /= 2;
    int nch = ICt / 16;
    int ch = r % nch; r /= nch;
    int ocT = r;
    int g = lane >> 2, t = lane & 3;
    int oc = ocT * 96 + og * 48 + mb * 16 + g + (v & 1) * 8;
    int ic0 = ch * 16 + t + (v >> 1) * 4;
    float w0 = W[oc * ICt + ic0] * gamma[ic0];
    float w1 = W[oc * ICt + ic0 + 8] * gamma[ic0 + 8];
    dst[idx] = packbf(w0, w1);
}

__global__ void pack3x3_kernel(const float* __restrict__ W) {
    int idx = blockIdx.x * 256 + threadIdx.x;
    if (idx >= WP3SZ) return;
    int r = idx;
    int v = r & 3; r >>= 2;
    int lane = r & 31; r >>= 5;
    int mb = r % 3; r /= 3;
    int kx = r % 3; r /= 3;
    int og = r % 2; r /= 2;
    int ky = r % 3; r /= 3;
    int ch = r % NCH3; r /= NCH3;
    int ocT = r;
    int g = lane >> 2, t = lane & 3;
    int oc = ocT * 96 + og * 48 + mb * 16 + g + (v & 1) * 8;
    int ic0 = ch * 16 + t + (v >> 1) * 4;
    float w0 = W[(oc * C3 + ic0) * 9 + ky * 3 + kx];
    float w1 = W[(oc * C3 + ic0 + 8) * 9 + ky * 3 + kx];
    g_Wp3[idx] = packbf(w0, w1);
}

__global__ void zero_kernel(float* __restrict__ p, int n) {
    int i = blockIdx.x * 256 + threadIdx.x;
    if (i < n) p[i] = 0.f;
}

// ---------------- x -> bf16 ch-pair convert ----------------
__global__ __launch_bounds__(256) void cvt_x_kernel(const float* __restrict__ x,
                                                    uint32_t* __restrict__ xh) {
    int idx = blockIdx.x * 256 + threadIdx.x;
    int b = idx / (48 * HW / 4);
    int rem = idx - b * (48 * HW / 4);
    int w = rem / (HW / 4);
    int p = (rem - w * (HW / 4)) * 4;
    int clo = (w >> 3) * 16 + (w & 7);
    const float* lo = x + ((size_t)b * DIM + clo) * HW + p;
    const float* hi = lo + (size_t)8 * HW;
    float4 l4 = *(const float4*)lo;
    float4 h4 = *(const float4*)hi;
    uint4 o;
    o.x = packbf(l4.x, h4.x); o.y = packbf(l4.y, h4.y);
    o.z = packbf(l4.z, h4.z); o.w = packbf(l4.w, h4.w);
    *(uint4*)&xh[((size_t)b * 48 + w) * HW + p] = o;
}

// ---------------- 1x1 conv, u32 ch-pair in, fused LN stats ----------------
template <int ICW, int OMODE>
__global__ __launch_bounds__(256, 2) void conv1x1uln_kernel(
    const uint32_t* __restrict__ in,
    const uint32_t* __restrict__ Wp,
    const float* __restrict__ wgs, const float* __restrict__ wb,
    uint32_t* __restrict__ outv) {
    constexpr int NCH = ICW / 8;
    __shared__ __align__(16) uint32_t bsmw[2][8 * BRW];
    __shared__ __align__(16) uint32_t wsm[2][768];
    __shared__ float smu[256], srstd[256];

    int b = blockIdx.z, ocT = blockIdx.y, px0 = blockIdx.x * 256;
    int OCtot = gridDim.y * 96;
    int tid = threadIdx.x, warp = tid >> 5, lane = tid & 31;
    int og = warp >> 2, pg = warp & 3, g = lane >> 2, t = lane & 3;

    float acc[3][8][4];
#pragma unroll
    for (int mb = 0; mb < 3; mb++)
#pragma unroll
        for (int j = 0; j < 8; j++)
#pragma unroll
            for (int v = 0; v < 4; v++) acc[mb][j][v] = 0.f;

    float psum = 0.f, psq = 0.f;

    const uint32_t* Wb = Wp + (size_t)ocT * NCH * 768;
    auto issue = [&](int ch, int buf) {
#pragma unroll
        for (int k = 0; k < 2; k++) {
            int idx = tid + k * 256;
            int row = idx >> 6, c4 = idx & 63;
            const uint32_t* src = in + ((size_t)b * ICW + ch * 8 + row) * HW + px0 + c4 * 4;
            cpa16((uint32_t)__cvta_generic_to_shared(&bsmw[buf][row * BRW + c4 * 4]), src);
        }
        if (tid < 192)
            cpa16((uint32_t)__cvta_generic_to_shared(&wsm[buf][tid * 4]), Wb + ch * 768 + tid * 4);
        asm volatile("cp.async.commit_group;");
    };
    issue(0, 0);
    for (int s = 0; s < NCH; s++) {
        if (s + 1 < NCH) { issue(s + 1, (s + 1) & 1); asm volatile("cp.async.wait_group 1;"); }
        else asm volatile("cp.async.wait_group 0;");
        __syncthreads();
        int buf = s & 1;
        const uint32_t* bB = &bsmw[buf][0];
#pragma unroll
        for (int w = 0; w < 8; w++) {
            uint32_t word = bB[w * BRW + tid];
            __nv_bfloat162 bb = *reinterpret_cast<__nv_bfloat162*>(&word);
            float a0 = __bfloat162float(bb.x), a1 = __bfloat162float(bb.y);
            psum += a0 + a1; psq += a0 * a0 + a1 * a1;
        }
        const uint32_t* wc = &wsm[buf][og * 384];
        uint32_t a[3][4];
#pragma unroll
        for (int mb = 0; mb < 3; mb++) *(uint4*)a[mb] = *(const uint4*)&wc[mb * 128 + lane * 4];
#pragma unroll
        for (int j = 0; j < 8; j++) {
            int col = pg * 64 + 8 * j + g;
            uint32_t b0 = bB[t * BRW + col], b1 = bB[(t + 4) * BRW + col];
#pragma unroll
            for (int mb = 0; mb < 3; mb++) mma_bf16(acc[mb][j], a[mb], b0, b1);
        }
        __syncthreads();
    }

    {
        float mu = psum * (1.f / DIM);
        float var = psq * (1.f / DIM) - mu * mu;
        smu[tid] = mu;
        srstd[tid] = rsqrtf(var + 1e-5f);
    }
    __syncthreads();

#pragma unroll
    for (int mb = 0; mb < 3; mb++) {
        int oc = ocT * 96 + og * 48 + mb * 16 + g;
        float gs0 = wgs[oc], gs8 = wgs[oc + 8], bb0 = wb[oc], bb8 = wb[oc + 8];
#pragma unroll
        for (int j = 0; j < 8; j++) {
            int pl = pg * 64 + 8 * j + 2 * t;
            int px = px0 + pl;
            float m0 = smu[pl], m1 = smu[pl + 1], r0 = srstd[pl], r1 = srstd[pl + 1];
            float v00 = r0 * (acc[mb][j][0] - m0 * gs0) + bb0;
            float v01 = r1 * (acc[mb][j][1] - m1 * gs0) + bb0;
            float v10 = r0 * (acc[mb][j][2] - m0 * gs8) + bb8;
            float v11 = r1 * (acc[mb][j][3] - m1 * gs8) + bb8;
            if (OMODE == 1) {
                int ch = ocT * 6 + og * 3 + mb;
                int c2 = ch * 8 + g;
                uint2 val = make_uint2(packbf(v00, v10), packbf(v01, v11));
                *(uint2*)&outv[((size_t)b * (OCtot / 2) + c2) * HW + px] = val;
            } else {
                outv[(((size_t)b * OCtot + oc) * HW + px) >> 1] = packbf(v00, v01);
                outv[(((size_t)b * OCtot + oc + 8) * HW + px) >> 1] = packbf(v10, v11);
            }
        }
    }
}

// ---------------- 1x1 conv, u32 pair-word in, fp32 out + residual ----------------
template <int ICW, bool WH>
__global__ __launch_bounds__(256, 2) void conv1x1u_bmma_kernel(
    const uint32_t* __restrict__ in, int in_bstride,
    const uint32_t* __restrict__ Wp, int w_bstride,
    const float* __restrict__ res, float* __restrict__ out,
    uint32_t* __restrict__ outh) {
    constexpr int NCH = ICW / 8;
    __shared__ __align__(16) uint32_t bsmw[2][8 * BRW];
    __shared__ __align__(16) uint32_t wsm[2][768];
    int b = blockIdx.z, px0 = blockIdx.x * 256;
    int tid = threadIdx.x, warp = tid >> 5, lane = tid & 31;
    int og = warp >> 2, pg = warp & 3, g = lane >> 2, t = lane & 3;
    float acc[3][8][4];
#pragma unroll
    for (int mb = 0; mb < 3; mb++)
#pragma unroll
        for (int j = 0; j < 8; j++)
#pragma unroll
            for (int v = 0; v < 4; v++) acc[mb][j][v] = 0.f;
    const uint32_t* Wb = Wp + (size_t)b * w_bstride;
    auto issue = [&](int ch, int buf) {
#pragma unroll
        for (int k = 0; k < 2; k++) {
            int idx = tid + k * 256;
            int row = idx >> 6, c4 = idx & 63;
            const uint32_t* src = in + (size_t)b * in_bstride + (size_t)(ch * 8 + row) * HW + px0 + c4 * 4;
            cpa16((uint32_t)__cvta_generic_to_shared(&bsmw[buf][row * BRW + c4 * 4]), src);
        }
        if (tid < 192)
            cpa16((uint32_t)__cvta_generic_to_shared(&wsm[buf][tid * 4]), Wb + ch * 768 + tid * 4);
        asm volatile("cp.async.commit_group;");
    };
    issue(0, 0);
    for (int s = 0; s < NCH; s++) {
        if (s + 1 < NCH) { issue(s + 1, (s + 1) & 1); asm volatile("cp.async.wait_group 1;"); }
        else asm volatile("cp.async.wait_group 0;");
        __syncthreads();
        int buf = s & 1;
        const uint32_t* wc = &wsm[buf][og * 384];
        uint32_t a[3][4];
#pragma unroll
        for (int mb = 0; mb < 3; mb++) *(uint4*)a[mb] = *(const uint4*)&wc[mb * 128 + lane * 4];
        const uint32_t* bB = &bsmw[buf][0];
#pragma unroll
        for (int j = 0; j < 8; j++) {
            int col = pg * 64 + 8 * j + g;
            uint32_t b0 = bB[t * BRW + col], b1 = bB[(t + 4) * BRW + col];
#pragma unroll
            for (int mb = 0; mb < 3; mb++) mma_bf16(acc[mb][j], a[mb], b0, b1);
        }
        __syncthreads();
    }
#pragma unroll
    for (int mb = 0; mb < 3; mb++) {
        int oc = og * 48 + mb * 16 + g;
#pragma unroll
        for (int j = 0; j < 8; j++) {
            int px = px0 + pg * 64 + 8 * j + 2 * t;
            float2 ra = *(const float2*)&res[((size_t)b * 96 + oc) * HW + px];
            float2 rb = *(const float2*)&res[((size_t)b * 96 + oc + 8) * HW + px];
            float v00 = acc[mb][j][0] + ra.x, v01 = acc[mb][j][1] + ra.y;
            float v10 = acc[mb][j][2] + rb.x, v11 = acc[mb][j][3] + rb.y;
            *(float2*)&out[((size_t)b * 96 + oc) * HW + px] = make_float2(v00, v01);
            *(float2*)&out[((size_t)b * 96 + oc + 8) * HW + px] = make_float2(v10, v11);
            if (WH) {
                int w = (og * 3 + mb) * 8 + g;
                uint2 val = make_uint2(packbf(v00, v10), packbf(v01, v11));
                *(uint2*)&outh[((size_t)b * 48 + w) * HW + px] = val;
            }
        }
    }
}

// ---------------- conv3x3 (proven bf16 mma, now 2 blocks/SM) ----------------
__global__ __launch_bounds__(256, 2) void conv3x3_bmma_kernel(const uint32_t* __restrict__ in,
                                                              uint32_t* __restrict__ qk,
                                                              uint32_t* __restrict__ vout,
                                                              float* __restrict__ sqk) {
    extern __shared__ uint32_t dynsmem[];
    uint32_t* bsm = dynsmem;
    uint32_t* wsm = dynsmem + 2 * BSM3;

    int b = blockIdx.z, ocT = blockIdx.y, y = blockIdx.x;
    int tid = threadIdx.x, warp = tid >> 5, lane = tid & 31;
    int og = warp >> 2, pg = warp & 3, g = lane >> 2, t = lane & 3;

    if (tid < 96) {
        int s = tid;
        int side = s & 1; s >>= 1;
        int wr = s % 24; int bufi = s / 24;
        bsm[bufi * BSM3 + wr * BROW3 + (side ? 260 : 3)] = 0u;
    }

    float acc[3][8][4];
#pragma unroll
    for (int mb = 0; mb < 3; mb++)
#pragma unroll
        for (int j = 0; j < 8; j++)
#pragma unroll
            for (int v = 0; v < 4; v++) acc[mb][j][v] = 0.f;

    const uint32_t* wp_base = g_Wp3 + (size_t)ocT * NCH3 * WCH3;

    auto issue = [&](int ch, int buf) {
        const uint32_t* ibase = in + ((size_t)b * (C3 / 2) + ch * 8) * HW;
        uint32_t* bdst = bsm + buf * BSM3;
#pragma unroll
        for (int k = 0; k < 6; k++) {
            int idx = tid + k * 256;
            int wr = idx >> 6, c4 = idx & 63;
            int w = wr / 3, rr = wr - 3 * w;
            int gy = y + rr - 1;
            bool ok = (unsigned)gy < 256u;
            const uint32_t* src = ibase + (size_t)w * HW + (ok ? gy : 0) * IMG + c4 * 4;
            cpa16z((uint32_t)__cvta_generic_to_shared(bdst + wr * BROW3 + 4 + c4 * 4), src, ok);
        }
        const uint32_t* wsrc = wp_base + (size_t)ch * WCH3;
        uint32_t* wdst = wsm + buf * WCH3;
#pragma unroll
        for (int k = 0; k < 7; k++) {
            int i = tid + k * 256;
            if (i < WCH3 / 4)
                cpa16((uint32_t)__cvta_generic_to_shared(wdst + i * 4), wsrc + i * 4);
        }
        asm volatile("cp.async.commit_group;");
    };

    issue(0, 0);
    for (int s = 0; s < NCH3; s++) {
        if (s + 1 < NCH3) { issue(s + 1, (s + 1) & 1); asm volatile("cp.async.wait_group 1;"); }
        else asm volatile("cp.async.wait_group 0;");
        __syncthreads();
        int buf = s & 1;
        const uint32_t* bB = bsm + buf * BSM3;
        const uint32_t* wc = wsm + buf * WCH3;
        int colb = 3 + pg * 64 + g;
#pragma unroll
        for (int ky = 0; ky < 3; ky++) {
#pragma unroll
            for (int kx = 0; kx < 3; kx++) {
                const uint32_t* wbp = wc + (((ky * 2 + og) * 3 + kx) * 3) * 128;
                uint32_t a[3][4];
#pragma unroll
                for (int mb = 0; mb < 3; mb++)
                    *(uint4*)a[mb] = *(const uint4*)&wbp[mb * 128 + lane * 4];
#pragma unroll
                for (int j = 0; j < 8; j++) {
                    int col = colb + 8 * j + kx;
                    uint32_t b0 = bB[(t * 3 + ky) * BROW3 + col];
                    uint32_t b1 = bB[((t + 4) * 3 + ky) * BROW3 + col];
#pragma unroll
                    for (int mb = 0; mb < 3; mb++) mma_bf16(acc[mb][j], a[mb], b0, b1);
                }
            }
        }
        __syncthreads();
    }

    if (ocT < 2) {
#pragma unroll
        for (int mb = 0; mb < 3; mb++) {
            float s0 = 0.f, s8 = 0.f;
#pragma unroll
            for (int j = 0; j < 8; j++) {
                s0 += acc[mb][j][0] * acc[mb][j][0] + acc[mb][j][1] * acc[mb][j][1];
                s8 += acc[mb][j][2] * acc[mb][j][2] + acc[mb][j][3] * acc[mb][j][3];
            }
            s0 += __shfl_xor_sync(0xffffffffu, s0, 1);
            s0 += __shfl_xor_sync(0xffffffffu, s0, 2);
            s8 += __shfl_xor_sync(0xffffffffu, s8, 1);
            s8 += __shfl_xor_sync(0xffffffffu, s8, 2);
            int oc = ocT * 96 + og * 48 + mb * 16 + g;
            if (t == 0) {
                atomicAdd(&sqk[b * 2 * DIM + oc], s0);
                atomicAdd(&sqk[b * 2 * DIM + oc + 8], s8);
            }
#pragma unroll
            for (int j = 0; j < 8; j++) {
                int px = pg * 64 + 8 * j + 2 * t;
                size_t base = (size_t)(b * 192 + oc) * (HW / 2) + ((y * IMG + px) >> 1);
                qk[base] = packbf(acc[mb][j][0], acc[mb][j][1]);
                qk[base + (size_t)8 * (HW / 2)] = packbf(acc[mb][j][2], acc[mb][j][3]);
            }
        }
    } else {
#pragma unroll
        for (int mb = 0; mb < 3; mb++) {
            int c2 = (og * 3 + mb) * 8 + g;
#pragma unroll
            for (int j = 0; j < 8; j++) {
                int px = pg * 64 + 8 * j + 2 * t;
                uint2 val = make_uint2(packbf(acc[mb][j][0], acc[mb][j][2]),
                                       packbf(acc[mb][j][1], acc[mb][j][3]));
                *(uint2*)&vout[((size_t)(b * 48 + c2)) * HW + y * IMG + px] = val;
            }
        }
    }
}

// ---------------- attention gram (wider grid) ----------------
__global__ __launch_bounds__(256) void attn_bmma_kernel(const uint32_t* __restrict__ qk,
                                                        float* __restrict__ attn_raw) {
    int bh = blockIdx.y;
    int b = bh / HEADS, h = bh - b * HEADS;
    int warp = threadIdx.x >> 5, lane = threadIdx.x & 31;
    int tg = lane >> 2, t = lane & 3;
    const uint32_t* q0 = qk + (size_t)(b * 192 + h * HDIM + tg) * (HW / 2);
    const uint32_t* q1 = q0 + (size_t)8 * (HW / 2);
    const uint32_t* k0 = qk + (size_t)(b * 192 + 96 + h * HDIM + tg) * (HW / 2);
    const uint32_t* k1 = k0 + (size_t)8 * (HW / 2);
    float c0[4] = {0.f, 0.f, 0.f, 0.f};
    float c1[4] = {0.f, 0.f, 0.f, 0.f};
    int slab0 = (blockIdx.x * 8 + warp) * 16;
    for (int s = 0; s < 16; s++) {
        int w0 = (slab0 + s) * 32 + 4 * t;
        uint32_t qa[4], qb[4], qc[4], qd[4], ka[4], kc[4], kb[4], kd[4];
        *(uint4*)qa = *(const uint4*)(q0 + w0);
        *(uint4*)qb = *(const uint4*)(q1 + w0);
        *(uint4*)qc = *(const uint4*)(q0 + w0 + 16);
        *(uint4*)qd = *(const uint4*)(q1 + w0 + 16);
        *(uint4*)ka = *(const uint4*)(k0 + w0);
        *(uint4*)kc = *(const uint4*)(k0 + w0 + 16);
        *(uint4*)kb = *(const uint4*)(k1 + w0);
        *(uint4*)kd = *(const uint4*)(k1 + w0 + 16);
#pragma unroll
        for (int m = 0; m < 4; m++) {
            uint32_t a[4] = { qa[m], qb[m], qc[m], qd[m] };
            mma_bf16(c0, a, ka[m], kc[m]);
            mma_bf16(c1, a, kb[m], kd[m]);
        }
    }
    float* dst = attn_raw + bh * 256;
    atomicAdd(dst + tg * 16 + 2 * t, c0[0]);
    atomicAdd(dst + tg * 16 + 2 * t + 1, c0[1]);
    atomicAdd(dst + (tg + 8) * 16 + 2 * t, c0[2]);
    atomicAdd(dst + (tg + 8) * 16 + 2 * t + 1, c0[3]);
    atomicAdd(dst + tg * 16 + 8 + 2 * t, c1[0]);
    atomicAdd(dst + tg * 16 + 8 + 2 * t + 1, c1[1]);
    atomicAdd(dst + (tg + 8) * 16 + 8 + 2 * t, c1[2]);
    atomicAdd(dst + (tg + 8) * 16 + 8 + 2 * t + 1, c1[3]);
}

// ---------------- softmax + fused M ----------------
__global__ __launch_bounds__(256) void softmax_build_M(const float* __restrict__ attn_raw,
                                                       const float* __restrict__ sqk,
                                                       const float* __restrict__ scale,
                                                       const float* __restrict__ proj_w,
                                                       uint32_t* __restrict__ Mp) {
    int b = blockIdx.x;
    int tdx = threadIdx.x;
    __shared__ float A[HEADS * 256];
    __shared__ float nq[DIM], nk[DIM];
    if (tdx < DIM) {
        nq[tdx] = fmaxf(sqrtf(sqk[b * 2 * DIM + tdx]), 1e-12f);
        nk[tdx] = fmaxf(sqrtf(sqk[b * 2 * DIM + DIM + tdx]), 1e-12f);
    }
    __syncthreads();
    for (int idx = tdx; idx < HEADS * 256; idx += 256) {
        int h = idx >> 8;
        int cd = idx & 255;
        int c = cd >> 4, d = cd & 15;
        A[idx] = attn_raw[b * HEADS * 256 + idx] /
                 (nq[h * HDIM + c] * nk[h * HDIM + d]) * scale[h];
    }
    __syncthreads();
    if (tdx < DIM) {
        int h = tdx >> 4, c = tdx & 15;
        float* row = &A[h * 256 + c * 16];
        float mx = row[0];
#pragma unroll
        for (int d = 1; d < 16; d++) mx = fmaxf(mx, row[d]);
        float sum = 0.f;
#pragma unroll
        for (int d = 0; d < 16; d++) { float e = expf(row[d] - mx); row[d] = e; sum += e; }
        float inv = 1.f / sum;
#pragma unroll
        for (int d = 0; d < 16; d++) row[d] *= inv;
    }
    __syncthreads();
    for (int idx = tdx; idx < DIM * DIM / 2; idx += 256) {
        int r = idx;
        int v = r & 3; r >>= 2;
        int lane = r & 31; r >>= 5;
        int mb = r % 3; r /= 3;
        int og = r % 2; r /= 2;
        int ch = r;
        int g = lane >> 2, t = lane & 3;
        int oc = og * 48 + mb * 16 + g + (v & 1) * 8;
        int d = t + (v >> 1) * 4;
        int h = ch;
        float s0 = 0.f, s1 = 0.f;
#pragma unroll
        for (int cg = 0; cg < 16; cg++) {
            float pw = proj_w[oc * DIM + h * HDIM + cg];
            s0 += pw * A[h * 256 + cg * 16 + d];
            s1 += pw * A[h * 256 + cg * 16 + d + 8];
        }
        Mp[b * (DIM * DIM / 2) + idx] = packbf(s0, s1);
    }
}

// ---------------- dwconv + gate (LDG-direct, 8 px/thread) ----------------
__device__ __forceinline__ float gelu_tanh(float x) {
    float x3 = x * x * x;
    return 0.5f * x * (1.f + tanhf(0.7978845608028654f * (x + 0.044715f * x3)));
}

__global__ __launch_bounds__(256) void dwgate_kernel(const uint32_t* __restrict__ tin,
                                                     const float* __restrict__ dw,
                                                     uint32_t* __restrict__ gw) {
    int b = blockIdx.z, m = blockIdx.y;
    int y = blockIdx.x * 8 + (threadIdx.x >> 5);
    int px0 = (threadIdx.x & 31) * 8;
    int tid = threadIdx.x;

    __shared__ float swt[72];
    int chans[4] = {2 * m, 2 * m + 1, HID + 2 * m, HID + 2 * m + 1};
    if (tid < 72) {
        int oci = tid / 18;
        swt[tid] = dw[(size_t)chans[oci] * 18 + (tid - oci * 18)];
    }
    __syncthreads();

    float u[4][8];
#pragma unroll
    for (int ol = 0; ol < 4; ol++)
#pragma unroll
        for (int j = 0; j < 8; j++) u[ol][j] = 0.f;

    int wbase = px0 >> 1;
#pragma unroll
    for (int ic = 0; ic < 4; ic++) {
        const uint32_t* chb = tin + ((size_t)(b * HID2 + chans[ic]) * HW) / 2;
        int olb = (ic >> 1) << 1;
        int wi0 = (ic & 1) * 9;
#pragma unroll
        for (int ky = 0; ky < 3; ky++) {
            int gy = y + ky - 1;
            bool rok = (unsigned)gy < 256u;
            const uint32_t* rowp = chb + gy * 128;
            float v[12];
#pragma unroll
            for (int w = 0; w < 6; w++) {
                int wi = wbase - 1 + w;
                uint32_t word = (rok && (unsigned)wi < 128u) ? __ldg(rowp + wi) : 0u;
                __nv_bfloat162 bb = *reinterpret_cast<__nv_bfloat162*>(&word);
                v[2 * w] = __bfloat162float(bb.x);
                v[2 * w + 1] = __bfloat162float(bb.y);
            }
#pragma unroll
            for (int kx = 0; kx < 3; kx++) {
                float w0 = swt[olb * 18 + wi0 + ky * 3 + kx];
                float w1 = swt[(olb + 1) * 18 + wi0 + ky * 3 + kx];
#pragma unroll
                for (int j = 0; j < 8; j++) {
                    float xv = v[j + kx + 1];
                    u[olb][j] += w0 * xv;
                    u[olb + 1][j] += w1 * xv;
                }
            }
        }
    }

    uint32_t outw[8];
#pragma unroll
    for (int j = 0; j < 8; j++)
        outw[j] = packbf(gelu_tanh(u[0][j]) * u[2][j], gelu_tanh(u[1][j]) * u[3][j]);
    uint32_t* dst = gw + ((size_t)b * 96 + m) * HW + y * IMG + px0;
    *(uint4*)dst = *(uint4*)&outw[0];
    *(uint4*)(dst + 4) = *(uint4*)&outw[4];
}

// ---------------- launch ----------------
static void* sym_addr(const void* sym) {
    void* p = nullptr;
    cudaGetSymbolAddress(&p, sym);
    return p;
}

extern "C" void kernel_launch(void* const* d_in, const int* in_sizes, int n_in,
                              void* d_out, int out_size) {
    const float* x      = (const float*)d_in[0];
    const float* ln1_w  = (const float*)d_in[1];
    const float* ln1_b  = (const float*)d_in[2];
    const float* qkv1_w = (const float*)d_in[3];
    const float* qkv2_w = (const float*)d_in[4];
    const float* proj_w = (const float*)d_in[5];
    const float* scale  = (const float*)d_in[6];
    const float* ln2_w  = (const float*)d_in[7];
    const float* ln2_b  = (const float*)d_in[8];
    const float* pin_w  = (const float*)d_in[9];
    const float* dw_w   = (const float*)d_in[10];
    const float* pout_w = (const float*)d_in[11];

    uint32_t* xh   = (uint32_t*)sym_addr(g_xh);
    uint32_t* x2h  = (uint32_t*)sym_addr(g_x2h);
    uint32_t* qkvh = (uint32_t*)sym_addr(g_qkvh);
    uint32_t* qkpp = (uint32_t*)sym_addr(g_qkpp);
    uint32_t* vcp  = (uint32_t*)sym_addr(g_vcp);
    uint32_t* tbuf = (uint32_t*)sym_addr(g_t);
    uint32_t* gw   = (uint32_t*)sym_addr(g_gw);
    float* x2   = (float*)sym_addr(g_x2);
    float* wgs1 = (float*)sym_addr(g_wgs1);
    float* wb1  = (float*)sym_addr(g_wb1);
    float* wgs2 = (float*)sym_addr(g_wgs2);
    float* wb2  = (float*)sym_addr(g_wb2);
    float* sqk  = (float*)sym_addr(g_sqk);
    float* attn = (float*)sym_addr(g_attn);
    uint32_t* Wp1 = (uint32_t*)sym_addr(g_Wp1);
    uint32_t* Wp2 = (uint32_t*)sym_addr(g_Wp2);
    uint32_t* Wpo = (uint32_t*)sym_addr(g_Wpo);
    uint32_t* Mp  = (uint32_t*)sym_addr(g_Mp);
    float* out = (float*)d_out;

    static bool attr_done = false;
    if (!attr_done) {
        cudaFuncSetAttribute(conv3x3_bmma_kernel,
                             cudaFuncAttributeMaxDynamicSharedMemorySize, SMEM3);
        attr_done = true;
    }

    prep_kernel<<<3, 256>>>(qkv1_w, ln1_w, ln1_b, pin_w, ln2_w, ln2_b);
    pack1x1p_kernel<<<(C3 * DIM / 2 + 255) / 256, 256>>>(qkv1_w, ln1_w, Wp1, C3, DIM);
    pack1x1p_kernel<<<(HID2 * DIM / 2 + 255) / 256, 256>>>(pin_w, ln2_w, Wp2, HID2, DIM);
    pack1x1_kernel<false><<<(DIM * HID / 2 + 255) / 256, 256>>>(pout_w, nullptr, Wpo, DIM, HID);
    pack3x3_kernel<<<(WP3SZ + 255) / 256, 256>>>(qkv2_w);
    zero_kernel<<<24, 256>>>(attn, BATCH * HEADS * 256);
    zero_kernel<<<3, 256>>>(sqk, BATCH * 2 * DIM);

    // x -> bf16 ch-pair words, then LN-fused qkv1 (96 -> 288) with internal stats
    cvt_x_kernel<<<BATCH * 48 * HW / 4 / 256, 256>>>(x, xh);
    conv1x1uln_kernel<48, 1><<<dim3(256, 3, BATCH), 256>>>(
        xh, Wp1, wgs1, wb1, qkvh);

    // qkv2: 3x3 conv 288 -> 288 (bf16 mma), q/k px-pair + v ch-pair + fused sumsq
    conv3x3_bmma_kernel<<<dim3(256, 3, BATCH), 256, SMEM3>>>(qkvh, qkpp, vcp, sqk);

    // attention statistics (bf16 gram) + fused M
    attn_bmma_kernel<<<dim3(8, BATCH * HEADS), 256>>>(qkpp, attn);
    softmax_build_M<<<BATCH, 256>>>(attn, sqk, scale, proj_w, Mp);

    // fused (attn@v -> proj -> +x) over bf16 v words; writes x2 fp32 + x2h bf16
    conv1x1u_bmma_kernel<48, true><<<dim3(256, 1, BATCH), 256>>>(
        vcp, 48 * HW, Mp, DIM * DIM / 2, x, x2, x2h);

    // LN-fused pin (96 -> 384) from x2h with internal stats -> bf16 px-pair words
    conv1x1uln_kernel<48, 2><<<dim3(256, 4, BATCH), 256>>>(
        x2h, Wp2, wgs2, wb2, tbuf);

    // grouped 3x3 conv + GELU gate -> bf16 consecutive-pair words
    dwgate_kernel<<<dim3(32, DIM, BATCH), 256>>>(tbuf, dw_w, gw);

    // pout (192 -> 96) + residual -> output
    conv1x1u_bmma_kernel<96, false><<<dim3(256, 1, BATCH), 256>>>(
        gw, 96 * HW, Wpo, 0, x2, out, nullptr);
}

// round 15
// speedup vs baseline: 10.8874x; 1.0057x over previous
#include <cuda_runtime.h>
#include <cuda_bf16.h>
#include <cmath>
#include <cstdint>

#define BATCH 4
#define DIM   96
#define HEADS 6
#define HDIM  16
#define C3    288
#define HID   192
#define HID2  384
#define HW    65536
#define IMG   256

// conv3x3 bf16 mma tiling: chunk = 16 ic (= 8 u32 pair-words)
#define NCH3   18
#define BROW3  280
#define BSM3   (8 * 3 * BROW3)
#define WCH3   6912
#define WP3SZ  (3 * NCH3 * WCH3)
#define SMEM3  ((2 * BSM3 + 2 * WCH3) * 4)   // 109056 bytes

#define BRW    264

// ---------------- scratch ----------------
__device__ __align__(16) uint32_t g_xh   [(size_t)BATCH * 48 * HW];
__device__ __align__(16) uint32_t g_x2h  [(size_t)BATCH * 48 * HW];
__device__ __align__(16) uint32_t g_qkvh [(size_t)BATCH * (C3 / 2) * HW];
__device__ __align__(16) uint32_t g_qkpp [(size_t)BATCH * 192 * (HW / 2)];
__device__ __align__(16) uint32_t g_vcp  [(size_t)BATCH * 48 * HW];
__device__ __align__(16) uint32_t g_t    [(size_t)BATCH * HID2 * HW / 2];
__device__ __align__(16) uint32_t g_gw   [(size_t)BATCH * 96 * HW];
__device__ float g_x2   [(size_t)BATCH * DIM * HW];
__device__ float g_wgs1 [C3];
__device__ float g_wb1  [C3];
__device__ float g_wgs2 [HID2];
__device__ float g_wb2  [HID2];
__device__ float g_sqk  [BATCH * 2 * DIM];
__device__ float g_attn [BATCH * HEADS * HDIM * HDIM];
__device__ __align__(16) uint32_t g_Wp1 [C3 * DIM / 2];
__device__ __align__(16) uint32_t g_Wp2 [HID2 * DIM / 2];
__device__ __align__(16) uint32_t g_Wpo [DIM * HID / 2];
__device__ __align__(16) uint32_t g_Mp  [BATCH * DIM * DIM / 2];
__device__ __align__(16) uint32_t g_Wp3 [WP3SZ];

// ---------------- helpers ----------------
__device__ __forceinline__ void cpa16(uint32_t dst, const void* src) {
    asm volatile("cp.async.cg.shared.global [%0], [%1], 16;" :: "r"(dst), "l"(src));
}
__device__ __forceinline__ void cpa16z(uint32_t dst, const void* src, bool v) {
    asm volatile("cp.async.cg.shared.global [%0], [%1], 16, %2;"
                 :: "r"(dst), "l"(src), "r"(v ? 16u : 0u));
}
__device__ __forceinline__ uint32_t packbf(float lo, float hi) {
    uint32_t r;
    asm("cvt.rn.bf16x2.f32 %0, %1, %2;" : "=r"(r) : "f"(hi), "f"(lo));
    return r;
}
__device__ __forceinline__ void mma_bf16(float* c, const uint32_t* a,
                                         uint32_t b0, uint32_t b1) {
    asm volatile("mma.sync.aligned.m16n8k16.row.col.f32.bf16.bf16.f32 "
                 "{%0,%1,%2,%3}, {%4,%5,%6,%7}, {%8,%9}, {%0,%1,%2,%3};"
                 : "+f"(c[0]), "+f"(c[1]), "+f"(c[2]), "+f"(c[3])
                 : "r"(a[0]), "r"(a[1]), "r"(a[2]), "r"(a[3]), "r"(b0), "r"(b1));
}

// ---------------- fused setup: prep + 3 packs + zeros ----------------
// region sizes
#define S_PREP   (C3 + HID2)                 // 672
#define S_P1     (C3 * DIM / 2)              // 13824
#define S_P2     (HID2 * DIM / 2)            // 18432
#define S_PO     (DIM * HID / 2)             // 9216
#define S_ZA     (BATCH * HEADS * 256)       // 6144
#define S_ZS     (BATCH * 2 * DIM)           // 768
#define S_TOTAL  (S_PREP + S_P1 + S_P2 + S_PO + S_ZA + S_ZS)

// (ic, ic+8)-pair pack + gamma fold
__device__ __forceinline__ void pack_pair(const float* W, const float* gamma,
                                          uint32_t* dst, int ICt, int idx) {
    int r = idx;
    int v = r & 3; r >>= 2;
    int lane = r & 31; r >>= 5;
    int mb = r % 3; r /= 3;
    int og = r % 2; r /= 2;
    int nch = ICt / 16;
    int ch = r % nch; r /= nch;
    int ocT = r;
    int g = lane >> 2, t = lane & 3;
    int oc = ocT * 96 + og * 48 + mb * 16 + g + (v & 1) * 8;
    int ic0 = ch * 16 + t + (v >> 1) * 4;
    float w0 = W[oc * ICt + ic0] * gamma[ic0];
    float w1 = W[oc * ICt + ic0 + 8] * gamma[ic0 + 8];
    dst[idx] = packbf(w0, w1);
}

// consecutive-pair pack (no fold)
__device__ __forceinline__ void pack_cons(const float* W, uint32_t* dst, int ICt, int idx) {
    int r = idx;
    int v = r & 3; r >>= 2;
    int lane = r & 31; r >>= 5;
    int mb = r % 3; r /= 3;
    int og = r % 2; r /= 2;
    int nch = ICt / 16;
    int ch = r % nch; r /= nch;
    int ocT = r;
    int g = lane >> 2, t = lane & 3;
    int oc = ocT * 96 + og * 48 + mb * 16 + g + (v & 1) * 8;
    int ic = ch * 16 + 2 * t + (v >> 1) * 8;
    dst[idx] = packbf(W[oc * ICt + ic], W[oc * ICt + ic + 1]);
}

__global__ void setup_kernel(const float* __restrict__ qkv1_w, const float* __restrict__ ln1_w,
                             const float* __restrict__ ln1_b, const float* __restrict__ pin_w,
                             const float* __restrict__ ln2_w, const float* __restrict__ ln2_b,
                             const float* __restrict__ pout_w) {
    int gid = blockIdx.x * 256 + threadIdx.x;
    if (gid < S_PREP) {
        int t = gid;
        if (t < C3) {
            float s = 0.f, sb = 0.f;
            for (int c = 0; c < DIM; c++) {
                float w = qkv1_w[t * DIM + c];
                s += w * ln1_w[c]; sb += w * ln1_b[c];
            }
            g_wgs1[t] = s; g_wb1[t] = sb;
        } else {
            int r = t - C3;
            float s = 0.f, sb = 0.f;
            for (int c = 0; c < DIM; c++) {
                float w = pin_w[r * DIM + c];
                s += w * ln2_w[c]; sb += w * ln2_b[c];
            }
            g_wgs2[r] = s; g_wb2[r] = sb;
        }
        return;
    }
    gid -= S_PREP;
    if (gid < S_P1) { pack_pair(qkv1_w, ln1_w, g_Wp1, DIM, gid); return; }
    gid -= S_P1;
    if (gid < S_P2) { pack_pair(pin_w, ln2_w, g_Wp2, DIM, gid); return; }
    gid -= S_P2;
    if (gid < S_PO) { pack_cons(pout_w, g_Wpo, HID, gid); return; }
    gid -= S_PO;
    if (gid < S_ZA) { g_attn[gid] = 0.f; return; }
    gid -= S_ZA;
    if (gid < S_ZS) { g_sqk[gid] = 0.f; return; }
}

__global__ void pack3x3_kernel(const float* __restrict__ W) {
    int idx = blockIdx.x * 256 + threadIdx.x;
    if (idx >= WP3SZ) return;
    int r = idx;
    int v = r & 3; r >>= 2;
    int lane = r & 31; r >>= 5;
    int mb = r % 3; r /= 3;
    int kx = r % 3; r /= 3;
    int og = r % 2; r /= 2;
    int ky = r % 3; r /= 3;
    int ch = r % NCH3; r /= NCH3;
    int ocT = r;
    int g = lane >> 2, t = lane & 3;
    int oc = ocT * 96 + og * 48 + mb * 16 + g + (v & 1) * 8;
    int ic0 = ch * 16 + t + (v >> 1) * 4;
    float w0 = W[(oc * C3 + ic0) * 9 + ky * 3 + kx];
    float w1 = W[(oc * C3 + ic0 + 8) * 9 + ky * 3 + kx];
    g_Wp3[idx] = packbf(w0, w1);
}

// ---------------- x -> bf16 ch-pair convert ----------------
__global__ __launch_bounds__(256) void cvt_x_kernel(const float* __restrict__ x,
                                                    uint32_t* __restrict__ xh) {
    int idx = blockIdx.x * 256 + threadIdx.x;
    int b = idx / (48 * HW / 4);
    int rem = idx - b * (48 * HW / 4);
    int w = rem / (HW / 4);
    int p = (rem - w * (HW / 4)) * 4;
    int clo = (w >> 3) * 16 + (w & 7);
    const float* lo = x + ((size_t)b * DIM + clo) * HW + p;
    const float* hi = lo + (size_t)8 * HW;
    float4 l4 = *(const float4*)lo;
    float4 h4 = *(const float4*)hi;
    uint4 o;
    o.x = packbf(l4.x, h4.x); o.y = packbf(l4.y, h4.y);
    o.z = packbf(l4.z, h4.z); o.w = packbf(l4.w, h4.w);
    *(uint4*)&xh[((size_t)b * 48 + w) * HW + p] = o;
}

// ---------------- 1x1 conv, u32 ch-pair in, fused LN stats ----------------
template <int ICW, int OMODE>
__global__ __launch_bounds__(256, 2) void conv1x1uln_kernel(
    const uint32_t* __restrict__ in,
    const uint32_t* __restrict__ Wp,
    const float* __restrict__ wgs, const float* __restrict__ wb,
    uint32_t* __restrict__ outv) {
    constexpr int NCH = ICW / 8;
    __shared__ __align__(16) uint32_t bsmw[2][8 * BRW];
    __shared__ __align__(16) uint32_t wsm[2][768];
    __shared__ float smu[256], srstd[256];

    int b = blockIdx.z, ocT = blockIdx.y, px0 = blockIdx.x * 256;
    int OCtot = gridDim.y * 96;
    int tid = threadIdx.x, warp = tid >> 5, lane = tid & 31;
    int og = warp >> 2, pg = warp & 3, g = lane >> 2, t = lane & 3;

    float acc[3][8][4];
#pragma unroll
    for (int mb = 0; mb < 3; mb++)
#pragma unroll
        for (int j = 0; j < 8; j++)
#pragma unroll
            for (int v = 0; v < 4; v++) acc[mb][j][v] = 0.f;

    float psum = 0.f, psq = 0.f;

    const uint32_t* Wb = Wp + (size_t)ocT * NCH * 768;
    auto issue = [&](int ch, int buf) {
#pragma unroll
        for (int k = 0; k < 2; k++) {
            int idx = tid + k * 256;
            int row = idx >> 6, c4 = idx & 63;
            const uint32_t* src = in + ((size_t)b * ICW + ch * 8 + row) * HW + px0 + c4 * 4;
            cpa16((uint32_t)__cvta_generic_to_shared(&bsmw[buf][row * BRW + c4 * 4]), src);
        }
        if (tid < 192)
            cpa16((uint32_t)__cvta_generic_to_shared(&wsm[buf][tid * 4]), Wb + ch * 768 + tid * 4);
        asm volatile("cp.async.commit_group;");
    };
    issue(0, 0);
    for (int s = 0; s < NCH; s++) {
        if (s + 1 < NCH) { issue(s + 1, (s + 1) & 1); asm volatile("cp.async.wait_group 1;"); }
        else asm volatile("cp.async.wait_group 0;");
        __syncthreads();
        int buf = s & 1;
        const uint32_t* bB = &bsmw[buf][0];
#pragma unroll
        for (int w = 0; w < 8; w++) {
            uint32_t word = bB[w * BRW + tid];
            __nv_bfloat162 bb = *reinterpret_cast<__nv_bfloat162*>(&word);
            float a0 = __bfloat162float(bb.x), a1 = __bfloat162float(bb.y);
            psum += a0 + a1; psq += a0 * a0 + a1 * a1;
        }
        const uint32_t* wc = &wsm[buf][og * 384];
        uint32_t a[3][4];
#pragma unroll
        for (int mb = 0; mb < 3; mb++) *(uint4*)a[mb] = *(const uint4*)&wc[mb * 128 + lane * 4];
#pragma unroll
        for (int j = 0; j < 8; j++) {
            int col = pg * 64 + 8 * j + g;
            uint32_t b0 = bB[t * BRW + col], b1 = bB[(t + 4) * BRW + col];
#pragma unroll
            for (int mb = 0; mb < 3; mb++) mma_bf16(acc[mb][j], a[mb], b0, b1);
        }
        __syncthreads();
    }

    {
        float mu = psum * (1.f / DIM);
        float var = psq * (1.f / DIM) - mu * mu;
        smu[tid] = mu;
        srstd[tid] = rsqrtf(var + 1e-5f);
    }
    __syncthreads();

#pragma unroll
    for (int mb = 0; mb < 3; mb++) {
        int oc = ocT * 96 + og * 48 + mb * 16 + g;
        float gs0 = wgs[oc], gs8 = wgs[oc + 8], bb0 = wb[oc], bb8 = wb[oc + 8];
#pragma unroll
        for (int j = 0; j < 8; j++) {
            int pl = pg * 64 + 8 * j + 2 * t;
            int px = px0 + pl;
            float m0 = smu[pl], m1 = smu[pl + 1], r0 = srstd[pl], r1 = srstd[pl + 1];
            float v00 = r0 * (acc[mb][j][0] - m0 * gs0) + bb0;
            float v01 = r1 * (acc[mb][j][1] - m1 * gs0) + bb0;
            float v10 = r0 * (acc[mb][j][2] - m0 * gs8) + bb8;
            float v11 = r1 * (acc[mb][j][3] - m1 * gs8) + bb8;
            if (OMODE == 1) {
                int ch = ocT * 6 + og * 3 + mb;
                int c2 = ch * 8 + g;
                uint2 val = make_uint2(packbf(v00, v10), packbf(v01, v11));
                *(uint2*)&outv[((size_t)b * (OCtot / 2) + c2) * HW + px] = val;
            } else {
                outv[(((size_t)b * OCtot + oc) * HW + px) >> 1] = packbf(v00, v01);
                outv[(((size_t)b * OCtot + oc + 8) * HW + px) >> 1] = packbf(v10, v11);
            }
        }
    }
}

// ---------------- 1x1 conv, u32 pair-word in, fp32 out + residual ----------------
template <int ICW, bool WH>
__global__ __launch_bounds__(256, 2) void conv1x1u_bmma_kernel(
    const uint32_t* __restrict__ in, int in_bstride,
    const uint32_t* __restrict__ Wp, int w_bstride,
    const float* __restrict__ res, float* __restrict__ out,
    uint32_t* __restrict__ outh) {
    constexpr int NCH = ICW / 8;
    __shared__ __align__(16) uint32_t bsmw[2][8 * BRW];
    __shared__ __align__(16) uint32_t wsm[2][768];
    int b = blockIdx.z, px0 = blockIdx.x * 256;
    int tid = threadIdx.x, warp = tid >> 5, lane = tid & 31;
    int og = warp >> 2, pg = warp & 3, g = lane >> 2, t = lane & 3;
    float acc[3][8][4];
#pragma unroll
    for (int mb = 0; mb < 3; mb++)
#pragma unroll
        for (int j = 0; j < 8; j++)
#pragma unroll
            for (int v = 0; v < 4; v++) acc[mb][j][v] = 0.f;
    const uint32_t* Wb = Wp + (size_t)b * w_bstride;
    auto issue = [&](int ch, int buf) {
#pragma unroll
        for (int k = 0; k < 2; k++) {
            int idx = tid + k * 256;
            int row = idx >> 6, c4 = idx & 63;
            const uint32_t* src = in + (size_t)b * in_bstride + (size_t)(ch * 8 + row) * HW + px0 + c4 * 4;
            cpa16((uint32_t)__cvta_generic_to_shared(&bsmw[buf][row * BRW + c4 * 4]), src);
        }
        if (tid < 192)
            cpa16((uint32_t)__cvta_generic_to_shared(&wsm[buf][tid * 4]), Wb + ch * 768 + tid * 4);
        asm volatile("cp.async.commit_group;");
    };
    issue(0, 0);
    for (int s = 0; s < NCH; s++) {
        if (s + 1 < NCH) { issue(s + 1, (s + 1) & 1); asm volatile("cp.async.wait_group 1;"); }
        else asm volatile("cp.async.wait_group 0;");
        __syncthreads();
        int buf = s & 1;
        const uint32_t* wc = &wsm[buf][og * 384];
        uint32_t a[3][4];
#pragma unroll
        for (int mb = 0; mb < 3; mb++) *(uint4*)a[mb] = *(const uint4*)&wc[mb * 128 + lane * 4];
        const uint32_t* bB = &bsmw[buf][0];
#pragma unroll
        for (int j = 0; j < 8; j++) {
            int col = pg * 64 + 8 * j + g;
            uint32_t b0 = bB[t * BRW + col], b1 = bB[(t + 4) * BRW + col];
#pragma unroll
            for (int mb = 0; mb < 3; mb++) mma_bf16(acc[mb][j], a[mb], b0, b1);
        }
        __syncthreads();
    }
#pragma unroll
    for (int mb = 0; mb < 3; mb++) {
        int oc = og * 48 + mb * 16 + g;
#pragma unroll
        for (int j = 0; j < 8; j++) {
            int px = px0 + pg * 64 + 8 * j + 2 * t;
            float2 ra = *(const float2*)&res[((size_t)b * 96 + oc) * HW + px];
            float2 rb = *(const float2*)&res[((size_t)b * 96 + oc + 8) * HW + px];
            float v00 = acc[mb][j][0] + ra.x, v01 = acc[mb][j][1] + ra.y;
            float v10 = acc[mb][j][2] + rb.x, v11 = acc[mb][j][3] + rb.y;
            *(float2*)&out[((size_t)b * 96 + oc) * HW + px] = make_float2(v00, v01);
            *(float2*)&out[((size_t)b * 96 + oc + 8) * HW + px] = make_float2(v10, v11);
            if (WH) {
                int w = (og * 3 + mb) * 8 + g;
                uint2 val = make_uint2(packbf(v00, v10), packbf(v01, v11));
                *(uint2*)&outh[((size_t)b * 48 + w) * HW + px] = val;
            }
        }
    }
}

// ---------------- conv3x3 (proven bf16 mma, 2 blocks/SM) ----------------
__global__ __launch_bounds__(256, 2) void conv3x3_bmma_kernel(const uint32_t* __restrict__ in,
                                                              uint32_t* __restrict__ qk,
                                                              uint32_t* __restrict__ vout,
                                                              float* __restrict__ sqk) {
    extern __shared__ uint32_t dynsmem[];
    uint32_t* bsm = dynsmem;
    uint32_t* wsm = dynsmem + 2 * BSM3;

    int b = blockIdx.z, ocT = blockIdx.y, y = blockIdx.x;
    int tid = threadIdx.x, warp = tid >> 5, lane = tid & 31;
    int og = warp >> 2, pg = warp & 3, g = lane >> 2, t = lane & 3;

    if (tid < 96) {
        int s = tid;
        int side = s & 1; s >>= 1;
        int wr = s % 24; int bufi = s / 24;
        bsm[bufi * BSM3 + wr * BROW3 + (side ? 260 : 3)] = 0u;
    }

    float acc[3][8][4];
#pragma unroll
    for (int mb = 0; mb < 3; mb++)
#pragma unroll
        for (int j = 0; j < 8; j++)
#pragma unroll
            for (int v = 0; v < 4; v++) acc[mb][j][v] = 0.f;

    const uint32_t* wp_base = g_Wp3 + (size_t)ocT * NCH3 * WCH3;

    auto issue = [&](int ch, int buf) {
        const uint32_t* ibase = in + ((size_t)b * (C3 / 2) + ch * 8) * HW;
        uint32_t* bdst = bsm + buf * BSM3;
#pragma unroll
        for (int k = 0; k < 6; k++) {
            int idx = tid + k * 256;
            int wr = idx >> 6, c4 = idx & 63;
            int w = wr / 3, rr = wr - 3 * w;
            int gy = y + rr - 1;
            bool ok = (unsigned)gy < 256u;
            const uint32_t* src = ibase + (size_t)w * HW + (ok ? gy : 0) * IMG + c4 * 4;
            cpa16z((uint32_t)__cvta_generic_to_shared(bdst + wr * BROW3 + 4 + c4 * 4), src, ok);
        }
        const uint32_t* wsrc = wp_base + (size_t)ch * WCH3;
        uint32_t* wdst = wsm + buf * WCH3;
#pragma unroll
        for (int k = 0; k < 7; k++) {
            int i = tid + k * 256;
            if (i < WCH3 / 4)
                cpa16((uint32_t)__cvta_generic_to_shared(wdst + i * 4), wsrc + i * 4);
        }
        asm volatile("cp.async.commit_group;");
    };

    issue(0, 0);
    for (int s = 0; s < NCH3; s++) {
        if (s + 1 < NCH3) { issue(s + 1, (s + 1) & 1); asm volatile("cp.async.wait_group 1;"); }
        else asm volatile("cp.async.wait_group 0;");
        __syncthreads();
        int buf = s & 1;
        const uint32_t* bB = bsm + buf * BSM3;
        const uint32_t* wc = wsm + buf * WCH3;
        int colb = 3 + pg * 64 + g;
#pragma unroll
        for (int ky = 0; ky < 3; ky++) {
#pragma unroll
            for (int kx = 0; kx < 3; kx++) {
                const uint32_t* wbp = wc + (((ky * 2 + og) * 3 + kx) * 3) * 128;
                uint32_t a[3][4];
#pragma unroll
                for (int mb = 0; mb < 3; mb++)
                    *(uint4*)a[mb] = *(const uint4*)&wbp[mb * 128 + lane * 4];
#pragma unroll
                for (int j = 0; j < 8; j++) {
                    int col = colb + 8 * j + kx;
                    uint32_t b0 = bB[(t * 3 + ky) * BROW3 + col];
                    uint32_t b1 = bB[((t + 4) * 3 + ky) * BROW3 + col];
#pragma unroll
                    for (int mb = 0; mb < 3; mb++) mma_bf16(acc[mb][j], a[mb], b0, b1);
                }
            }
        }
        __syncthreads();
    }

    if (ocT < 2) {
#pragma unroll
        for (int mb = 0; mb < 3; mb++) {
            float s0 = 0.f, s8 = 0.f;
#pragma unroll
            for (int j = 0; j < 8; j++) {
                s0 += acc[mb][j][0] * acc[mb][j][0] + acc[mb][j][1] * acc[mb][j][1];
                s8 += acc[mb][j][2] * acc[mb][j][2] + acc[mb][j][3] * acc[mb][j][3];
            }
            s0 += __shfl_xor_sync(0xffffffffu, s0, 1);
            s0 += __shfl_xor_sync(0xffffffffu, s0, 2);
            s8 += __shfl_xor_sync(0xffffffffu, s8, 1);
            s8 += __shfl_xor_sync(0xffffffffu, s8, 2);
            int oc = ocT * 96 + og * 48 + mb * 16 + g;
            if (t == 0) {
                atomicAdd(&sqk[b * 2 * DIM + oc], s0);
                atomicAdd(&sqk[b * 2 * DIM + oc + 8], s8);
            }
#pragma unroll
            for (int j = 0; j < 8; j++) {
                int px = pg * 64 + 8 * j + 2 * t;
                size_t base = (size_t)(b * 192 + oc) * (HW / 2) + ((y * IMG + px) >> 1);
                qk[base] = packbf(acc[mb][j][0], acc[mb][j][1]);
                qk[base + (size_t)8 * (HW / 2)] = packbf(acc[mb][j][2], acc[mb][j][3]);
            }
        }
    } else {
#pragma unroll
        for (int mb = 0; mb < 3; mb++) {
            int c2 = (og * 3 + mb) * 8 + g;
#pragma unroll
            for (int j = 0; j < 8; j++) {
                int px = pg * 64 + 8 * j + 2 * t;
                uint2 val = make_uint2(packbf(acc[mb][j][0], acc[mb][j][2]),
                                       packbf(acc[mb][j][1], acc[mb][j][3]));
                *(uint2*)&vout[((size_t)(b * 48 + c2)) * HW + y * IMG + px] = val;
            }
        }
    }
}

// ---------------- attention gram ----------------
__global__ __launch_bounds__(256) void attn_bmma_kernel(const uint32_t* __restrict__ qk,
                                                        float* __restrict__ attn_raw) {
    int bh = blockIdx.y;
    int b = bh / HEADS, h = bh - b * HEADS;
    int warp = threadIdx.x >> 5, lane = threadIdx.x & 31;
    int tg = lane >> 2, t = lane & 3;
    const uint32_t* q0 = qk + (size_t)(b * 192 + h * HDIM + tg) * (HW / 2);
    const uint32_t* q1 = q0 + (size_t)8 * (HW / 2);
    const uint32_t* k0 = qk + (size_t)(b * 192 + 96 + h * HDIM + tg) * (HW / 2);
    const uint32_t* k1 = k0 + (size_t)8 * (HW / 2);
    float c0[4] = {0.f, 0.f, 0.f, 0.f};
    float c1[4] = {0.f, 0.f, 0.f, 0.f};
    int slab0 = (blockIdx.x * 8 + warp) * 16;
    for (int s = 0; s < 16; s++) {
        int w0 = (slab0 + s) * 32 + 4 * t;
        uint32_t qa[4], qb[4], qc[4], qd[4], ka[4], kc[4], kb[4], kd[4];
        *(uint4*)qa = *(const uint4*)(q0 + w0);
        *(uint4*)qb = *(const uint4*)(q1 + w0);
        *(uint4*)qc = *(const uint4*)(q0 + w0 + 16);
        *(uint4*)qd = *(const uint4*)(q1 + w0 + 16);
        *(uint4*)ka = *(const uint4*)(k0 + w0);
        *(uint4*)kc = *(const uint4*)(k0 + w0 + 16);
        *(uint4*)kb = *(const uint4*)(k1 + w0);
        *(uint4*)kd = *(const uint4*)(k1 + w0 + 16);
#pragma unroll
        for (int m = 0; m < 4; m++) {
            uint32_t a[4] = { qa[m], qb[m], qc[m], qd[m] };
            mma_bf16(c0, a, ka[m], kc[m]);
            mma_bf16(c1, a, kb[m], kd[m]);
        }
    }
    float* dst = attn_raw + bh * 256;
    atomicAdd(dst + tg * 16 + 2 * t, c0[0]);
    atomicAdd(dst + tg * 16 + 2 * t + 1, c0[1]);
    atomicAdd(dst + (tg + 8) * 16 + 2 * t, c0[2]);
    atomicAdd(dst + (tg + 8) * 16 + 2 * t + 1, c0[3]);
    atomicAdd(dst + tg * 16 + 8 + 2 * t, c1[0]);
    atomicAdd(dst + tg * 16 + 8 + 2 * t + 1, c1[1]);
    atomicAdd(dst + (tg + 8) * 16 + 8 + 2 * t, c1[2]);
    atomicAdd(dst + (tg + 8) * 16 + 8 + 2 * t + 1, c1[3]);
}

// ---------------- softmax + fused M ----------------
__global__ __launch_bounds__(256) void softmax_build_M(const float* __restrict__ attn_raw,
                                                       const float* __restrict__ sqk,
                                                       const float* __restrict__ scale,
                                                       const float* __restrict__ proj_w,
                                                       uint32_t* __restrict__ Mp) {
    int b = blockIdx.x;
    int tdx = threadIdx.x;
    __shared__ float A[HEADS * 256];
    __shared__ float nq[DIM], nk[DIM];
    if (tdx < DIM) {
        nq[tdx] = fmaxf(sqrtf(sqk[b * 2 * DIM + tdx]), 1e-12f);
        nk[tdx] = fmaxf(sqrtf(sqk[b * 2 * DIM + DIM + tdx]), 1e-12f);
    }
    __syncthreads();
    for (int idx = tdx; idx < HEADS * 256; idx += 256) {
        int h = idx >> 8;
        int cd = idx & 255;
        int c = cd >> 4, d = cd & 15;
        A[idx] = attn_raw[b * HEADS * 256 + idx] /
                 (nq[h * HDIM + c] * nk[h * HDIM + d]) * scale[h];
    }
    __syncthreads();
    if (tdx < DIM) {
        int h = tdx >> 4, c = tdx & 15;
        float* row = &A[h * 256 + c * 16];
        float mx = row[0];
#pragma unroll
        for (int d = 1; d < 16; d++) mx = fmaxf(mx, row[d]);
        float sum = 0.f;
#pragma unroll
        for (int d = 0; d < 16; d++) { float e = expf(row[d] - mx); row[d] = e; sum += e; }
        float inv = 1.f / sum;
#pragma unroll
        for (int d = 0; d < 16; d++) row[d] *= inv;
    }
    __syncthreads();
    for (int idx = tdx; idx < DIM * DIM / 2; idx += 256) {
        int r = idx;
        int v = r & 3; r >>= 2;
        int lane = r & 31; r >>= 5;
        int mb = r % 3; r /= 3;
        int og = r % 2; r /= 2;
        int ch = r;
        int g = lane >> 2, t = lane & 3;
        int oc = og * 48 + mb * 16 + g + (v & 1) * 8;
        int d = t + (v >> 1) * 4;
        int h = ch;
        float s0 = 0.f, s1 = 0.f;
#pragma unroll
        for (int cg = 0; cg < 16; cg++) {
            float pw = proj_w[oc * DIM + h * HDIM + cg];
            s0 += pw * A[h * 256 + cg * 16 + d];
            s1 += pw * A[h * 256 + cg * 16 + d + 8];
        }
        Mp[b * (DIM * DIM / 2) + idx] = packbf(s0, s1);
    }
}

// ---------------- dwconv + gate (LDG-direct, 8 px/thread) ----------------
__device__ __forceinline__ float gelu_tanh(float x) {
    float x3 = x * x * x;
    return 0.5f * x * (1.f + tanhf(0.7978845608028654f * (x + 0.044715f * x3)));
}

__global__ __launch_bounds__(256) void dwgate_kernel(const uint32_t* __restrict__ tin,
                                                     const float* __restrict__ dw,
                                                     uint32_t* __restrict__ gw) {
    int b = blockIdx.z, m = blockIdx.y;
    int y = blockIdx.x * 8 + (threadIdx.x >> 5);
    int px0 = (threadIdx.x & 31) * 8;
    int tid = threadIdx.x;

    __shared__ float swt[72];
    int chans[4] = {2 * m, 2 * m + 1, HID + 2 * m, HID + 2 * m + 1};
    if (tid < 72) {
        int oci = tid / 18;
        swt[tid] = dw[(size_t)chans[oci] * 18 + (tid - oci * 18)];
    }
    __syncthreads();

    float u[4][8];
#pragma unroll
    for (int ol = 0; ol < 4; ol++)
#pragma unroll
        for (int j = 0; j < 8; j++) u[ol][j] = 0.f;

    int wbase = px0 >> 1;
#pragma unroll
    for (int ic = 0; ic < 4; ic++) {
        const uint32_t* chb = tin + ((size_t)(b * HID2 + chans[ic]) * HW) / 2;
        int olb = (ic >> 1) << 1;
        int wi0 = (ic & 1) * 9;
#pragma unroll
        for (int ky = 0; ky < 3; ky++) {
            int gy = y + ky - 1;
            bool rok = (unsigned)gy < 256u;
            const uint32_t* rowp = chb + gy * 128;
            float v[12];
#pragma unroll
            for (int w = 0; w < 6; w++) {
                int wi = wbase - 1 + w;
                uint32_t word = (rok && (unsigned)wi < 128u) ? __ldg(rowp + wi) : 0u;
                __nv_bfloat162 bb = *reinterpret_cast<__nv_bfloat162*>(&word);
                v[2 * w] = __bfloat162float(bb.x);
                v[2 * w + 1] = __bfloat162float(bb.y);
            }
#pragma unroll
            for (int kx = 0; kx < 3; kx++) {
                float w0 = swt[olb * 18 + wi0 + ky * 3 + kx];
                float w1 = swt[(olb + 1) * 18 + wi0 + ky * 3 + kx];
#pragma unroll
                for (int j = 0; j < 8; j++) {
                    float xv = v[j + kx + 1];
                    u[olb][j] += w0 * xv;
                    u[olb + 1][j] += w1 * xv;
                }
            }
        }
    }

    uint32_t outw[8];
#pragma unroll
    for (int j = 0; j < 8; j++)
        outw[j] = packbf(gelu_tanh(u[0][j]) * u[2][j], gelu_tanh(u[1][j]) * u[3][j]);
    uint32_t* dst = gw + ((size_t)b * 96 + m) * HW + y * IMG + px0;
    *(uint4*)dst = *(uint4*)&outw[0];
    *(uint4*)(dst + 4) = *(uint4*)&outw[4];
}

// ---------------- launch ----------------
static void* sym_addr(const void* sym) {
    void* p = nullptr;
    cudaGetSymbolAddress(&p, sym);
    return p;
}

extern "C" void kernel_launch(void* const* d_in, const int* in_sizes, int n_in,
                              void* d_out, int out_size) {
    const float* x      = (const float*)d_in[0];
    const float* ln1_w  = (const float*)d_in[1];
    const float* ln1_b  = (const float*)d_in[2];
    const float* qkv1_w = (const float*)d_in[3];
    const float* qkv2_w = (const float*)d_in[4];
    const float* proj_w = (const float*)d_in[5];
    const float* scale  = (const float*)d_in[6];
    const float* ln2_w  = (const float*)d_in[7];
    const float* ln2_b  = (const float*)d_in[8];
    const float* pin_w  = (const float*)d_in[9];
    const float* dw_w   = (const float*)d_in[10];
    const float* pout_w = (const float*)d_in[11];

    uint32_t* xh   = (uint32_t*)sym_addr(g_xh);
    uint32_t* x2h  = (uint32_t*)sym_addr(g_x2h);
    uint32_t* qkvh = (uint32_t*)sym_addr(g_qkvh);
    uint32_t* qkpp = (uint32_t*)sym_addr(g_qkpp);
    uint32_t* vcp  = (uint32_t*)sym_addr(g_vcp);
    uint32_t* tbuf = (uint32_t*)sym_addr(g_t);
    uint32_t* gw   = (uint32_t*)sym_addr(g_gw);
    float* x2   = (float*)sym_addr(g_x2);
    float* wgs1 = (float*)sym_addr(g_wgs1);
    float* wb1  = (float*)sym_addr(g_wb1);
    float* wgs2 = (float*)sym_addr(g_wgs2);
    float* wb2  = (float*)sym_addr(g_wb2);
    float* sqk  = (float*)sym_addr(g_sqk);
    float* attn = (float*)sym_addr(g_attn);
    uint32_t* Wp1 = (uint32_t*)sym_addr(g_Wp1);
    uint32_t* Wp2 = (uint32_t*)sym_addr(g_Wp2);
    uint32_t* Wpo = (uint32_t*)sym_addr(g_Wpo);
    uint32_t* Mp  = (uint32_t*)sym_addr(g_Mp);
    float* out = (float*)d_out;

    static bool attr_done = false;
    if (!attr_done) {
        cudaFuncSetAttribute(conv3x3_bmma_kernel,
                             cudaFuncAttributeMaxDynamicSharedMemorySize, SMEM3);
        attr_done = true;
    }

    // fused setup (prep row-sums + weight packs + zero fills), plus conv3x3 pack
    setup_kernel<<<(S_TOTAL + 255) / 256, 256>>>(qkv1_w, ln1_w, ln1_b,
                                                 pin_w, ln2_w, ln2_b, pout_w);
    pack3x3_kernel<<<(WP3SZ + 255) / 256, 256>>>(qkv2_w);

    // x -> bf16 ch-pair words, then LN-fused qkv1 (96 -> 288) with internal stats
    cvt_x_kernel<<<BATCH * 48 * HW / 4 / 256, 256>>>(x, xh);
    conv1x1uln_kernel<48, 1><<<dim3(256, 3, BATCH), 256>>>(
        xh, Wp1, wgs1, wb1, qkvh);

    // qkv2: 3x3 conv 288 -> 288 (bf16 mma), q/k px-pair + v ch-pair + fused sumsq
    conv3x3_bmma_kernel<<<dim3(256, 3, BATCH), 256, SMEM3>>>(qkvh, qkpp, vcp, sqk);

    // attention statistics (bf16 gram) + fused M
    attn_bmma_kernel<<<dim3(8, BATCH * HEADS), 256>>>(qkpp, attn);
    softmax_build_M<<<BATCH, 256>>>(attn, sqk, scale, proj_w, Mp);

    // fused (attn@v -> proj -> +x) over bf16 v words; writes x2 fp32 + x2h bf16
    conv1x1u_bmma_kernel<48, true><<<dim3(256, 1, BATCH), 256>>>(
        vcp, 48 * HW, Mp, DIM * DIM / 2, x, x2, x2h);

    // LN-fused pin (96 -> 384) from x2h with internal stats -> bf16 px-pair words
    conv1x1uln_kernel<48, 2><<<dim3(256, 4, BATCH), 256>>>(
        x2h, Wp2, wgs2, wb2, tbuf);

    // grouped 3x3 conv + GELU gate -> bf16 consecutive-pair words
    dwgate_kernel<<<dim3(32, DIM, BATCH), 256>>>(tbuf, dw_w, gw);

    // pout (192 -> 96) + residual -> output
    conv1x1u_bmma_kernel<96, false><<<dim3(256, 1, BATCH), 256>>>(
        gw, 96 * HW, Wpo, 0, x2, out, nullptr);
}